// round 1
// baseline (speedup 1.0000x reference)
#include <cuda_runtime.h>
#include <math.h>

#define DIM   1024
#define HEADS 16
#define DHEAD 64
#define BTOK  8192   // 4 * 2048 tokens
#define FFIN  4096

// ---------------- scratch (device globals: allocation-free) ----------------
__device__ float g_ln [BTOK * DIM];
__device__ float g_q  [BTOK * DIM];
__device__ float g_k  [BTOK * DIM];
__device__ float g_v  [BTOK * DIM];
__device__ float g_att[BTOK * DIM];
__device__ float g_x  [BTOK * DIM];
__device__ float g_h  [(size_t)BTOK * (2 * FFIN)];
__device__ float g_gl [(size_t)BTOK * FFIN];

// ---------------- LayerNorm: one block per row (dim=1024) ----------------
__global__ __launch_bounds__(256) void ln_kernel(
    const float* __restrict__ x, const float* __restrict__ gamma,
    const float* __restrict__ beta, float* __restrict__ out)
{
    int row = blockIdx.x;
    int tid = threadIdx.x;
    const float4* xr = (const float4*)(x + (size_t)row * DIM);
    float4 t = xr[tid];
    float s = t.x + t.y + t.z + t.w;
    float q = t.x * t.x + t.y * t.y + t.z * t.z + t.w * t.w;
    #pragma unroll
    for (int o = 16; o; o >>= 1) {
        s += __shfl_xor_sync(0xffffffffu, s, o);
        q += __shfl_xor_sync(0xffffffffu, q, o);
    }
    __shared__ float ssum[8], ssq[8];
    __shared__ float smean, srstd;
    int wid = tid >> 5, lane = tid & 31;
    if (lane == 0) { ssum[wid] = s; ssq[wid] = q; }
    __syncthreads();
    if (tid == 0) {
        float S = 0.f, Q = 0.f;
        #pragma unroll
        for (int i = 0; i < 8; i++) { S += ssum[i]; Q += ssq[i]; }
        float mean = S * (1.f / DIM);
        float var  = Q * (1.f / DIM) - mean * mean;
        smean = mean;
        srstd = rsqrtf(var + 1e-5f);
    }
    __syncthreads();
    float mean = smean, rstd = srstd;
    float4 gg = ((const float4*)gamma)[tid];
    float4 bb = ((const float4*)beta)[tid];
    float4 o;
    o.x = (t.x - mean) * rstd * gg.x + bb.x;
    o.y = (t.y - mean) * rstd * gg.y + bb.y;
    o.z = (t.z - mean) * rstd * gg.z + bb.z;
    o.w = (t.w - mean) * rstd * gg.w + bb.w;
    ((float4*)(out + (size_t)row * DIM))[tid] = o;
}

// ---------------- SGEMM: C[M,N] = A[M,K] @ B[K,N] (+bias)(+Res) ----------------
// Block tile 128x128, K-tile 8, 256 threads, 8x8 per-thread micro tile.
// Requires: K % 8 == 0, N % 128 == 0. M arbitrary (guarded).
__global__ __launch_bounds__(256) void sgemm(
    const float* __restrict__ A, const float* __restrict__ B,
    const float* __restrict__ bias, const float* __restrict__ Res,
    float* __restrict__ C, int M, int N, int K)
{
    __shared__ float As[8][128];
    __shared__ float Bs[8][128];
    int t = threadIdx.x;
    int m0 = blockIdx.y * 128, n0 = blockIdx.x * 128;
    int arow = t >> 1,  acol = (t & 1) * 4;
    int brow = t >> 5,  bcol = (t & 31) * 4;
    int tx = t & 15, ty = t >> 4;
    float acc[8][8];
    #pragma unroll
    for (int i = 0; i < 8; i++)
        #pragma unroll
        for (int j = 0; j < 8; j++) acc[i][j] = 0.f;

    bool avalid = (m0 + arow) < M;
    const float* Aptr = A + (size_t)(m0 + arow) * K + acol;
    const float* Bptr = B + (size_t)brow * N + n0 + bcol;

    for (int k0 = 0; k0 < K; k0 += 8) {
        float4 av = avalid ? *(const float4*)(Aptr + k0) : make_float4(0.f, 0.f, 0.f, 0.f);
        float4 bv = *(const float4*)(Bptr + (size_t)k0 * N);
        __syncthreads();
        As[acol + 0][arow] = av.x;
        As[acol + 1][arow] = av.y;
        As[acol + 2][arow] = av.z;
        As[acol + 3][arow] = av.w;
        *(float4*)&Bs[brow][bcol] = bv;
        __syncthreads();
        #pragma unroll
        for (int k = 0; k < 8; k++) {
            float a[8], b[8];
            *(float4*)(a)     = *(float4*)&As[k][ty * 8];
            *(float4*)(a + 4) = *(float4*)&As[k][ty * 8 + 4];
            *(float4*)(b)     = *(float4*)&Bs[k][tx * 8];
            *(float4*)(b + 4) = *(float4*)&Bs[k][tx * 8 + 4];
            #pragma unroll
            for (int i = 0; i < 8; i++)
                #pragma unroll
                for (int j = 0; j < 8; j++)
                    acc[i][j] = fmaf(a[i], b[j], acc[i][j]);
        }
    }

    #pragma unroll
    for (int i = 0; i < 8; i++) {
        int m = m0 + ty * 8 + i;
        if (m >= M) break;
        size_t base = (size_t)m * N + n0 + tx * 8;
        #pragma unroll
        for (int j = 0; j < 8; j += 4) {
            int n = n0 + tx * 8 + j;
            float4 o;
            o.x = acc[i][j + 0]; o.y = acc[i][j + 1];
            o.z = acc[i][j + 2]; o.w = acc[i][j + 3];
            if (bias) {
                o.x += bias[n + 0]; o.y += bias[n + 1];
                o.z += bias[n + 2]; o.w += bias[n + 3];
            }
            if (Res) {
                float4 rr = *(const float4*)&Res[base + j];
                o.x += rr.x; o.y += rr.y; o.z += rr.z; o.w += rr.w;
            }
            *(float4*)&C[base + j] = o;
        }
    }
}

// ---------------- Flash attention: one thread per query row ----------------
// Q: [B*N, HEADS*DHEAD], K/V: [B*S, HEADS*DHEAD]. grid(N/128, HEADS, B), 128 thr.
__global__ __launch_bounds__(128) void attn_kernel(
    const float* __restrict__ Q, const float* __restrict__ K,
    const float* __restrict__ V, float* __restrict__ O, int N, int S)
{
    __shared__ float Ks[64 * 64];
    __shared__ float Vs[64 * 64];
    int b = blockIdx.z, h = blockIdx.y;
    int n = blockIdx.x * 128 + threadIdx.x;
    const float scale = 0.125f;  // 1/sqrt(64)
    size_t qoff = ((size_t)(b * N + n)) * DIM + h * DHEAD;

    float qv[64];
    #pragma unroll
    for (int d = 0; d < 64; d += 4)
        *(float4*)&qv[d] = *(const float4*)&Q[qoff + d];

    float acc[64];
    #pragma unroll
    for (int d = 0; d < 64; d++) acc[d] = 0.f;
    float mrow = -1e30f, lrow = 0.f;

    for (int s0 = 0; s0 < S; s0 += 64) {
        __syncthreads();
        for (int i = threadIdx.x; i < 64 * 16; i += 128) {
            int r = i >> 4;
            int d4 = (i & 15) * 4;
            int sg = s0 + r;
            float4 kv = make_float4(0.f, 0.f, 0.f, 0.f), vv = kv;
            if (sg < S) {
                size_t off = ((size_t)(b * S + sg)) * DIM + h * DHEAD + d4;
                kv = *(const float4*)&K[off];
                vv = *(const float4*)&V[off];
            }
            *(float4*)&Ks[r * 64 + d4] = kv;
            *(float4*)&Vs[r * 64 + d4] = vv;
        }
        __syncthreads();
        int jmax = min(64, S - s0);
        for (int j = 0; j < jmax; j++) {
            const float* kr = &Ks[j * 64];
            float s_0 = 0.f, s_1 = 0.f, s_2 = 0.f, s_3 = 0.f;
            #pragma unroll
            for (int d = 0; d < 64; d += 4) {
                s_0 = fmaf(qv[d + 0], kr[d + 0], s_0);
                s_1 = fmaf(qv[d + 1], kr[d + 1], s_1);
                s_2 = fmaf(qv[d + 2], kr[d + 2], s_2);
                s_3 = fmaf(qv[d + 3], kr[d + 3], s_3);
            }
            float s = (s_0 + s_1 + s_2 + s_3) * scale;
            float mnew = fmaxf(mrow, s);
            float corr = __expf(mrow - mnew);
            float p    = __expf(s - mnew);
            lrow = lrow * corr + p;
            const float* vr = &Vs[j * 64];
            #pragma unroll
            for (int d = 0; d < 64; d++)
                acc[d] = fmaf(acc[d], corr, p * vr[d]);
            mrow = mnew;
        }
    }
    float inv = 1.f / lrow;
    #pragma unroll
    for (int d = 0; d < 64; d += 4) {
        float4 o;
        o.x = acc[d + 0] * inv; o.y = acc[d + 1] * inv;
        o.z = acc[d + 2] * inv; o.w = acc[d + 3] * inv;
        *(float4*)&O[qoff + d] = o;
    }
}

// ---------------- GEGLU: out[m,j] = h[m,j] * gelu(h[m,4096+j]) ----------------
__global__ __launch_bounds__(256) void geglu_kernel(
    const float* __restrict__ h, float* __restrict__ out)
{
    size_t i = (size_t)blockIdx.x * 256 + threadIdx.x;
    if (i >= (size_t)BTOK * FFIN) return;
    size_t m = i >> 12;        // / 4096
    size_t j = i & (FFIN - 1);
    float a = h[m * (2 * FFIN) + j];
    float g = h[m * (2 * FFIN) + FFIN + j];
    float gl = 0.5f * g * (1.f + erff(g * 0.70710678118654752f));
    out[i] = a * gl;
}

// ---------------- host orchestration ----------------
extern "C" void kernel_launch(void* const* d_in, const int* in_sizes, int n_in,
                              void* d_out, int out_size)
{
    (void)in_sizes; (void)n_in; (void)out_size;
    const float* x    = (const float*)d_in[0];
    const float* ctx  = (const float*)d_in[1];
    const float* Wq1  = (const float*)d_in[2];
    const float* Wk1  = (const float*)d_in[3];
    const float* Wv1  = (const float*)d_in[4];
    const float* Wo1  = (const float*)d_in[5];
    const float* bo1  = (const float*)d_in[6];
    const float* Wq2  = (const float*)d_in[7];
    const float* Wk2  = (const float*)d_in[8];
    const float* Wv2  = (const float*)d_in[9];
    const float* Wo2  = (const float*)d_in[10];
    const float* bo2  = (const float*)d_in[11];
    const float* Wp   = (const float*)d_in[12];
    const float* bp   = (const float*)d_in[13];
    const float* Wf   = (const float*)d_in[14];
    const float* bf   = (const float*)d_in[15];
    const float* g1   = (const float*)d_in[16];
    const float* b1   = (const float*)d_in[17];
    const float* g2   = (const float*)d_in[18];
    const float* b2   = (const float*)d_in[19];
    const float* g3   = (const float*)d_in[20];
    const float* b3   = (const float*)d_in[21];
    float* out = (float*)d_out;

    float *ln, *q, *k, *v, *att, *xb, *hb, *gl;
    cudaGetSymbolAddress((void**)&ln,  g_ln);
    cudaGetSymbolAddress((void**)&q,   g_q);
    cudaGetSymbolAddress((void**)&k,   g_k);
    cudaGetSymbolAddress((void**)&v,   g_v);
    cudaGetSymbolAddress((void**)&att, g_att);
    cudaGetSymbolAddress((void**)&xb,  g_x);
    cudaGetSymbolAddress((void**)&hb,  g_h);
    cudaGetSymbolAddress((void**)&gl,  g_gl);

    const int B = 4, N = 2048, S = 77;
    const int M = B * N;           // 8192
    const int Mc = B * S;          // 308

    dim3 gemm1024(1024 / 128, M / 128);          // N=1024, M=8192
    dim3 gemmCtx(1024 / 128, (Mc + 127) / 128);  // N=1024, M=308
    dim3 gemmWp(2 * FFIN / 128, M / 128);        // N=8192, M=8192
    dim3 attnGrid(N / 128, HEADS, B);

    // ---- stage 1: self-attention ----
    ln_kernel<<<M, 256>>>(x, g1, b1, ln);
    sgemm<<<gemm1024, 256>>>(ln, Wq1, nullptr, nullptr, q, M, 1024, 1024);
    sgemm<<<gemm1024, 256>>>(ln, Wk1, nullptr, nullptr, k, M, 1024, 1024);
    sgemm<<<gemm1024, 256>>>(ln, Wv1, nullptr, nullptr, v, M, 1024, 1024);
    attn_kernel<<<attnGrid, 128>>>(q, k, v, att, N, N);
    sgemm<<<gemm1024, 256>>>(att, Wo1, bo1, x, xb, M, 1024, 1024);

    // ---- stage 2: cross-attention ----
    ln_kernel<<<M, 256>>>(xb, g2, b2, ln);
    sgemm<<<gemm1024, 256>>>(ln, Wq2, nullptr, nullptr, q, M, 1024, 1024);
    sgemm<<<gemmCtx, 256>>>(ctx, Wk2, nullptr, nullptr, k, Mc, 1024, 768);
    sgemm<<<gemmCtx, 256>>>(ctx, Wv2, nullptr, nullptr, v, Mc, 1024, 768);
    attn_kernel<<<attnGrid, 128>>>(q, k, v, att, N, S);
    sgemm<<<gemm1024, 256>>>(att, Wo2, bo2, xb, xb, M, 1024, 1024);

    // ---- stage 3: GEGLU feed-forward ----
    ln_kernel<<<M, 256>>>(xb, g3, b3, ln);
    sgemm<<<gemmWp, 256>>>(ln, Wp, bp, nullptr, hb, M, 2 * FFIN, 1024);
    {
        size_t total = (size_t)M * FFIN;
        int blocks = (int)((total + 255) / 256);
        geglu_kernel<<<blocks, 256>>>(hb, gl);
    }
    sgemm<<<gemm1024, 256>>>(gl, Wf, bf, xb, out, M, 1024, FFIN);
}

// round 3
// speedup vs baseline: 1.8099x; 1.8099x over previous
#include <cuda_runtime.h>
#include <math.h>

#define DIM   1024
#define HEADS 16
#define DHEAD 64
#define BTOK  8192   // 4 * 2048 tokens
#define FFIN  4096

// ---------------- scratch (device globals: allocation-free) ----------------
__device__ float g_ln [BTOK * DIM];
__device__ float g_q  [BTOK * DIM];
__device__ float g_k  [BTOK * DIM];
__device__ float g_v  [BTOK * DIM];
__device__ float g_att[BTOK * DIM];
__device__ float g_x  [BTOK * DIM];
__device__ float g_h  [(size_t)BTOK * (2 * FFIN)];
__device__ float g_gl [(size_t)BTOK * FFIN];

// ---------------- LayerNorm: one block per row (dim=1024) ----------------
__global__ __launch_bounds__(256) void ln_kernel(
    const float* __restrict__ x, const float* __restrict__ gamma,
    const float* __restrict__ beta, float* __restrict__ out)
{
    int row = blockIdx.x;
    int tid = threadIdx.x;
    const float4* xr = (const float4*)(x + (size_t)row * DIM);
    float4 t = xr[tid];
    float s = t.x + t.y + t.z + t.w;
    float q = t.x * t.x + t.y * t.y + t.z * t.z + t.w * t.w;
    #pragma unroll
    for (int o = 16; o; o >>= 1) {
        s += __shfl_xor_sync(0xffffffffu, s, o);
        q += __shfl_xor_sync(0xffffffffu, q, o);
    }
    __shared__ float ssum[8], ssq[8];
    __shared__ float smean, srstd;
    int wid = tid >> 5, lane = tid & 31;
    if (lane == 0) { ssum[wid] = s; ssq[wid] = q; }
    __syncthreads();
    if (tid == 0) {
        float S = 0.f, Q = 0.f;
        #pragma unroll
        for (int i = 0; i < 8; i++) { S += ssum[i]; Q += ssq[i]; }
        float mean = S * (1.f / DIM);
        float var  = Q * (1.f / DIM) - mean * mean;
        smean = mean;
        srstd = rsqrtf(var + 1e-5f);
    }
    __syncthreads();
    float mean = smean, rstd = srstd;
    float4 gg = ((const float4*)gamma)[tid];
    float4 bb = ((const float4*)beta)[tid];
    float4 o;
    o.x = (t.x - mean) * rstd * gg.x + bb.x;
    o.y = (t.y - mean) * rstd * gg.y + bb.y;
    o.z = (t.z - mean) * rstd * gg.z + bb.z;
    o.w = (t.w - mean) * rstd * gg.w + bb.w;
    ((float4*)(out + (size_t)row * DIM))[tid] = o;
}

// ---------------- TF32 tensor-core GEMM ----------------
// C[M,N] = A[M,K] @ B[K,N] (+bias)(+Res). A,B row-major fp32; converted to
// TF32 (cvt.rna) on the smem store path; fp32 accumulate via
// mma.sync.aligned.m16n8k8.row.col.f32.tf32.tf32.f32.
// Block tile 128x128, K-tile 16, 256 threads (8 warps, each 64x32).
// Requires K % 16 == 0, N % 128 == 0. M arbitrary (guarded).

__device__ __forceinline__ unsigned f2tf32(float x) {
    unsigned u;
    asm("cvt.rna.tf32.f32 %0, %1;" : "=r"(u) : "f"(x));
    return u;
}

__global__ __launch_bounds__(256, 2) void tf32_gemm(
    const float* __restrict__ A, const float* __restrict__ B,
    const float* __restrict__ bias, const float* __restrict__ Res,
    float* __restrict__ C, int M, int N, int K)
{
    // Padded layouts chosen for conflict-free fragment loads:
    //  A frag: addr = m*20 + k  -> banks (g*20+tg)%32 all-distinct
    //  B frag: addr = k*136 + n -> banks (tg*8+g)%32 all-distinct
    __shared__ float As[2][128][20];
    __shared__ float Bs[2][16][136];

    const int t = threadIdx.x;
    const int m0 = blockIdx.y * 128, n0 = blockIdx.x * 128;
    const int warp = t >> 5, lane = t & 31;
    const int wm = (warp & 1) * 64;   // warp M offset (2 warps x 64)
    const int wn = (warp >> 1) * 32;  // warp N offset (4 warps x 32)
    const int g  = lane >> 2;         // groupID
    const int tg = lane & 3;          // thread in group

    // staging registers for the next tile
    float4 areg[2], breg[2];
    int am[2], ak[2], bk[2], bn[2];
    bool aval[2];
    #pragma unroll
    for (int i = 0; i < 2; i++) {
        int lin = t + i * 256;
        am[i] = lin >> 2;  ak[i] = (lin & 3) << 2;
        bk[i] = lin >> 5;  bn[i] = (lin & 31) << 2;
        aval[i] = (m0 + am[i]) < M;
    }

    float c[4][4][4];
    #pragma unroll
    for (int i = 0; i < 4; i++)
        #pragma unroll
        for (int j = 0; j < 4; j++)
            #pragma unroll
            for (int r = 0; r < 4; r++) c[i][j][r] = 0.f;

    const int T = K / 16;

    // ---- prologue: load + store tile 0 ----
    #pragma unroll
    for (int i = 0; i < 2; i++) {
        areg[i] = aval[i] ? *(const float4*)&A[(size_t)(m0 + am[i]) * K + ak[i]]
                          : make_float4(0.f, 0.f, 0.f, 0.f);
        breg[i] = *(const float4*)&B[(size_t)bk[i] * N + n0 + bn[i]];
    }
    #pragma unroll
    for (int i = 0; i < 2; i++) {
        As[0][am[i]][ak[i] + 0] = __uint_as_float(f2tf32(areg[i].x));
        As[0][am[i]][ak[i] + 1] = __uint_as_float(f2tf32(areg[i].y));
        As[0][am[i]][ak[i] + 2] = __uint_as_float(f2tf32(areg[i].z));
        As[0][am[i]][ak[i] + 3] = __uint_as_float(f2tf32(areg[i].w));
        Bs[0][bk[i]][bn[i] + 0] = __uint_as_float(f2tf32(breg[i].x));
        Bs[0][bk[i]][bn[i] + 1] = __uint_as_float(f2tf32(breg[i].y));
        Bs[0][bk[i]][bn[i] + 2] = __uint_as_float(f2tf32(breg[i].z));
        Bs[0][bk[i]][bn[i] + 3] = __uint_as_float(f2tf32(breg[i].w));
    }
    __syncthreads();

    for (int tt = 0; tt < T; tt++) {
        const int buf = tt & 1;
        // prefetch next tile into registers (overlaps with MMA below)
        if (tt + 1 < T) {
            int k0 = (tt + 1) * 16;
            #pragma unroll
            for (int i = 0; i < 2; i++) {
                areg[i] = aval[i] ? *(const float4*)&A[(size_t)(m0 + am[i]) * K + k0 + ak[i]]
                                  : make_float4(0.f, 0.f, 0.f, 0.f);
                breg[i] = *(const float4*)&B[(size_t)(k0 + bk[i]) * N + n0 + bn[i]];
            }
        }

        // ---- compute on buf ----
        #pragma unroll
        for (int kk = 0; kk < 16; kk += 8) {
            unsigned a[4][4], b[4][2];
            #pragma unroll
            for (int i = 0; i < 4; i++) {
                int mb = wm + i * 16;
                a[i][0] = __float_as_uint(As[buf][mb + g    ][kk + tg    ]);
                a[i][1] = __float_as_uint(As[buf][mb + g + 8][kk + tg    ]);
                a[i][2] = __float_as_uint(As[buf][mb + g    ][kk + tg + 4]);
                a[i][3] = __float_as_uint(As[buf][mb + g + 8][kk + tg + 4]);
            }
            #pragma unroll
            for (int j = 0; j < 4; j++) {
                int nb = wn + j * 8;
                b[j][0] = __float_as_uint(Bs[buf][kk + tg    ][nb + g]);
                b[j][1] = __float_as_uint(Bs[buf][kk + tg + 4][nb + g]);
            }
            #pragma unroll
            for (int i = 0; i < 4; i++)
                #pragma unroll
                for (int j = 0; j < 4; j++) {
                    asm volatile(
                        "mma.sync.aligned.m16n8k8.row.col.f32.tf32.tf32.f32 "
                        "{%0,%1,%2,%3}, {%4,%5,%6,%7}, {%8,%9}, {%0,%1,%2,%3};"
                        : "+f"(c[i][j][0]), "+f"(c[i][j][1]),
                          "+f"(c[i][j][2]), "+f"(c[i][j][3])
                        : "r"(a[i][0]), "r"(a[i][1]), "r"(a[i][2]), "r"(a[i][3]),
                          "r"(b[j][0]), "r"(b[j][1]));
                }
        }
        __syncthreads();

        // store prefetched tile into the other buffer
        if (tt + 1 < T) {
            const int nb = (tt + 1) & 1;
            #pragma unroll
            for (int i = 0; i < 2; i++) {
                As[nb][am[i]][ak[i] + 0] = __uint_as_float(f2tf32(areg[i].x));
                As[nb][am[i]][ak[i] + 1] = __uint_as_float(f2tf32(areg[i].y));
                As[nb][am[i]][ak[i] + 2] = __uint_as_float(f2tf32(areg[i].z));
                As[nb][am[i]][ak[i] + 3] = __uint_as_float(f2tf32(areg[i].w));
                Bs[nb][bk[i]][bn[i] + 0] = __uint_as_float(f2tf32(breg[i].x));
                Bs[nb][bk[i]][bn[i] + 1] = __uint_as_float(f2tf32(breg[i].y));
                Bs[nb][bk[i]][bn[i] + 2] = __uint_as_float(f2tf32(breg[i].z));
                Bs[nb][bk[i]][bn[i] + 3] = __uint_as_float(f2tf32(breg[i].w));
            }
            __syncthreads();
        }
    }

    // ---- epilogue ----
    #pragma unroll
    for (int i = 0; i < 4; i++) {
        #pragma unroll
        for (int j = 0; j < 4; j++) {
            int col = n0 + wn + j * 8 + 2 * tg;
            int r0  = m0 + wm + i * 16 + g;
            int r1  = r0 + 8;
            float bx = 0.f, by = 0.f;
            if (bias) { bx = bias[col]; by = bias[col + 1]; }
            if (r0 < M) {
                size_t o0 = (size_t)r0 * N + col;
                float2 v; v.x = c[i][j][0] + bx; v.y = c[i][j][1] + by;
                if (Res) { float2 rr = *(const float2*)&Res[o0]; v.x += rr.x; v.y += rr.y; }
                *(float2*)&C[o0] = v;
            }
            if (r1 < M) {
                size_t o1 = (size_t)r1 * N + col;
                float2 v; v.x = c[i][j][2] + bx; v.y = c[i][j][3] + by;
                if (Res) { float2 rr = *(const float2*)&Res[o1]; v.x += rr.x; v.y += rr.y; }
                *(float2*)&C[o1] = v;
            }
        }
    }
}

// ---------------- Flash attention: one thread per query row ----------------
__global__ __launch_bounds__(128) void attn_kernel(
    const float* __restrict__ Q, const float* __restrict__ K,
    const float* __restrict__ V, float* __restrict__ O, int N, int S)
{
    __shared__ float Ks[64 * 64];
    __shared__ float Vs[64 * 64];
    int b = blockIdx.z, h = blockIdx.y;
    int n = blockIdx.x * 128 + threadIdx.x;
    const float scale = 0.125f;  // 1/sqrt(64)
    size_t qoff = ((size_t)(b * N + n)) * DIM + h * DHEAD;

    float qv[64];
    #pragma unroll
    for (int d = 0; d < 64; d += 4)
        *(float4*)&qv[d] = *(const float4*)&Q[qoff + d];

    float acc[64];
    #pragma unroll
    for (int d = 0; d < 64; d++) acc[d] = 0.f;
    float mrow = -1e30f, lrow = 0.f;

    for (int s0 = 0; s0 < S; s0 += 64) {
        __syncthreads();
        for (int i = threadIdx.x; i < 64 * 16; i += 128) {
            int r = i >> 4;
            int d4 = (i & 15) * 4;
            int sg = s0 + r;
            float4 kv = make_float4(0.f, 0.f, 0.f, 0.f), vv = kv;
            if (sg < S) {
                size_t off = ((size_t)(b * S + sg)) * DIM + h * DHEAD + d4;
                kv = *(const float4*)&K[off];
                vv = *(const float4*)&V[off];
            }
            *(float4*)&Ks[r * 64 + d4] = kv;
            *(float4*)&Vs[r * 64 + d4] = vv;
        }
        __syncthreads();
        int jmax = min(64, S - s0);
        for (int j = 0; j < jmax; j++) {
            const float* kr = &Ks[j * 64];
            float s_0 = 0.f, s_1 = 0.f, s_2 = 0.f, s_3 = 0.f;
            #pragma unroll
            for (int d = 0; d < 64; d += 4) {
                s_0 = fmaf(qv[d + 0], kr[d + 0], s_0);
                s_1 = fmaf(qv[d + 1], kr[d + 1], s_1);
                s_2 = fmaf(qv[d + 2], kr[d + 2], s_2);
                s_3 = fmaf(qv[d + 3], kr[d + 3], s_3);
            }
            float s = (s_0 + s_1 + s_2 + s_3) * scale;
            float mnew = fmaxf(mrow, s);
            float corr = __expf(mrow - mnew);
            float p    = __expf(s - mnew);
            lrow = lrow * corr + p;
            const float* vr = &Vs[j * 64];
            #pragma unroll
            for (int d = 0; d < 64; d++)
                acc[d] = fmaf(acc[d], corr, p * vr[d]);
            mrow = mnew;
        }
    }
    float inv = 1.f / lrow;
    #pragma unroll
    for (int d = 0; d < 64; d += 4) {
        float4 o;
        o.x = acc[d + 0] * inv; o.y = acc[d + 1] * inv;
        o.z = acc[d + 2] * inv; o.w = acc[d + 3] * inv;
        *(float4*)&O[qoff + d] = o;
    }
}

// ---------------- GEGLU: out[m,j] = h[m,j] * gelu(h[m,4096+j]) ----------------
__global__ __launch_bounds__(256) void geglu_kernel(
    const float* __restrict__ h, float* __restrict__ out)
{
    size_t i = (size_t)blockIdx.x * 256 + threadIdx.x;
    if (i >= (size_t)BTOK * FFIN) return;
    size_t m = i >> 12;        // / 4096
    size_t j = i & (FFIN - 1);
    float a = h[m * (2 * FFIN) + j];
    float g = h[m * (2 * FFIN) + FFIN + j];
    float gl = 0.5f * g * (1.f + erff(g * 0.70710678118654752f));
    out[i] = a * gl;
}

// ---------------- host orchestration ----------------
extern "C" void kernel_launch(void* const* d_in, const int* in_sizes, int n_in,
                              void* d_out, int out_size)
{
    (void)in_sizes; (void)n_in; (void)out_size;
    const float* x    = (const float*)d_in[0];
    const float* ctx  = (const float*)d_in[1];
    const float* Wq1  = (const float*)d_in[2];
    const float* Wk1  = (const float*)d_in[3];
    const float* Wv1  = (const float*)d_in[4];
    const float* Wo1  = (const float*)d_in[5];
    const float* bo1  = (const float*)d_in[6];
    const float* Wq2  = (const float*)d_in[7];
    const float* Wk2  = (const float*)d_in[8];
    const float* Wv2  = (const float*)d_in[9];
    const float* Wo2  = (const float*)d_in[10];
    const float* bo2  = (const float*)d_in[11];
    const float* Wp   = (const float*)d_in[12];
    const float* bp   = (const float*)d_in[13];
    const float* Wf   = (const float*)d_in[14];
    const float* bf   = (const float*)d_in[15];
    const float* g1   = (const float*)d_in[16];
    const float* b1   = (const float*)d_in[17];
    const float* g2   = (const float*)d_in[18];
    const float* b2   = (const float*)d_in[19];
    const float* g3   = (const float*)d_in[20];
    const float* b3   = (const float*)d_in[21];
    float* out = (float*)d_out;

    float *ln, *q, *k, *v, *att, *xb, *hb, *gl;
    cudaGetSymbolAddress((void**)&ln,  g_ln);
    cudaGetSymbolAddress((void**)&q,   g_q);
    cudaGetSymbolAddress((void**)&k,   g_k);
    cudaGetSymbolAddress((void**)&v,   g_v);
    cudaGetSymbolAddress((void**)&att, g_att);
    cudaGetSymbolAddress((void**)&xb,  g_x);
    cudaGetSymbolAddress((void**)&hb,  g_h);
    cudaGetSymbolAddress((void**)&gl,  g_gl);

    const int B = 4, N = 2048, S = 77;
    const int M = B * N;           // 8192
    const int Mc = B * S;          // 308

    dim3 gemm1024(1024 / 128, M / 128);          // N=1024, M=8192
    dim3 gemmCtx(1024 / 128, (Mc + 127) / 128);  // N=1024, M=308
    dim3 gemmWp(2 * FFIN / 128, M / 128);        // N=8192, M=8192
    dim3 attnGrid(N / 128, HEADS, B);

    // ---- stage 1: self-attention ----
    ln_kernel<<<M, 256>>>(x, g1, b1, ln);
    tf32_gemm<<<gemm1024, 256>>>(ln, Wq1, nullptr, nullptr, q, M, 1024, 1024);
    tf32_gemm<<<gemm1024, 256>>>(ln, Wk1, nullptr, nullptr, k, M, 1024, 1024);
    tf32_gemm<<<gemm1024, 256>>>(ln, Wv1, nullptr, nullptr, v, M, 1024, 1024);
    attn_kernel<<<attnGrid, 128>>>(q, k, v, att, N, N);
    tf32_gemm<<<gemm1024, 256>>>(att, Wo1, bo1, x, xb, M, 1024, 1024);

    // ---- stage 2: cross-attention ----
    ln_kernel<<<M, 256>>>(xb, g2, b2, ln);
    tf32_gemm<<<gemm1024, 256>>>(ln, Wq2, nullptr, nullptr, q, M, 1024, 1024);
    tf32_gemm<<<gemmCtx, 256>>>(ctx, Wk2, nullptr, nullptr, k, Mc, 1024, 768);
    tf32_gemm<<<gemmCtx, 256>>>(ctx, Wv2, nullptr, nullptr, v, Mc, 1024, 768);
    attn_kernel<<<attnGrid, 128>>>(q, k, v, att, N, S);
    tf32_gemm<<<gemm1024, 256>>>(att, Wo2, bo2, xb, xb, M, 1024, 1024);

    // ---- stage 3: GEGLU feed-forward ----
    ln_kernel<<<M, 256>>>(xb, g3, b3, ln);
    tf32_gemm<<<gemmWp, 256>>>(ln, Wp, bp, nullptr, hb, M, 2 * FFIN, 1024);
    {
        size_t total = (size_t)M * FFIN;
        int blocks = (int)((total + 255) / 256);
        geglu_kernel<<<blocks, 256>>>(hb, gl);
    }
    tf32_gemm<<<gemm1024, 256>>>(gl, Wf, bf, xb, out, M, 1024, FFIN);
}

// round 5
// speedup vs baseline: 3.1366x; 1.7331x over previous
#include <cuda_runtime.h>
#include <math.h>

#define DIM   1024
#define HEADS 16
#define DHEAD 64
#define BTOK  8192   // 4 * 2048 tokens
#define FFIN  4096

// ---------------- scratch (device globals: allocation-free) ----------------
__device__ float g_ln [BTOK * DIM];
__device__ float g_q  [BTOK * DIM];
__device__ float g_k  [BTOK * DIM];
__device__ float g_v  [BTOK * DIM];
__device__ float g_att[BTOK * DIM];
__device__ float g_x  [BTOK * DIM];
__device__ float g_h  [(size_t)BTOK * (2 * FFIN)];
__device__ float g_gl [(size_t)BTOK * FFIN];

__device__ __forceinline__ unsigned f2tf32(float x) {
    unsigned u;
    asm("cvt.rna.tf32.f32 %0, %1;" : "=r"(u) : "f"(x));
    return u;
}
__device__ __forceinline__ float tf32f(float x) {
    return __uint_as_float(f2tf32(x));
}

#define MMA_TF32(c0,c1,c2,c3,a0,a1,a2,a3,b0,b1)                              \
    asm volatile(                                                            \
        "mma.sync.aligned.m16n8k8.row.col.f32.tf32.tf32.f32 "                \
        "{%0,%1,%2,%3}, {%4,%5,%6,%7}, {%8,%9}, {%0,%1,%2,%3};"              \
        : "+f"(c0), "+f"(c1), "+f"(c2), "+f"(c3)                             \
        : "r"(a0), "r"(a1), "r"(a2), "r"(a3), "r"(b0), "r"(b1))

// ---------------- LayerNorm: one block per row (dim=1024) ----------------
__global__ __launch_bounds__(256) void ln_kernel(
    const float* __restrict__ x, const float* __restrict__ gamma,
    const float* __restrict__ beta, float* __restrict__ out)
{
    int row = blockIdx.x;
    int tid = threadIdx.x;
    const float4* xr = (const float4*)(x + (size_t)row * DIM);
    float4 t = xr[tid];
    float s = t.x + t.y + t.z + t.w;
    float q = t.x * t.x + t.y * t.y + t.z * t.z + t.w * t.w;
    #pragma unroll
    for (int o = 16; o; o >>= 1) {
        s += __shfl_xor_sync(0xffffffffu, s, o);
        q += __shfl_xor_sync(0xffffffffu, q, o);
    }
    __shared__ float ssum[8], ssq[8];
    __shared__ float smean, srstd;
    int wid = tid >> 5, lane = tid & 31;
    if (lane == 0) { ssum[wid] = s; ssq[wid] = q; }
    __syncthreads();
    if (tid == 0) {
        float S = 0.f, Q = 0.f;
        #pragma unroll
        for (int i = 0; i < 8; i++) { S += ssum[i]; Q += ssq[i]; }
        float mean = S * (1.f / DIM);
        float var  = Q * (1.f / DIM) - mean * mean;
        smean = mean;
        srstd = rsqrtf(var + 1e-5f);
    }
    __syncthreads();
    float mean = smean, rstd = srstd;
    float4 gg = ((const float4*)gamma)[tid];
    float4 bb = ((const float4*)beta)[tid];
    float4 o;
    o.x = (t.x - mean) * rstd * gg.x + bb.x;
    o.y = (t.y - mean) * rstd * gg.y + bb.y;
    o.z = (t.z - mean) * rstd * gg.z + bb.z;
    o.w = (t.w - mean) * rstd * gg.w + bb.w;
    ((float4*)(out + (size_t)row * DIM))[tid] = o;
}

// ---------------- TF32 tensor-core GEMM ----------------
__global__ __launch_bounds__(256, 2) void tf32_gemm(
    const float* __restrict__ A, const float* __restrict__ B,
    const float* __restrict__ bias, const float* __restrict__ Res,
    float* __restrict__ C, int M, int N, int K)
{
    __shared__ float As[2][128][20];
    __shared__ float Bs[2][16][136];

    const int t = threadIdx.x;
    const int m0 = blockIdx.y * 128, n0 = blockIdx.x * 128;
    const int warp = t >> 5, lane = t & 31;
    const int wm = (warp & 1) * 64;
    const int wn = (warp >> 1) * 32;
    const int g  = lane >> 2;
    const int tg = lane & 3;

    float4 areg[2], breg[2];
    int am[2], ak[2], bk[2], bn[2];
    bool aval[2];
    #pragma unroll
    for (int i = 0; i < 2; i++) {
        int lin = t + i * 256;
        am[i] = lin >> 2;  ak[i] = (lin & 3) << 2;
        bk[i] = lin >> 5;  bn[i] = (lin & 31) << 2;
        aval[i] = (m0 + am[i]) < M;
    }

    float c[4][4][4];
    #pragma unroll
    for (int i = 0; i < 4; i++)
        #pragma unroll
        for (int j = 0; j < 4; j++)
            #pragma unroll
            for (int r = 0; r < 4; r++) c[i][j][r] = 0.f;

    const int T = K / 16;

    #pragma unroll
    for (int i = 0; i < 2; i++) {
        areg[i] = aval[i] ? *(const float4*)&A[(size_t)(m0 + am[i]) * K + ak[i]]
                          : make_float4(0.f, 0.f, 0.f, 0.f);
        breg[i] = *(const float4*)&B[(size_t)bk[i] * N + n0 + bn[i]];
    }
    #pragma unroll
    for (int i = 0; i < 2; i++) {
        As[0][am[i]][ak[i] + 0] = tf32f(areg[i].x);
        As[0][am[i]][ak[i] + 1] = tf32f(areg[i].y);
        As[0][am[i]][ak[i] + 2] = tf32f(areg[i].z);
        As[0][am[i]][ak[i] + 3] = tf32f(areg[i].w);
        Bs[0][bk[i]][bn[i] + 0] = tf32f(breg[i].x);
        Bs[0][bk[i]][bn[i] + 1] = tf32f(breg[i].y);
        Bs[0][bk[i]][bn[i] + 2] = tf32f(breg[i].z);
        Bs[0][bk[i]][bn[i] + 3] = tf32f(breg[i].w);
    }
    __syncthreads();

    #pragma unroll 2
    for (int tt = 0; tt < T; tt++) {
        const int buf = tt & 1;
        if (tt + 1 < T) {
            int k0 = (tt + 1) * 16;
            #pragma unroll
            for (int i = 0; i < 2; i++) {
                areg[i] = aval[i] ? *(const float4*)&A[(size_t)(m0 + am[i]) * K + k0 + ak[i]]
                                  : make_float4(0.f, 0.f, 0.f, 0.f);
                breg[i] = *(const float4*)&B[(size_t)(k0 + bk[i]) * N + n0 + bn[i]];
            }
        }

        #pragma unroll
        for (int kk = 0; kk < 16; kk += 8) {
            unsigned a[4][4], b[4][2];
            #pragma unroll
            for (int i = 0; i < 4; i++) {
                int mb = wm + i * 16;
                a[i][0] = __float_as_uint(As[buf][mb + g    ][kk + tg    ]);
                a[i][1] = __float_as_uint(As[buf][mb + g + 8][kk + tg    ]);
                a[i][2] = __float_as_uint(As[buf][mb + g    ][kk + tg + 4]);
                a[i][3] = __float_as_uint(As[buf][mb + g + 8][kk + tg + 4]);
            }
            #pragma unroll
            for (int j = 0; j < 4; j++) {
                int nb = wn + j * 8;
                b[j][0] = __float_as_uint(Bs[buf][kk + tg    ][nb + g]);
                b[j][1] = __float_as_uint(Bs[buf][kk + tg + 4][nb + g]);
            }
            #pragma unroll
            for (int i = 0; i < 4; i++)
                #pragma unroll
                for (int j = 0; j < 4; j++)
                    MMA_TF32(c[i][j][0], c[i][j][1], c[i][j][2], c[i][j][3],
                             a[i][0], a[i][1], a[i][2], a[i][3],
                             b[j][0], b[j][1]);
        }
        __syncthreads();

        if (tt + 1 < T) {
            const int nb = (tt + 1) & 1;
            #pragma unroll
            for (int i = 0; i < 2; i++) {
                As[nb][am[i]][ak[i] + 0] = tf32f(areg[i].x);
                As[nb][am[i]][ak[i] + 1] = tf32f(areg[i].y);
                As[nb][am[i]][ak[i] + 2] = tf32f(areg[i].z);
                As[nb][am[i]][ak[i] + 3] = tf32f(areg[i].w);
                Bs[nb][bk[i]][bn[i] + 0] = tf32f(breg[i].x);
                Bs[nb][bk[i]][bn[i] + 1] = tf32f(breg[i].y);
                Bs[nb][bk[i]][bn[i] + 2] = tf32f(breg[i].z);
                Bs[nb][bk[i]][bn[i] + 3] = tf32f(breg[i].w);
            }
            __syncthreads();
        }
    }

    #pragma unroll
    for (int i = 0; i < 4; i++) {
        #pragma unroll
        for (int j = 0; j < 4; j++) {
            int col = n0 + wn + j * 8 + 2 * tg;
            int r0  = m0 + wm + i * 16 + g;
            int r1  = r0 + 8;
            float bx = 0.f, by = 0.f;
            if (bias) { bx = bias[col]; by = bias[col + 1]; }
            if (r0 < M) {
                size_t o0 = (size_t)r0 * N + col;
                float2 v; v.x = c[i][j][0] + bx; v.y = c[i][j][1] + by;
                if (Res) { float2 rr = *(const float2*)&Res[o0]; v.x += rr.x; v.y += rr.y; }
                *(float2*)&C[o0] = v;
            }
            if (r1 < M) {
                size_t o1 = (size_t)r1 * N + col;
                float2 v; v.x = c[i][j][2] + bx; v.y = c[i][j][3] + by;
                if (Res) { float2 rr = *(const float2*)&Res[o1]; v.x += rr.x; v.y += rr.y; }
                *(float2*)&C[o1] = v;
            }
        }
    }
}

// ---------------- TF32 tensor-core flash attention ----------------
// Q block 128 rows (8 warps x m16), K/V chunks of 64, D=64.
// Layouts (floats): Qs/Ps [128][68], Ks [64][68], Vs [64][72].
// All fragment LDS patterns are 32-bank conflict-free by stride choice.
#define QP_ST 68
#define K_ST  68
#define V_ST  72
#define ATTN_SMEM ((128 * QP_ST + 64 * K_ST + 64 * V_ST) * 4)

__global__ __launch_bounds__(256) void attn_mma(
    const float* __restrict__ Q, const float* __restrict__ K,
    const float* __restrict__ V, float* __restrict__ O, int N, int S)
{
    extern __shared__ float sm[];
    float* Qs = sm;                       // reused as Ps after frag load
    float* Ks = sm + 128 * QP_ST;
    float* Vs = sm + 128 * QP_ST + 64 * K_ST;

    const int t = threadIdx.x, warp = t >> 5, lane = t & 31;
    const int g = lane >> 2, tg = lane & 3;
    const int b = blockIdx.z, h = blockIdx.y;
    const int q0 = blockIdx.x * 128;
    const int mb = warp * 16;
    const float scale = 0.125f;

    // ---- load Q tile (coalesced, tf32-converted) ----
    #pragma unroll
    for (int it = 0; it < 8; it++) {
        int lin = t + it * 256;
        int r = lin >> 4;
        int d4 = (lin & 15) * 4;
        float4 qv = *(const float4*)&Q[((size_t)(b * N + q0 + r)) * DIM + h * DHEAD + d4];
        float4 cv;
        cv.x = tf32f(qv.x); cv.y = tf32f(qv.y);
        cv.z = tf32f(qv.z); cv.w = tf32f(qv.w);
        *(float4*)&Qs[r * QP_ST + d4] = cv;
    }
    __syncthreads();

    // ---- Q fragments to registers (warp-private rows) ----
    unsigned aq[8][4];
    #pragma unroll
    for (int kk = 0; kk < 8; kk++) {
        aq[kk][0] = __float_as_uint(Qs[(mb + g    ) * QP_ST + kk * 8 + tg    ]);
        aq[kk][1] = __float_as_uint(Qs[(mb + g + 8) * QP_ST + kk * 8 + tg    ]);
        aq[kk][2] = __float_as_uint(Qs[(mb + g    ) * QP_ST + kk * 8 + tg + 4]);
        aq[kk][3] = __float_as_uint(Qs[(mb + g + 8) * QP_ST + kk * 8 + tg + 4]);
    }
    __syncthreads();   // Qs now reusable as Ps

    float o[8][4];
    #pragma unroll
    for (int j = 0; j < 8; j++)
        #pragma unroll
        for (int r = 0; r < 4; r++) o[j][r] = 0.f;
    float m0_ = -1e30f, m1_ = -1e30f, l0_ = 0.f, l1_ = 0.f;

    for (int s0 = 0; s0 < S; s0 += 64) {
        // ---- cooperative K/V chunk load (zero-padded tail) ----
        #pragma unroll
        for (int it = 0; it < 4; it++) {
            int lin = t + it * 256;
            int r = lin >> 4;
            int d4 = (lin & 15) * 4;
            int sg = s0 + r;
            float4 kv = make_float4(0.f, 0.f, 0.f, 0.f), vv = kv;
            if (sg < S) {
                size_t off = ((size_t)(b * S + sg)) * DIM + h * DHEAD + d4;
                kv = *(const float4*)&K[off];
                vv = *(const float4*)&V[off];
            }
            float4 kc, vc;
            kc.x = tf32f(kv.x); kc.y = tf32f(kv.y); kc.z = tf32f(kv.z); kc.w = tf32f(kv.w);
            vc.x = tf32f(vv.x); vc.y = tf32f(vv.y); vc.z = tf32f(vv.z); vc.w = tf32f(vv.w);
            *(float4*)&Ks[r * K_ST + d4] = kc;
            *(float4*)&Vs[r * V_ST + d4] = vc;
        }
        __syncthreads();

        // ---- scores = Q @ K^T  (B-frag read directly from K[s][d]) ----
        float sc[8][4];
        #pragma unroll
        for (int j = 0; j < 8; j++) {
            sc[j][0] = sc[j][1] = sc[j][2] = sc[j][3] = 0.f;
            #pragma unroll
            for (int kk = 0; kk < 8; kk++) {
                unsigned b0 = __float_as_uint(Ks[(j * 8 + g) * K_ST + kk * 8 + tg    ]);
                unsigned b1 = __float_as_uint(Ks[(j * 8 + g) * K_ST + kk * 8 + tg + 4]);
                MMA_TF32(sc[j][0], sc[j][1], sc[j][2], sc[j][3],
                         aq[kk][0], aq[kk][1], aq[kk][2], aq[kk][3], b0, b1);
            }
        }

        // ---- scale + mask ----
        bool tail = (s0 + 64 > S);
        #pragma unroll
        for (int j = 0; j < 8; j++) {
            sc[j][0] *= scale; sc[j][1] *= scale;
            sc[j][2] *= scale; sc[j][3] *= scale;
            if (tail) {
                int col = s0 + j * 8 + 2 * tg;
                if (col     >= S) { sc[j][0] = -1e30f; sc[j][2] = -1e30f; }
                if (col + 1 >= S) { sc[j][1] = -1e30f; sc[j][3] = -1e30f; }
            }
        }

        // ---- online softmax (rows g, g+8) ----
        float rm0 = -1e30f, rm1 = -1e30f;
        #pragma unroll
        for (int j = 0; j < 8; j++) {
            rm0 = fmaxf(rm0, fmaxf(sc[j][0], sc[j][1]));
            rm1 = fmaxf(rm1, fmaxf(sc[j][2], sc[j][3]));
        }
        rm0 = fmaxf(rm0, __shfl_xor_sync(0xffffffffu, rm0, 1));
        rm0 = fmaxf(rm0, __shfl_xor_sync(0xffffffffu, rm0, 2));
        rm1 = fmaxf(rm1, __shfl_xor_sync(0xffffffffu, rm1, 1));
        rm1 = fmaxf(rm1, __shfl_xor_sync(0xffffffffu, rm1, 2));
        float nm0 = fmaxf(m0_, rm0), nm1 = fmaxf(m1_, rm1);
        float cc0 = __expf(m0_ - nm0), cc1 = __expf(m1_ - nm1);
        m0_ = nm0; m1_ = nm1;

        float rs0 = 0.f, rs1 = 0.f;
        #pragma unroll
        for (int j = 0; j < 8; j++) {
            float p0 = __expf(sc[j][0] - nm0);
            float p1 = __expf(sc[j][1] - nm0);
            float p2 = __expf(sc[j][2] - nm1);
            float p3 = __expf(sc[j][3] - nm1);
            rs0 += p0 + p1; rs1 += p2 + p3;
            float2 v01; v01.x = tf32f(p0); v01.y = tf32f(p1);
            float2 v23; v23.x = tf32f(p2); v23.y = tf32f(p3);
            *(float2*)&Qs[(mb + g    ) * QP_ST + j * 8 + 2 * tg] = v01;
            *(float2*)&Qs[(mb + g + 8) * QP_ST + j * 8 + 2 * tg] = v23;
        }
        rs0 += __shfl_xor_sync(0xffffffffu, rs0, 1);
        rs0 += __shfl_xor_sync(0xffffffffu, rs0, 2);
        rs1 += __shfl_xor_sync(0xffffffffu, rs1, 1);
        rs1 += __shfl_xor_sync(0xffffffffu, rs1, 2);
        l0_ = l0_ * cc0 + rs0;
        l1_ = l1_ * cc1 + rs1;

        #pragma unroll
        for (int j = 0; j < 8; j++) {
            o[j][0] *= cc0; o[j][1] *= cc0;
            o[j][2] *= cc1; o[j][3] *= cc1;
        }
        __syncwarp();   // P rows are warp-private; order STS->LDS across lanes

        // ---- O += P @ V  (B-frag read directly from V[s][d]) ----
        #pragma unroll
        for (int kk = 0; kk < 8; kk++) {
            unsigned ap[4];
            ap[0] = __float_as_uint(Qs[(mb + g    ) * QP_ST + kk * 8 + tg    ]);
            ap[1] = __float_as_uint(Qs[(mb + g + 8) * QP_ST + kk * 8 + tg    ]);
            ap[2] = __float_as_uint(Qs[(mb + g    ) * QP_ST + kk * 8 + tg + 4]);
            ap[3] = __float_as_uint(Qs[(mb + g + 8) * QP_ST + kk * 8 + tg + 4]);
            #pragma unroll
            for (int j = 0; j < 8; j++) {
                unsigned b0 = __float_as_uint(Vs[(kk * 8 + tg    ) * V_ST + j * 8 + g]);
                unsigned b1 = __float_as_uint(Vs[(kk * 8 + tg + 4) * V_ST + j * 8 + g]);
                MMA_TF32(o[j][0], o[j][1], o[j][2], o[j][3],
                         ap[0], ap[1], ap[2], ap[3], b0, b1);
            }
        }
        __syncthreads();   // before next chunk overwrites Ks/Vs
    }

    // ---- normalize + store ----
    float inv0 = 1.f / l0_, inv1 = 1.f / l1_;
    size_t r0 = ((size_t)(b * N + q0 + mb + g    )) * DIM + h * DHEAD;
    size_t r1 = ((size_t)(b * N + q0 + mb + g + 8)) * DIM + h * DHEAD;
    #pragma unroll
    for (int j = 0; j < 8; j++) {
        float2 v0; v0.x = o[j][0] * inv0; v0.y = o[j][1] * inv0;
        float2 v1; v1.x = o[j][2] * inv1; v1.y = o[j][3] * inv1;
        *(float2*)&O[r0 + j * 8 + 2 * tg] = v0;
        *(float2*)&O[r1 + j * 8 + 2 * tg] = v1;
    }
}

// ---------------- GEGLU: out[m,j] = h[m,j] * gelu(h[m,4096+j]) ----------------
__global__ __launch_bounds__(256) void geglu_kernel(
    const float* __restrict__ h, float* __restrict__ out)
{
    size_t i = (size_t)blockIdx.x * 256 + threadIdx.x;
    if (i >= (size_t)BTOK * FFIN) return;
    size_t m = i >> 12;        // / 4096
    size_t j = i & (FFIN - 1);
    float a = h[m * (2 * FFIN) + j];
    float g = h[m * (2 * FFIN) + FFIN + j];
    float gl = 0.5f * g * (1.f + erff(g * 0.70710678118654752f));
    out[i] = a * gl;
}

// ---------------- host orchestration ----------------
extern "C" void kernel_launch(void* const* d_in, const int* in_sizes, int n_in,
                              void* d_out, int out_size)
{
    (void)in_sizes; (void)n_in; (void)out_size;
    const float* x    = (const float*)d_in[0];
    const float* ctx  = (const float*)d_in[1];
    const float* Wq1  = (const float*)d_in[2];
    const float* Wk1  = (const float*)d_in[3];
    const float* Wv1  = (const float*)d_in[4];
    const float* Wo1  = (const float*)d_in[5];
    const float* bo1  = (const float*)d_in[6];
    const float* Wq2  = (const float*)d_in[7];
    const float* Wk2  = (const float*)d_in[8];
    const float* Wv2  = (const float*)d_in[9];
    const float* Wo2  = (const float*)d_in[10];
    const float* bo2  = (const float*)d_in[11];
    const float* Wp   = (const float*)d_in[12];
    const float* bp   = (const float*)d_in[13];
    const float* Wf   = (const float*)d_in[14];
    const float* bf   = (const float*)d_in[15];
    const float* g1   = (const float*)d_in[16];
    const float* b1   = (const float*)d_in[17];
    const float* g2   = (const float*)d_in[18];
    const float* b2   = (const float*)d_in[19];
    const float* g3   = (const float*)d_in[20];
    const float* b3   = (const float*)d_in[21];
    float* out = (float*)d_out;

    float *ln, *q, *k, *v, *att, *xb, *hb, *gl;
    cudaGetSymbolAddress((void**)&ln,  g_ln);
    cudaGetSymbolAddress((void**)&q,   g_q);
    cudaGetSymbolAddress((void**)&k,   g_k);
    cudaGetSymbolAddress((void**)&v,   g_v);
    cudaGetSymbolAddress((void**)&att, g_att);
    cudaGetSymbolAddress((void**)&xb,  g_x);
    cudaGetSymbolAddress((void**)&hb,  g_h);
    cudaGetSymbolAddress((void**)&gl,  g_gl);

    cudaFuncSetAttribute(attn_mma,
        cudaFuncAttributeMaxDynamicSharedMemorySize, ATTN_SMEM);

    const int B = 4, N = 2048, S = 77;
    const int M = B * N;           // 8192
    const int Mc = B * S;          // 308

    dim3 gemm1024(1024 / 128, M / 128);
    dim3 gemmCtx(1024 / 128, (Mc + 127) / 128);
    dim3 gemmWp(2 * FFIN / 128, M / 128);
    dim3 attnGrid(N / 128, HEADS, B);

    // ---- stage 1: self-attention ----
    ln_kernel<<<M, 256>>>(x, g1, b1, ln);
    tf32_gemm<<<gemm1024, 256>>>(ln, Wq1, nullptr, nullptr, q, M, 1024, 1024);
    tf32_gemm<<<gemm1024, 256>>>(ln, Wk1, nullptr, nullptr, k, M, 1024, 1024);
    tf32_gemm<<<gemm1024, 256>>>(ln, Wv1, nullptr, nullptr, v, M, 1024, 1024);
    attn_mma<<<attnGrid, 256, ATTN_SMEM>>>(q, k, v, att, N, N);
    tf32_gemm<<<gemm1024, 256>>>(att, Wo1, bo1, x, xb, M, 1024, 1024);

    // ---- stage 2: cross-attention ----
    ln_kernel<<<M, 256>>>(xb, g2, b2, ln);
    tf32_gemm<<<gemm1024, 256>>>(ln, Wq2, nullptr, nullptr, q, M, 1024, 1024);
    tf32_gemm<<<gemmCtx, 256>>>(ctx, Wk2, nullptr, nullptr, k, Mc, 1024, 768);
    tf32_gemm<<<gemmCtx, 256>>>(ctx, Wv2, nullptr, nullptr, v, Mc, 1024, 768);
    attn_mma<<<attnGrid, 256, ATTN_SMEM>>>(q, k, v, att, N, S);
    tf32_gemm<<<gemm1024, 256>>>(att, Wo2, bo2, xb, xb, M, 1024, 1024);

    // ---- stage 3: GEGLU feed-forward ----
    ln_kernel<<<M, 256>>>(xb, g3, b3, ln);
    tf32_gemm<<<gemmWp, 256>>>(ln, Wp, bp, nullptr, hb, M, 2 * FFIN, 1024);
    {
        size_t total = (size_t)M * FFIN;
        int blocks = (int)((total + 255) / 256);
        geglu_kernel<<<blocks, 256>>>(hb, gl);
    }
    tf32_gemm<<<gemm1024, 256>>>(gl, Wf, bf, xb, out, M, 1024, FFIN);
}

// round 6
// speedup vs baseline: 3.1485x; 1.0038x over previous
#include <cuda_runtime.h>
#include <math.h>

#define DIM   1024
#define HEADS 16
#define DHEAD 64
#define BTOK  8192   // 4 * 2048 tokens
#define FFIN  4096

// ---------------- scratch (device globals: allocation-free) ----------------
__device__ float g_ln [BTOK * DIM];
__device__ float g_q  [BTOK * DIM];
__device__ float g_k  [BTOK * DIM];
__device__ float g_v  [BTOK * DIM];
__device__ float g_att[BTOK * DIM];
__device__ float g_x  [BTOK * DIM];
__device__ float g_h  [(size_t)BTOK * (2 * FFIN)];
__device__ float g_gl [(size_t)BTOK * FFIN];

__device__ __forceinline__ unsigned f2tf32(float x) {
    unsigned u;
    asm("cvt.rna.tf32.f32 %0, %1;" : "=r"(u) : "f"(x));
    return u;
}
__device__ __forceinline__ float tf32f(float x) {
    return __uint_as_float(f2tf32(x));
}

#define MMA_TF32(c0,c1,c2,c3,a0,a1,a2,a3,b0,b1)                              \
    asm volatile(                                                            \
        "mma.sync.aligned.m16n8k8.row.col.f32.tf32.tf32.f32 "                \
        "{%0,%1,%2,%3}, {%4,%5,%6,%7}, {%8,%9}, {%0,%1,%2,%3};"              \
        : "+f"(c0), "+f"(c1), "+f"(c2), "+f"(c3)                             \
        : "r"(a0), "r"(a1), "r"(a2), "r"(a3), "r"(b0), "r"(b1))

// ---------------- LayerNorm: one block per row (dim=1024) ----------------
__global__ __launch_bounds__(256) void ln_kernel(
    const float* __restrict__ x, const float* __restrict__ gamma,
    const float* __restrict__ beta, float* __restrict__ out)
{
    int row = blockIdx.x;
    int tid = threadIdx.x;
    const float4* xr = (const float4*)(x + (size_t)row * DIM);
    float4 t = xr[tid];
    float s = t.x + t.y + t.z + t.w;
    float q = t.x * t.x + t.y * t.y + t.z * t.z + t.w * t.w;
    #pragma unroll
    for (int o = 16; o; o >>= 1) {
        s += __shfl_xor_sync(0xffffffffu, s, o);
        q += __shfl_xor_sync(0xffffffffu, q, o);
    }
    __shared__ float ssum[8], ssq[8];
    __shared__ float smean, srstd;
    int wid = tid >> 5, lane = tid & 31;
    if (lane == 0) { ssum[wid] = s; ssq[wid] = q; }
    __syncthreads();
    if (tid == 0) {
        float S = 0.f, Q = 0.f;
        #pragma unroll
        for (int i = 0; i < 8; i++) { S += ssum[i]; Q += ssq[i]; }
        float mean = S * (1.f / DIM);
        float var  = Q * (1.f / DIM) - mean * mean;
        smean = mean;
        srstd = rsqrtf(var + 1e-5f);
    }
    __syncthreads();
    float mean = smean, rstd = srstd;
    float4 gg = ((const float4*)gamma)[tid];
    float4 bb = ((const float4*)beta)[tid];
    float4 o;
    o.x = (t.x - mean) * rstd * gg.x + bb.x;
    o.y = (t.y - mean) * rstd * gg.y + bb.y;
    o.z = (t.z - mean) * rstd * gg.z + bb.z;
    o.w = (t.w - mean) * rstd * gg.w + bb.w;
    ((float4*)(out + (size_t)row * DIM))[tid] = o;
}

// ---------------- TF32 tensor-core GEMM ----------------
__global__ __launch_bounds__(256, 2) void tf32_gemm(
    const float* __restrict__ A, const float* __restrict__ B,
    const float* __restrict__ bias, const float* __restrict__ Res,
    float* __restrict__ C, int M, int N, int K)
{
    __shared__ float As[2][128][20];
    __shared__ float Bs[2][16][136];

    const int t = threadIdx.x;
    const int m0 = blockIdx.y * 128, n0 = blockIdx.x * 128;
    const int warp = t >> 5, lane = t & 31;
    const int wm = (warp & 1) * 64;
    const int wn = (warp >> 1) * 32;
    const int g  = lane >> 2;
    const int tg = lane & 3;

    float4 areg[2], breg[2];
    int am[2], ak[2], bk[2], bn[2];
    bool aval[2];
    #pragma unroll
    for (int i = 0; i < 2; i++) {
        int lin = t + i * 256;
        am[i] = lin >> 2;  ak[i] = (lin & 3) << 2;
        bk[i] = lin >> 5;  bn[i] = (lin & 31) << 2;
        aval[i] = (m0 + am[i]) < M;
    }

    float c[4][4][4];
    #pragma unroll
    for (int i = 0; i < 4; i++)
        #pragma unroll
        for (int j = 0; j < 4; j++)
            #pragma unroll
            for (int r = 0; r < 4; r++) c[i][j][r] = 0.f;

    const int T = K / 16;

    #pragma unroll
    for (int i = 0; i < 2; i++) {
        areg[i] = aval[i] ? *(const float4*)&A[(size_t)(m0 + am[i]) * K + ak[i]]
                          : make_float4(0.f, 0.f, 0.f, 0.f);
        breg[i] = *(const float4*)&B[(size_t)bk[i] * N + n0 + bn[i]];
    }
    #pragma unroll
    for (int i = 0; i < 2; i++) {
        As[0][am[i]][ak[i] + 0] = tf32f(areg[i].x);
        As[0][am[i]][ak[i] + 1] = tf32f(areg[i].y);
        As[0][am[i]][ak[i] + 2] = tf32f(areg[i].z);
        As[0][am[i]][ak[i] + 3] = tf32f(areg[i].w);
        Bs[0][bk[i]][bn[i] + 0] = tf32f(breg[i].x);
        Bs[0][bk[i]][bn[i] + 1] = tf32f(breg[i].y);
        Bs[0][bk[i]][bn[i] + 2] = tf32f(breg[i].z);
        Bs[0][bk[i]][bn[i] + 3] = tf32f(breg[i].w);
    }
    __syncthreads();

    #pragma unroll 2
    for (int tt = 0; tt < T; tt++) {
        const int buf = tt & 1;
        if (tt + 1 < T) {
            int k0 = (tt + 1) * 16;
            #pragma unroll
            for (int i = 0; i < 2; i++) {
                areg[i] = aval[i] ? *(const float4*)&A[(size_t)(m0 + am[i]) * K + k0 + ak[i]]
                                  : make_float4(0.f, 0.f, 0.f, 0.f);
                breg[i] = *(const float4*)&B[(size_t)(k0 + bk[i]) * N + n0 + bn[i]];
            }
        }

        #pragma unroll
        for (int kk = 0; kk < 16; kk += 8) {
            unsigned a[4][4], b[4][2];
            #pragma unroll
            for (int i = 0; i < 4; i++) {
                int mb = wm + i * 16;
                a[i][0] = __float_as_uint(As[buf][mb + g    ][kk + tg    ]);
                a[i][1] = __float_as_uint(As[buf][mb + g + 8][kk + tg    ]);
                a[i][2] = __float_as_uint(As[buf][mb + g    ][kk + tg + 4]);
                a[i][3] = __float_as_uint(As[buf][mb + g + 8][kk + tg + 4]);
            }
            #pragma unroll
            for (int j = 0; j < 4; j++) {
                int nb = wn + j * 8;
                b[j][0] = __float_as_uint(Bs[buf][kk + tg    ][nb + g]);
                b[j][1] = __float_as_uint(Bs[buf][kk + tg + 4][nb + g]);
            }
            #pragma unroll
            for (int i = 0; i < 4; i++)
                #pragma unroll
                for (int j = 0; j < 4; j++)
                    MMA_TF32(c[i][j][0], c[i][j][1], c[i][j][2], c[i][j][3],
                             a[i][0], a[i][1], a[i][2], a[i][3],
                             b[j][0], b[j][1]);
        }
        __syncthreads();

        if (tt + 1 < T) {
            const int nb = (tt + 1) & 1;
            #pragma unroll
            for (int i = 0; i < 2; i++) {
                As[nb][am[i]][ak[i] + 0] = tf32f(areg[i].x);
                As[nb][am[i]][ak[i] + 1] = tf32f(areg[i].y);
                As[nb][am[i]][ak[i] + 2] = tf32f(areg[i].z);
                As[nb][am[i]][ak[i] + 3] = tf32f(areg[i].w);
                Bs[nb][bk[i]][bn[i] + 0] = tf32f(breg[i].x);
                Bs[nb][bk[i]][bn[i] + 1] = tf32f(breg[i].y);
                Bs[nb][bk[i]][bn[i] + 2] = tf32f(breg[i].z);
                Bs[nb][bk[i]][bn[i] + 3] = tf32f(breg[i].w);
            }
            __syncthreads();
        }
    }

    #pragma unroll
    for (int i = 0; i < 4; i++) {
        #pragma unroll
        for (int j = 0; j < 4; j++) {
            int col = n0 + wn + j * 8 + 2 * tg;
            int r0  = m0 + wm + i * 16 + g;
            int r1  = r0 + 8;
            float bx = 0.f, by = 0.f;
            if (bias) { bx = bias[col]; by = bias[col + 1]; }
            if (r0 < M) {
                size_t o0 = (size_t)r0 * N + col;
                float2 v; v.x = c[i][j][0] + bx; v.y = c[i][j][1] + by;
                if (Res) { float2 rr = *(const float2*)&Res[o0]; v.x += rr.x; v.y += rr.y; }
                *(float2*)&C[o0] = v;
            }
            if (r1 < M) {
                size_t o1 = (size_t)r1 * N + col;
                float2 v; v.x = c[i][j][2] + bx; v.y = c[i][j][3] + by;
                if (Res) { float2 rr = *(const float2*)&Res[o1]; v.x += rr.x; v.y += rr.y; }
                *(float2*)&C[o1] = v;
            }
        }
    }
}

// ---------------- TF32 tensor-core flash attention ----------------
// Q block 128 rows (8 warps x m16), K/V chunks of 64, D=64.
// Layouts (floats): Qs/Ps [128][68], Ks [64][68], Vs [64][72].
// All fragment LDS patterns are 32-bank conflict-free by stride choice.
#define QP_ST 68
#define K_ST  68
#define V_ST  72
#define ATTN_SMEM ((128 * QP_ST + 64 * K_ST + 64 * V_ST) * 4)

__global__ __launch_bounds__(256) void attn_mma(
    const float* __restrict__ Q, const float* __restrict__ K,
    const float* __restrict__ V, float* __restrict__ O, int N, int S)
{
    extern __shared__ float sm[];
    float* Qs = sm;                       // reused as Ps after frag load
    float* Ks = sm + 128 * QP_ST;
    float* Vs = sm + 128 * QP_ST + 64 * K_ST;

    const int t = threadIdx.x, warp = t >> 5, lane = t & 31;
    const int g = lane >> 2, tg = lane & 3;
    const int b = blockIdx.z, h = blockIdx.y;
    const int q0 = blockIdx.x * 128;
    const int mb = warp * 16;
    const float scale = 0.125f;

    // ---- load Q tile (coalesced, tf32-converted) ----
    #pragma unroll
    for (int it = 0; it < 8; it++) {
        int lin = t + it * 256;
        int r = lin >> 4;
        int d4 = (lin & 15) * 4;
        float4 qv = *(const float4*)&Q[((size_t)(b * N + q0 + r)) * DIM + h * DHEAD + d4];
        float4 cv;
        cv.x = tf32f(qv.x); cv.y = tf32f(qv.y);
        cv.z = tf32f(qv.z); cv.w = tf32f(qv.w);
        *(float4*)&Qs[r * QP_ST + d4] = cv;
    }
    __syncthreads();

    // ---- Q fragments to registers (warp-private rows) ----
    unsigned aq[8][4];
    #pragma unroll
    for (int kk = 0; kk < 8; kk++) {
        aq[kk][0] = __float_as_uint(Qs[(mb + g    ) * QP_ST + kk * 8 + tg    ]);
        aq[kk][1] = __float_as_uint(Qs[(mb + g + 8) * QP_ST + kk * 8 + tg    ]);
        aq[kk][2] = __float_as_uint(Qs[(mb + g    ) * QP_ST + kk * 8 + tg + 4]);
        aq[kk][3] = __float_as_uint(Qs[(mb + g + 8) * QP_ST + kk * 8 + tg + 4]);
    }
    __syncthreads();   // Qs now reusable as Ps

    float o[8][4];
    #pragma unroll
    for (int j = 0; j < 8; j++)
        #pragma unroll
        for (int r = 0; r < 4; r++) o[j][r] = 0.f;
    float m0_ = -1e30f, m1_ = -1e30f, l0_ = 0.f, l1_ = 0.f;

    for (int s0 = 0; s0 < S; s0 += 64) {
        // ---- cooperative K/V chunk load (zero-padded tail) ----
        #pragma unroll
        for (int it = 0; it < 4; it++) {
            int lin = t + it * 256;
            int r = lin >> 4;
            int d4 = (lin & 15) * 4;
            int sg = s0 + r;
            float4 kv = make_float4(0.f, 0.f, 0.f, 0.f), vv = kv;
            if (sg < S) {
                size_t off = ((size_t)(b * S + sg)) * DIM + h * DHEAD + d4;
                kv = *(const float4*)&K[off];
                vv = *(const float4*)&V[off];
            }
            float4 kc, vc;
            kc.x = tf32f(kv.x); kc.y = tf32f(kv.y); kc.z = tf32f(kv.z); kc.w = tf32f(kv.w);
            vc.x = tf32f(vv.x); vc.y = tf32f(vv.y); vc.z = tf32f(vv.z); vc.w = tf32f(vv.w);
            *(float4*)&Ks[r * K_ST + d4] = kc;
            *(float4*)&Vs[r * V_ST + d4] = vc;
        }
        __syncthreads();

        // ---- scores = Q @ K^T  (B-frag read directly from K[s][d]) ----
        float sc[8][4];
        #pragma unroll
        for (int j = 0; j < 8; j++) {
            sc[j][0] = sc[j][1] = sc[j][2] = sc[j][3] = 0.f;
            #pragma unroll
            for (int kk = 0; kk < 8; kk++) {
                unsigned b0 = __float_as_uint(Ks[(j * 8 + g) * K_ST + kk * 8 + tg    ]);
                unsigned b1 = __float_as_uint(Ks[(j * 8 + g) * K_ST + kk * 8 + tg + 4]);
                MMA_TF32(sc[j][0], sc[j][1], sc[j][2], sc[j][3],
                         aq[kk][0], aq[kk][1], aq[kk][2], aq[kk][3], b0, b1);
            }
        }

        // ---- scale + mask ----
        bool tail = (s0 + 64 > S);
        #pragma unroll
        for (int j = 0; j < 8; j++) {
            sc[j][0] *= scale; sc[j][1] *= scale;
            sc[j][2] *= scale; sc[j][3] *= scale;
            if (tail) {
                int col = s0 + j * 8 + 2 * tg;
                if (col     >= S) { sc[j][0] = -1e30f; sc[j][2] = -1e30f; }
                if (col + 1 >= S) { sc[j][1] = -1e30f; sc[j][3] = -1e30f; }
            }
        }

        // ---- online softmax (rows g, g+8) ----
        float rm0 = -1e30f, rm1 = -1e30f;
        #pragma unroll
        for (int j = 0; j < 8; j++) {
            rm0 = fmaxf(rm0, fmaxf(sc[j][0], sc[j][1]));
            rm1 = fmaxf(rm1, fmaxf(sc[j][2], sc[j][3]));
        }
        rm0 = fmaxf(rm0, __shfl_xor_sync(0xffffffffu, rm0, 1));
        rm0 = fmaxf(rm0, __shfl_xor_sync(0xffffffffu, rm0, 2));
        rm1 = fmaxf(rm1, __shfl_xor_sync(0xffffffffu, rm1, 1));
        rm1 = fmaxf(rm1, __shfl_xor_sync(0xffffffffu, rm1, 2));
        float nm0 = fmaxf(m0_, rm0), nm1 = fmaxf(m1_, rm1);
        float cc0 = __expf(m0_ - nm0), cc1 = __expf(m1_ - nm1);
        m0_ = nm0; m1_ = nm1;

        float rs0 = 0.f, rs1 = 0.f;
        #pragma unroll
        for (int j = 0; j < 8; j++) {
            float p0 = __expf(sc[j][0] - nm0);
            float p1 = __expf(sc[j][1] - nm0);
            float p2 = __expf(sc[j][2] - nm1);
            float p3 = __expf(sc[j][3] - nm1);
            rs0 += p0 + p1; rs1 += p2 + p3;
            float2 v01; v01.x = tf32f(p0); v01.y = tf32f(p1);
            float2 v23; v23.x = tf32f(p2); v23.y = tf32f(p3);
            *(float2*)&Qs[(mb + g    ) * QP_ST + j * 8 + 2 * tg] = v01;
            *(float2*)&Qs[(mb + g + 8) * QP_ST + j * 8 + 2 * tg] = v23;
        }
        rs0 += __shfl_xor_sync(0xffffffffu, rs0, 1);
        rs0 += __shfl_xor_sync(0xffffffffu, rs0, 2);
        rs1 += __shfl_xor_sync(0xffffffffu, rs1, 1);
        rs1 += __shfl_xor_sync(0xffffffffu, rs1, 2);
        l0_ = l0_ * cc0 + rs0;
        l1_ = l1_ * cc1 + rs1;

        #pragma unroll
        for (int j = 0; j < 8; j++) {
            o[j][0] *= cc0; o[j][1] *= cc0;
            o[j][2] *= cc1; o[j][3] *= cc1;
        }
        __syncwarp();   // P rows are warp-private; order STS->LDS across lanes

        // ---- O += P @ V  (B-frag read directly from V[s][d]) ----
        #pragma unroll
        for (int kk = 0; kk < 8; kk++) {
            unsigned ap[4];
            ap[0] = __float_as_uint(Qs[(mb + g    ) * QP_ST + kk * 8 + tg    ]);
            ap[1] = __float_as_uint(Qs[(mb + g + 8) * QP_ST + kk * 8 + tg    ]);
            ap[2] = __float_as_uint(Qs[(mb + g    ) * QP_ST + kk * 8 + tg + 4]);
            ap[3] = __float_as_uint(Qs[(mb + g + 8) * QP_ST + kk * 8 + tg + 4]);
            #pragma unroll
            for (int j = 0; j < 8; j++) {
                unsigned b0 = __float_as_uint(Vs[(kk * 8 + tg    ) * V_ST + j * 8 + g]);
                unsigned b1 = __float_as_uint(Vs[(kk * 8 + tg + 4) * V_ST + j * 8 + g]);
                MMA_TF32(o[j][0], o[j][1], o[j][2], o[j][3],
                         ap[0], ap[1], ap[2], ap[3], b0, b1);
            }
        }
        __syncthreads();   // before next chunk overwrites Ks/Vs
    }

    // ---- normalize + store ----
    float inv0 = 1.f / l0_, inv1 = 1.f / l1_;
    size_t r0 = ((size_t)(b * N + q0 + mb + g    )) * DIM + h * DHEAD;
    size_t r1 = ((size_t)(b * N + q0 + mb + g + 8)) * DIM + h * DHEAD;
    #pragma unroll
    for (int j = 0; j < 8; j++) {
        float2 v0; v0.x = o[j][0] * inv0; v0.y = o[j][1] * inv0;
        float2 v1; v1.x = o[j][2] * inv1; v1.y = o[j][3] * inv1;
        *(float2*)&O[r0 + j * 8 + 2 * tg] = v0;
        *(float2*)&O[r1 + j * 8 + 2 * tg] = v1;
    }
}

// ---------------- GEGLU: out[m,j] = h[m,j] * gelu(h[m,4096+j]) ----------------
__global__ __launch_bounds__(256) void geglu_kernel(
    const float* __restrict__ h, float* __restrict__ out)
{
    size_t i = (size_t)blockIdx.x * 256 + threadIdx.x;
    if (i >= (size_t)BTOK * FFIN) return;
    size_t m = i >> 12;        // / 4096
    size_t j = i & (FFIN - 1);
    float a = h[m * (2 * FFIN) + j];
    float g = h[m * (2 * FFIN) + FFIN + j];
    float gl = 0.5f * g * (1.f + erff(g * 0.70710678118654752f));
    out[i] = a * gl;
}

// ---------------- host orchestration ----------------
extern "C" void kernel_launch(void* const* d_in, const int* in_sizes, int n_in,
                              void* d_out, int out_size)
{
    (void)in_sizes; (void)n_in; (void)out_size;
    const float* x    = (const float*)d_in[0];
    const float* ctx  = (const float*)d_in[1];
    const float* Wq1  = (const float*)d_in[2];
    const float* Wk1  = (const float*)d_in[3];
    const float* Wv1  = (const float*)d_in[4];
    const float* Wo1  = (const float*)d_in[5];
    const float* bo1  = (const float*)d_in[6];
    const float* Wq2  = (const float*)d_in[7];
    const float* Wk2  = (const float*)d_in[8];
    const float* Wv2  = (const float*)d_in[9];
    const float* Wo2  = (const float*)d_in[10];
    const float* bo2  = (const float*)d_in[11];
    const float* Wp   = (const float*)d_in[12];
    const float* bp   = (const float*)d_in[13];
    const float* Wf   = (const float*)d_in[14];
    const float* bf   = (const float*)d_in[15];
    const float* g1   = (const float*)d_in[16];
    const float* b1   = (const float*)d_in[17];
    const float* g2   = (const float*)d_in[18];
    const float* b2   = (const float*)d_in[19];
    const float* g3   = (const float*)d_in[20];
    const float* b3   = (const float*)d_in[21];
    float* out = (float*)d_out;

    float *ln, *q, *k, *v, *att, *xb, *hb, *gl;
    cudaGetSymbolAddress((void**)&ln,  g_ln);
    cudaGetSymbolAddress((void**)&q,   g_q);
    cudaGetSymbolAddress((void**)&k,   g_k);
    cudaGetSymbolAddress((void**)&v,   g_v);
    cudaGetSymbolAddress((void**)&att, g_att);
    cudaGetSymbolAddress((void**)&xb,  g_x);
    cudaGetSymbolAddress((void**)&hb,  g_h);
    cudaGetSymbolAddress((void**)&gl,  g_gl);

    cudaFuncSetAttribute(attn_mma,
        cudaFuncAttributeMaxDynamicSharedMemorySize, ATTN_SMEM);

    const int B = 4, N = 2048, S = 77;
    const int M = B * N;           // 8192
    const int Mc = B * S;          // 308

    dim3 gemm1024(1024 / 128, M / 128);
    dim3 gemmCtx(1024 / 128, (Mc + 127) / 128);
    dim3 gemmWp(2 * FFIN / 128, M / 128);
    dim3 attnGrid(N / 128, HEADS, B);

    // ---- stage 1: self-attention ----
    ln_kernel<<<M, 256>>>(x, g1, b1, ln);
    tf32_gemm<<<gemm1024, 256>>>(ln, Wq1, nullptr, nullptr, q, M, 1024, 1024);
    tf32_gemm<<<gemm1024, 256>>>(ln, Wk1, nullptr, nullptr, k, M, 1024, 1024);
    tf32_gemm<<<gemm1024, 256>>>(ln, Wv1, nullptr, nullptr, v, M, 1024, 1024);
    attn_mma<<<attnGrid, 256, ATTN_SMEM>>>(q, k, v, att, N, N);
    tf32_gemm<<<gemm1024, 256>>>(att, Wo1, bo1, x, xb, M, 1024, 1024);

    // ---- stage 2: cross-attention ----
    ln_kernel<<<M, 256>>>(xb, g2, b2, ln);
    tf32_gemm<<<gemm1024, 256>>>(ln, Wq2, nullptr, nullptr, q, M, 1024, 1024);
    tf32_gemm<<<gemmCtx, 256>>>(ctx, Wk2, nullptr, nullptr, k, Mc, 1024, 768);
    tf32_gemm<<<gemmCtx, 256>>>(ctx, Wv2, nullptr, nullptr, v, Mc, 1024, 768);
    attn_mma<<<attnGrid, 256, ATTN_SMEM>>>(q, k, v, att, N, S);
    tf32_gemm<<<gemm1024, 256>>>(att, Wo2, bo2, xb, xb, M, 1024, 1024);

    // ---- stage 3: GEGLU feed-forward ----
    ln_kernel<<<M, 256>>>(xb, g3, b3, ln);
    tf32_gemm<<<gemmWp, 256>>>(ln, Wp, bp, nullptr, hb, M, 2 * FFIN, 1024);
    {
        size_t total = (size_t)M * FFIN;
        int blocks = (int)((total + 255) / 256);
        geglu_kernel<<<blocks, 256>>>(hb, gl);
    }
    tf32_gemm<<<gemm1024, 256>>>(gl, Wf, bf, xb, out, M, 1024, FFIN);
}

// round 9
// speedup vs baseline: 7.0895x; 2.2517x over previous
#include <cuda_runtime.h>
#include <cuda_fp16.h>
#include <math.h>
#include <stdint.h>

#define DIM   1024
#define HEADS 16
#define DHEAD 64
#define BTOK  8192
#define FFIN  4096

// ---------------- scratch ----------------
__device__ __half g_ln [BTOK * DIM];
__device__ __half g_q  [BTOK * DIM];
__device__ __half g_k  [BTOK * DIM];
__device__ __half g_v  [BTOK * DIM];
__device__ __half g_att[BTOK * DIM];
__device__ float  g_x  [BTOK * DIM];
__device__ __half g_h  [(size_t)BTOK * (2 * FFIN)];
__device__ __half g_gl [(size_t)BTOK * FFIN];
__device__ __half g_w1t[1024 * 1024];
__device__ __half g_w2t[1024 * 1024];
__device__ __half g_w3t[1024 * 1024];
__device__ __half g_w4t[1024 * 1024];
__device__ __half g_w5t[1024 * 768];
__device__ __half g_w6t[1024 * 768];
__device__ __half g_w7t[1024 * 1024];
__device__ __half g_wpt[(size_t)(2 * FFIN) * 1024];
__device__ __half g_wft[1024 * FFIN];
__device__ __half g_cc [308 * 768];

__device__ __forceinline__ uint32_t smem_u32(const void* p) {
    uint32_t a;
    asm("{ .reg .u64 t; cvta.to.shared.u64 t, %1; cvt.u32.u64 %0, t; }" : "=r"(a) : "l"(p));
    return a;
}
#define SWZ(o) ((o) ^ (((o) >> 3) & 0x70))
__device__ __forceinline__ void ldsm4(unsigned &r0, unsigned &r1, unsigned &r2,
                                      unsigned &r3, uint32_t a) {
    asm volatile("ldmatrix.sync.aligned.m8n8.x4.shared.b16 {%0,%1,%2,%3}, [%4];"
                 : "=r"(r0), "=r"(r1), "=r"(r2), "=r"(r3) : "r"(a));
}
__device__ __forceinline__ void ldsm4t(unsigned &r0, unsigned &r1, unsigned &r2,
                                       unsigned &r3, uint32_t a) {
    asm volatile("ldmatrix.sync.aligned.m8n8.x4.trans.shared.b16 {%0,%1,%2,%3}, [%4];"
                 : "=r"(r0), "=r"(r1), "=r"(r2), "=r"(r3) : "r"(a));
}
#define MMA_F16(c0,c1,c2,c3,a0,a1,a2,a3,b0,b1)                               \
    asm volatile(                                                            \
        "mma.sync.aligned.m16n8k16.row.col.f32.f16.f16.f32 "                 \
        "{%0,%1,%2,%3}, {%4,%5,%6,%7}, {%8,%9}, {%0,%1,%2,%3};"              \
        : "+f"(c0), "+f"(c1), "+f"(c2), "+f"(c3)                             \
        : "r"(a0), "r"(a1), "r"(a2), "r"(a3), "r"(b0), "r"(b1))
__device__ __forceinline__ void cpa16(uint32_t dst, const void* src, uint32_t sz) {
    asm volatile("cp.async.cg.shared.global [%0], [%1], 16, %2;"
                 :: "r"(dst), "l"(src), "r"(sz) : "memory");
}
#define CP_COMMIT() asm volatile("cp.async.commit_group;" ::: "memory")
#define CP_WAIT(n)  asm volatile("cp.async.wait_group %0;" :: "n"(n) : "memory")

// ---- weight transpose to half: Wt[N][K] = W[K][N] ----
__global__ __launch_bounds__(256) void transpose_cvt(
    const float* __restrict__ W, __half* __restrict__ Wt, int K, int N)
{
    __shared__ float tile[32][33];
    int tx = threadIdx.x, ty = threadIdx.y;
    int n = blockIdx.x * 32 + tx, k0 = blockIdx.y * 32;
    #pragma unroll
    for (int j = 0; j < 32; j += 8)
        tile[ty + j][tx] = W[(size_t)(k0 + ty + j) * N + n];
    __syncthreads();
    int k = k0 + tx, n0 = blockIdx.x * 32;
    #pragma unroll
    for (int j = 0; j < 32; j += 8)
        Wt[(size_t)(n0 + ty + j) * K + k] = __float2half(tile[tx][ty + j]);
}

__global__ __launch_bounds__(256) void cvt_kernel(
    const float* __restrict__ in, __half* __restrict__ out, int n)
{
    int i = blockIdx.x * 256 + threadIdx.x;
    if (i < n) out[i] = __float2half(in[i]);
}

// ---- LayerNorm: fp32 in, half out ----
__global__ __launch_bounds__(256) void ln_kernel(
    const float* __restrict__ x, const float* __restrict__ gamma,
    const float* __restrict__ beta, __half* __restrict__ out)
{
    int row = blockIdx.x, tid = threadIdx.x;
    float4 t = ((const float4*)(x + (size_t)row * DIM))[tid];
    float s = t.x + t.y + t.z + t.w;
    float q = t.x * t.x + t.y * t.y + t.z * t.z + t.w * t.w;
    #pragma unroll
    for (int o = 16; o; o >>= 1) {
        s += __shfl_xor_sync(0xffffffffu, s, o);
        q += __shfl_xor_sync(0xffffffffu, q, o);
    }
    __shared__ float ssum[8], ssq[8], smean, srstd;
    int wid = tid >> 5, lane = tid & 31;
    if (lane == 0) { ssum[wid] = s; ssq[wid] = q; }
    __syncthreads();
    if (tid == 0) {
        float S = 0.f, Q = 0.f;
        #pragma unroll
        for (int i = 0; i < 8; i++) { S += ssum[i]; Q += ssq[i]; }
        float mean = S * (1.f / DIM);
        smean = mean;
        srstd = rsqrtf(Q * (1.f / DIM) - mean * mean + 1e-5f);
    }
    __syncthreads();
    float mean = smean, rstd = srstd;
    float4 gg = ((const float4*)gamma)[tid];
    float4 bb = ((const float4*)beta)[tid];
    __half2* orow = (__half2*)(out + (size_t)row * DIM);
    orow[tid * 2 + 0] = __floats2half2_rn((t.x - mean) * rstd * gg.x + bb.x,
                                          (t.y - mean) * rstd * gg.y + bb.y);
    orow[tid * 2 + 1] = __floats2half2_rn((t.z - mean) * rstd * gg.z + bb.z,
                                          (t.w - mean) * rstd * gg.w + bb.w);
}

// ---- fp16 tensor GEMM: C[M,N] = A[M,K] @ Bt[N,K]^T (+bias)(+Res) ----
// A, Bt half row-major K-contiguous. OUTH: half out; else float out.
template<bool OUTH>
__global__ __launch_bounds__(256, 2) void hgemm(
    const __half* __restrict__ A, const __half* __restrict__ Bt,
    const float* __restrict__ bias, const float* __restrict__ Res,
    void* __restrict__ Cv, int M, int N, int K)
{
    __shared__ uint8_t As[2][8192];
    __shared__ uint8_t Bs[2][8192];
    const int t = threadIdx.x, warp = t >> 5, lane = t & 31;
    const int g = lane >> 2, tg = lane & 3;
    const int sub = lane >> 3, lr = lane & 7;
    const int m0 = blockIdx.y * 128, n0 = blockIdx.x * 128;
    const int wm = (warp & 1) * 64, wn = (warp >> 1) * 32;
    const uint32_t abase = smem_u32(As), bbase = smem_u32(Bs);

    uint32_t a_off[2], a_sz[2];
    const __half* a_src[2];
    const __half* b_src[2];
    #pragma unroll
    for (int i = 0; i < 2; i++) {
        int idx = t + i * 256;
        int row = idx >> 2, kq = idx & 3;
        uint32_t o = (uint32_t)(row * 64 + kq * 16);
        a_off[i] = SWZ(o);
        int ar = (m0 + row < M) ? (m0 + row) : 0;
        a_sz[i]  = (m0 + row < M) ? 16u : 0u;
        a_src[i] = A  + (size_t)ar * K + kq * 8;
        b_src[i] = Bt + (size_t)(n0 + row) * K + kq * 8;
    }

    float c[4][4][4];
    #pragma unroll
    for (int i = 0; i < 4; i++)
        #pragma unroll
        for (int j = 0; j < 4; j++)
            #pragma unroll
            for (int r = 0; r < 4; r++) c[i][j][r] = 0.f;

    const int S = K / 32;
    #pragma unroll
    for (int i = 0; i < 2; i++) {
        cpa16(abase + a_off[i], a_src[i], a_sz[i]);
        cpa16(bbase + a_off[i], b_src[i], 16u);
    }
    CP_COMMIT();

    for (int s = 0; s < S; s++) {
        const int buf = s & 1;
        if (s + 1 < S) {
            uint32_t so = (uint32_t)(((s + 1) & 1) * 8192);
            #pragma unroll
            for (int i = 0; i < 2; i++) {
                cpa16(abase + so + a_off[i], a_src[i] + (s + 1) * 32, a_sz[i]);
                cpa16(bbase + so + a_off[i], b_src[i] + (s + 1) * 32, 16u);
            }
            CP_COMMIT();
            CP_WAIT(1);
        } else {
            CP_WAIT(0);
        }
        __syncthreads();

        const uint32_t ab = abase + buf * 8192, bb = bbase + buf * 8192;
        #pragma unroll
        for (int kk = 0; kk < 2; kk++) {
            unsigned af[4][4], bf[4][2];
            #pragma unroll
            for (int i = 0; i < 4; i++) {
                uint32_t o = (uint32_t)((wm + i * 16 + (sub & 1) * 8 + lr) * 64
                                        + kk * 32 + (sub >> 1) * 16);
                ldsm4(af[i][0], af[i][1], af[i][2], af[i][3], ab + SWZ(o));
            }
            #pragma unroll
            for (int j2 = 0; j2 < 2; j2++) {
                uint32_t o = (uint32_t)((wn + j2 * 16 + (sub >> 1) * 8 + lr) * 64
                                        + kk * 32 + (sub & 1) * 16);
                unsigned r0, r1, r2, r3;
                ldsm4(r0, r1, r2, r3, bb + SWZ(o));
                bf[j2 * 2][0] = r0;     bf[j2 * 2][1] = r1;
                bf[j2 * 2 + 1][0] = r2; bf[j2 * 2 + 1][1] = r3;
            }
            #pragma unroll
            for (int i = 0; i < 4; i++)
                #pragma unroll
                for (int j = 0; j < 4; j++)
                    MMA_F16(c[i][j][0], c[i][j][1], c[i][j][2], c[i][j][3],
                            af[i][0], af[i][1], af[i][2], af[i][3],
                            bf[j][0], bf[j][1]);
        }
        __syncthreads();
    }

    #pragma unroll
    for (int i = 0; i < 4; i++) {
        #pragma unroll
        for (int j = 0; j < 4; j++) {
            int col = n0 + wn + j * 8 + 2 * tg;
            int r0m = m0 + wm + i * 16 + g, r1m = r0m + 8;
            float bx = 0.f, by = 0.f;
            if (bias) { bx = bias[col]; by = bias[col + 1]; }
            if (OUTH) {
                __half* C = (__half*)Cv;
                if (r0m < M)
                    *(__half2*)&C[(size_t)r0m * N + col] =
                        __floats2half2_rn(c[i][j][0] + bx, c[i][j][1] + by);
                if (r1m < M)
                    *(__half2*)&C[(size_t)r1m * N + col] =
                        __floats2half2_rn(c[i][j][2] + bx, c[i][j][3] + by);
            } else {
                float* C = (float*)Cv;
                if (r0m < M) {
                    size_t o0 = (size_t)r0m * N + col;
                    float2 v; v.x = c[i][j][0] + bx; v.y = c[i][j][1] + by;
                    if (Res) { float2 rr = *(const float2*)&Res[o0]; v.x += rr.x; v.y += rr.y; }
                    *(float2*)&C[o0] = v;
                }
                if (r1m < M) {
                    size_t o1 = (size_t)r1m * N + col;
                    float2 v; v.x = c[i][j][2] + bx; v.y = c[i][j][3] + by;
                    if (Res) { float2 rr = *(const float2*)&Res[o1]; v.x += rr.x; v.y += rr.y; }
                    *(float2*)&C[o1] = v;
                }
            }
        }
    }
}

// ---- fp16 flash attention: 128-query blocks, 64-key chunks, D=64 ----
__global__ __launch_bounds__(256) void attn_h(
    const __half* __restrict__ Q, const __half* __restrict__ K,
    const __half* __restrict__ V, __half* __restrict__ O, int N, int S)
{
    __shared__ uint8_t Qs[128 * 128];   // also P after prologue
    __shared__ uint8_t Ks[64 * 128];
    __shared__ uint8_t Vs[64 * 128];
    const int t = threadIdx.x, warp = t >> 5, lane = t & 31;
    const int g = lane >> 2, tg = lane & 3;
    const int sub = lane >> 3, lr = lane & 7;
    const int b = blockIdx.z, h = blockIdx.y;
    const int q0 = blockIdx.x * 128, mb = warp * 16;
    const float scale = 0.125f;
    const uint32_t qb = smem_u32(Qs), kb = smem_u32(Ks), vb = smem_u32(Vs);

    #pragma unroll
    for (int it = 0; it < 4; it++) {
        int lin = t + it * 256;
        int r = lin >> 3, cq = lin & 7;
        uint4 qv = *(const uint4*)&Q[((size_t)(b * N + q0 + r)) * DIM + h * DHEAD + cq * 8];
        uint32_t o = (uint32_t)(r * 128 + cq * 16);
        *(uint4*)(Qs + SWZ(o)) = qv;
    }
    __syncthreads();
    unsigned aq[4][4];
    #pragma unroll
    for (int kk = 0; kk < 4; kk++) {
        uint32_t o = (uint32_t)((mb + (sub & 1) * 8 + lr) * 128 + kk * 32 + (sub >> 1) * 16);
        ldsm4(aq[kk][0], aq[kk][1], aq[kk][2], aq[kk][3], qb + SWZ(o));
    }
    __syncthreads();

    float ov[8][4];
    #pragma unroll
    for (int j = 0; j < 8; j++) { ov[j][0] = ov[j][1] = ov[j][2] = ov[j][3] = 0.f; }
    float m0_ = -1e30f, m1_ = -1e30f, l0_ = 0.f, l1_ = 0.f;

    for (int s0 = 0; s0 < S; s0 += 64) {
        #pragma unroll
        for (int it = 0; it < 2; it++) {
            int lin = t + it * 256;
            int r = lin >> 3, cq = lin & 7;
            int sg = s0 + r;
            uint4 kv = make_uint4(0, 0, 0, 0), vv = kv;
            if (sg < S) {
                size_t off = ((size_t)(b * S + sg)) * DIM + h * DHEAD + cq * 8;
                kv = *(const uint4*)&K[off];
                vv = *(const uint4*)&V[off];
            }
            uint32_t o = (uint32_t)(r * 128 + cq * 16);
            *(uint4*)(Ks + SWZ(o)) = kv;
            *(uint4*)(Vs + SWZ(o)) = vv;
        }
        __syncthreads();

        float sc[8][4];
        #pragma unroll
        for (int j = 0; j < 8; j++) { sc[j][0] = sc[j][1] = sc[j][2] = sc[j][3] = 0.f; }
        #pragma unroll
        for (int kk = 0; kk < 4; kk++) {
            #pragma unroll
            for (int j2 = 0; j2 < 4; j2++) {
                uint32_t o = (uint32_t)(((2 * j2 + (sub >> 1)) * 8 + lr) * 128
                                        + kk * 32 + (sub & 1) * 16);
                unsigned r0, r1, r2, r3;
                ldsm4(r0, r1, r2, r3, kb + SWZ(o));
                MMA_F16(sc[2 * j2][0], sc[2 * j2][1], sc[2 * j2][2], sc[2 * j2][3],
                        aq[kk][0], aq[kk][1], aq[kk][2], aq[kk][3], r0, r1);
                MMA_F16(sc[2 * j2 + 1][0], sc[2 * j2 + 1][1], sc[2 * j2 + 1][2], sc[2 * j2 + 1][3],
                        aq[kk][0], aq[kk][1], aq[kk][2], aq[kk][3], r2, r3);
            }
        }

        bool tail = (s0 + 64 > S);
        #pragma unroll
        for (int j = 0; j < 8; j++) {
            sc[j][0] *= scale; sc[j][1] *= scale; sc[j][2] *= scale; sc[j][3] *= scale;
            if (tail) {
                int col = s0 + j * 8 + 2 * tg;
                if (col     >= S) { sc[j][0] = -1e30f; sc[j][2] = -1e30f; }
                if (col + 1 >= S) { sc[j][1] = -1e30f; sc[j][3] = -1e30f; }
            }
        }
        float rm0 = -1e30f, rm1 = -1e30f;
        #pragma unroll
        for (int j = 0; j < 8; j++) {
            rm0 = fmaxf(rm0, fmaxf(sc[j][0], sc[j][1]));
            rm1 = fmaxf(rm1, fmaxf(sc[j][2], sc[j][3]));
        }
        rm0 = fmaxf(rm0, __shfl_xor_sync(0xffffffffu, rm0, 1));
        rm0 = fmaxf(rm0, __shfl_xor_sync(0xffffffffu, rm0, 2));
        rm1 = fmaxf(rm1, __shfl_xor_sync(0xffffffffu, rm1, 1));
        rm1 = fmaxf(rm1, __shfl_xor_sync(0xffffffffu, rm1, 2));
        float nm0 = fmaxf(m0_, rm0), nm1 = fmaxf(m1_, rm1);
        float cc0 = __expf(m0_ - nm0), cc1 = __expf(m1_ - nm1);
        m0_ = nm0; m1_ = nm1;
        float rs0 = 0.f, rs1 = 0.f;
        #pragma unroll
        for (int j = 0; j < 8; j++) {
            float p0 = __expf(sc[j][0] - nm0), p1 = __expf(sc[j][1] - nm0);
            float p2 = __expf(sc[j][2] - nm1), p3 = __expf(sc[j][3] - nm1);
            rs0 += p0 + p1; rs1 += p2 + p3;
            uint32_t o0 = (uint32_t)((mb + g) * 128 + j * 16 + 4 * tg);
            uint32_t o1 = (uint32_t)((mb + g + 8) * 128 + j * 16 + 4 * tg);
            *(__half2*)(Qs + SWZ(o0)) = __floats2half2_rn(p0, p1);
            *(__half2*)(Qs + SWZ(o1)) = __floats2half2_rn(p2, p3);
        }
        rs0 += __shfl_xor_sync(0xffffffffu, rs0, 1);
        rs0 += __shfl_xor_sync(0xffffffffu, rs0, 2);
        rs1 += __shfl_xor_sync(0xffffffffu, rs1, 1);
        rs1 += __shfl_xor_sync(0xffffffffu, rs1, 2);
        l0_ = l0_ * cc0 + rs0;
        l1_ = l1_ * cc1 + rs1;
        #pragma unroll
        for (int j = 0; j < 8; j++) {
            ov[j][0] *= cc0; ov[j][1] *= cc0; ov[j][2] *= cc1; ov[j][3] *= cc1;
        }
        __syncwarp();

        #pragma unroll
        for (int kk = 0; kk < 4; kk++) {
            unsigned ap[4];
            uint32_t o = (uint32_t)((mb + (sub & 1) * 8 + lr) * 128 + kk * 32 + (sub >> 1) * 16);
            ldsm4(ap[0], ap[1], ap[2], ap[3], qb + SWZ(o));
            #pragma unroll
            for (int j2 = 0; j2 < 4; j2++) {
                uint32_t o2 = (uint32_t)((kk * 16 + (sub & 1) * 8 + lr) * 128
                                         + (2 * j2 + (sub >> 1)) * 16);
                unsigned r0, r1, r2, r3;
                ldsm4t(r0, r1, r2, r3, vb + SWZ(o2));
                MMA_F16(ov[2 * j2][0], ov[2 * j2][1], ov[2 * j2][2], ov[2 * j2][3],
                        ap[0], ap[1], ap[2], ap[3], r0, r1);
                MMA_F16(ov[2 * j2 + 1][0], ov[2 * j2 + 1][1], ov[2 * j2 + 1][2], ov[2 * j2 + 1][3],
                        ap[0], ap[1], ap[2], ap[3], r2, r3);
            }
        }
        __syncthreads();
    }

    float inv0 = 1.f / l0_, inv1 = 1.f / l1_;
    size_t r0 = ((size_t)(b * N + q0 + mb + g)) * DIM + h * DHEAD;
    size_t r1 = ((size_t)(b * N + q0 + mb + g + 8)) * DIM + h * DHEAD;
    #pragma unroll
    for (int j = 0; j < 8; j++) {
        *(__half2*)&O[r0 + j * 8 + 2 * tg] = __floats2half2_rn(ov[j][0] * inv0, ov[j][1] * inv0);
        *(__half2*)&O[r1 + j * 8 + 2 * tg] = __floats2half2_rn(ov[j][2] * inv1, ov[j][3] * inv1);
    }
}

// ---- GEGLU: half in/out ----
__global__ __launch_bounds__(256) void geglu_kernel(
    const __half* __restrict__ h, __half* __restrict__ out)
{
    int idx = blockIdx.x * 256 + threadIdx.x;   // half2 index, total 16.7M
    if (idx >= BTOK * (FFIN / 2)) return;
    int m = idx >> 11, j2 = idx & 2047;
    const __half2* hr = (const __half2*)(h + (size_t)m * 2 * FFIN);
    float2 a = __half22float2(hr[j2]);
    float2 gt = __half22float2(hr[2048 + j2]);
    float g0 = 0.5f * gt.x * (1.f + erff(gt.x * 0.70710678118654752f));
    float g1 = 0.5f * gt.y * (1.f + erff(gt.y * 0.70710678118654752f));
    ((__half2*)(out + (size_t)m * FFIN))[j2] = __floats2half2_rn(a.x * g0, a.y * g1);
}

extern "C" void kernel_launch(void* const* d_in, const int* in_sizes, int n_in,
                              void* d_out, int out_size)
{
    (void)in_sizes; (void)n_in; (void)out_size;
    const float* x   = (const float*)d_in[0];
    const float* ctx = (const float*)d_in[1];
    const float* Wq1 = (const float*)d_in[2];
    const float* Wk1 = (const float*)d_in[3];
    const float* Wv1 = (const float*)d_in[4];
    const float* Wo1 = (const float*)d_in[5];
    const float* bo1 = (const float*)d_in[6];
    const float* Wq2 = (const float*)d_in[7];
    const float* Wk2 = (const float*)d_in[8];
    const float* Wv2 = (const float*)d_in[9];
    const float* Wo2 = (const float*)d_in[10];
    const float* bo2 = (const float*)d_in[11];
    const float* Wp  = (const float*)d_in[12];
    const float* bp  = (const float*)d_in[13];
    const float* Wf  = (const float*)d_in[14];
    const float* bf  = (const float*)d_in[15];
    const float* g1 = (const float*)d_in[16]; const float* b1 = (const float*)d_in[17];
    const float* g2 = (const float*)d_in[18]; const float* b2 = (const float*)d_in[19];
    const float* g3 = (const float*)d_in[20]; const float* b3 = (const float*)d_in[21];
    float* out = (float*)d_out;

    __half *ln, *q, *k, *v, *att, *hb, *gl, *cc;
    __half *w1, *w2, *w3, *w4, *w5, *w6, *w7, *wp, *wf;
    float* xb;
    cudaGetSymbolAddress((void**)&ln,  g_ln);
    cudaGetSymbolAddress((void**)&q,   g_q);
    cudaGetSymbolAddress((void**)&k,   g_k);
    cudaGetSymbolAddress((void**)&v,   g_v);
    cudaGetSymbolAddress((void**)&att, g_att);
    cudaGetSymbolAddress((void**)&xb,  g_x);
    cudaGetSymbolAddress((void**)&hb,  g_h);
    cudaGetSymbolAddress((void**)&gl,  g_gl);
    cudaGetSymbolAddress((void**)&cc,  g_cc);
    cudaGetSymbolAddress((void**)&w1,  g_w1t);
    cudaGetSymbolAddress((void**)&w2,  g_w2t);
    cudaGetSymbolAddress((void**)&w3,  g_w3t);
    cudaGetSymbolAddress((void**)&w4,  g_w4t);
    cudaGetSymbolAddress((void**)&w5,  g_w5t);
    cudaGetSymbolAddress((void**)&w6,  g_w6t);
    cudaGetSymbolAddress((void**)&w7,  g_w7t);
    cudaGetSymbolAddress((void**)&wp,  g_wpt);
    cudaGetSymbolAddress((void**)&wf,  g_wft);

    const int B = 4, N = 2048, S = 77;
    const int M = B * N, Mc = B * S;
    dim3 tb(32, 8);
    dim3 gemm1024(1024 / 128, M / 128);
    dim3 gemmCtx(1024 / 128, (Mc + 127) / 128);
    dim3 gemmWp(2 * FFIN / 128, M / 128);
    dim3 aGrid(N / 128, HEADS, B);

    // weight prep (Wo2 reuses w1 after the Wq1 GEMM consumed it)
    transpose_cvt<<<dim3(32, 32), tb>>>(Wq1, w1, 1024, 1024);
    transpose_cvt<<<dim3(32, 32), tb>>>(Wk1, w2, 1024, 1024);
    transpose_cvt<<<dim3(32, 32), tb>>>(Wv1, w3, 1024, 1024);
    transpose_cvt<<<dim3(32, 32), tb>>>(Wo1, w4, 1024, 1024);
    transpose_cvt<<<dim3(32, 32), tb>>>(Wq2, w7, 1024, 1024);
    transpose_cvt<<<dim3(32, 24), tb>>>(Wk2, w5, 768, 1024);
    transpose_cvt<<<dim3(32, 24), tb>>>(Wv2, w6, 768, 1024);
    transpose_cvt<<<dim3(256, 32), tb>>>(Wp, wp, 1024, 2 * FFIN);
    transpose_cvt<<<dim3(32, 128), tb>>>(Wf, wf, 4096, 1024);
    cvt_kernel<<<(Mc * 768 + 255) / 256, 256>>>(ctx, cc, Mc * 768);

    // stage 1: self-attention
    ln_kernel<<<M, 256>>>(x, g1, b1, ln);
    hgemm<true><<<gemm1024, 256>>>(ln, w1, nullptr, nullptr, q, M, 1024, 1024);
    hgemm<true><<<gemm1024, 256>>>(ln, w2, nullptr, nullptr, k, M, 1024, 1024);
    hgemm<true><<<gemm1024, 256>>>(ln, w3, nullptr, nullptr, v, M, 1024, 1024);
    transpose_cvt<<<dim3(32, 32), tb>>>(Wo2, w1, 1024, 1024);
    attn_h<<<aGrid, 256>>>(q, k, v, att, N, N);
    hgemm<false><<<gemm1024, 256>>>(att, w4, bo1, x, xb, M, 1024, 1024);

    // stage 2: cross-attention
    ln_kernel<<<M, 256>>>(xb, g2, b2, ln);
    hgemm<true><<<gemm1024, 256>>>(ln, w7, nullptr, nullptr, q, M, 1024, 1024);
    hgemm<true><<<gemmCtx, 256>>>(cc, w5, nullptr, nullptr, k, Mc, 1024, 768);
    hgemm<true><<<gemmCtx, 256>>>(cc, w6, nullptr, nullptr, v, Mc, 1024, 768);
    attn_h<<<aGrid, 256>>>(q, k, v, att, N, S);
    hgemm<false><<<gemm1024, 256>>>(att, w1, bo2, xb, xb, M, 1024, 1024);

    // stage 3: GEGLU FF
    ln_kernel<<<M, 256>>>(xb, g3, b3, ln);
    hgemm<true><<<gemmWp, 256>>>(ln, wp, bp, nullptr, hb, M, 2 * FFIN, 1024);
    geglu_kernel<<<BTOK * (FFIN / 2) / 256, 256>>>(hb, gl);
    hgemm<false><<<gemm1024, 256>>>(gl, wf, bf, xb, out, M, 1024, FFIN);
}

// round 11
// speedup vs baseline: 8.4355x; 1.1899x over previous
#include <cuda_runtime.h>
#include <cuda_fp16.h>
#include <math.h>
#include <stdint.h>

#define DIM   1024
#define HEADS 16
#define DHEAD 64
#define BTOK  8192
#define FFIN  4096

// ---------------- scratch ----------------
__device__ __half g_ln [BTOK * DIM];
__device__ __half g_q  [BTOK * DIM];
__device__ __half g_k  [BTOK * DIM];
__device__ __half g_v  [BTOK * DIM];
__device__ __half g_att[BTOK * DIM];
__device__ float  g_x  [BTOK * DIM];
__device__ __half g_h  [(size_t)BTOK * (2 * FFIN)];
__device__ __half g_gl [(size_t)BTOK * FFIN];
__device__ __half g_w1t[1024 * 1024];
__device__ __half g_w2t[1024 * 1024];
__device__ __half g_w3t[1024 * 1024];
__device__ __half g_w4t[1024 * 1024];
__device__ __half g_w5t[1024 * 768];
__device__ __half g_w6t[1024 * 768];
__device__ __half g_w7t[1024 * 1024];
__device__ __half g_wpt[(size_t)(2 * FFIN) * 1024];
__device__ __half g_wft[1024 * FFIN];
__device__ __half g_cc [308 * 768];

__device__ __forceinline__ uint32_t smem_u32(const void* p) {
    uint32_t a;
    asm("{ .reg .u64 t; cvta.to.shared.u64 t, %1; cvt.u32.u64 %0, t; }" : "=r"(a) : "l"(p));
    return a;
}
#define SWZ(o) ((o) ^ (((o) >> 3) & 0x70))
__device__ __forceinline__ void ldsm4(unsigned &r0, unsigned &r1, unsigned &r2,
                                      unsigned &r3, uint32_t a) {
    asm volatile("ldmatrix.sync.aligned.m8n8.x4.shared.b16 {%0,%1,%2,%3}, [%4];"
                 : "=r"(r0), "=r"(r1), "=r"(r2), "=r"(r3) : "r"(a));
}
__device__ __forceinline__ void ldsm4t(unsigned &r0, unsigned &r1, unsigned &r2,
                                       unsigned &r3, uint32_t a) {
    asm volatile("ldmatrix.sync.aligned.m8n8.x4.trans.shared.b16 {%0,%1,%2,%3}, [%4];"
                 : "=r"(r0), "=r"(r1), "=r"(r2), "=r"(r3) : "r"(a));
}
#define MMA_F16(c0,c1,c2,c3,a0,a1,a2,a3,b0,b1)                               \
    asm volatile(                                                            \
        "mma.sync.aligned.m16n8k16.row.col.f32.f16.f16.f32 "                 \
        "{%0,%1,%2,%3}, {%4,%5,%6,%7}, {%8,%9}, {%0,%1,%2,%3};"              \
        : "+f"(c0), "+f"(c1), "+f"(c2), "+f"(c3)                             \
        : "r"(a0), "r"(a1), "r"(a2), "r"(a3), "r"(b0), "r"(b1))
__device__ __forceinline__ void cpa16(uint32_t dst, const void* src, uint32_t sz) {
    asm volatile("cp.async.cg.shared.global [%0], [%1], 16, %2;"
                 :: "r"(dst), "l"(src), "r"(sz) : "memory");
}
#define CP_COMMIT() asm volatile("cp.async.commit_group;" ::: "memory")
#define CP_WAIT(n)  asm volatile("cp.async.wait_group %0;" :: "n"(n) : "memory")

// ---- weight transpose to half: Wt[N][K] = W[K][N] ----
__global__ __launch_bounds__(256) void transpose_cvt(
    const float* __restrict__ W, __half* __restrict__ Wt, int K, int N)
{
    __shared__ float tile[32][33];
    int tx = threadIdx.x, ty = threadIdx.y;
    int n = blockIdx.x * 32 + tx, k0 = blockIdx.y * 32;
    #pragma unroll
    for (int j = 0; j < 32; j += 8)
        tile[ty + j][tx] = W[(size_t)(k0 + ty + j) * N + n];
    __syncthreads();
    int k = k0 + tx, n0 = blockIdx.x * 32;
    #pragma unroll
    for (int j = 0; j < 32; j += 8)
        Wt[(size_t)(n0 + ty + j) * K + k] = __float2half(tile[tx][ty + j]);
}

__global__ __launch_bounds__(256) void cvt_kernel(
    const float* __restrict__ in, __half* __restrict__ out, int n)
{
    int i = blockIdx.x * 256 + threadIdx.x;
    if (i < n) out[i] = __float2half(in[i]);
}

// ---- LayerNorm: fp32 in, half out ----
__global__ __launch_bounds__(256) void ln_kernel(
    const float* __restrict__ x, const float* __restrict__ gamma,
    const float* __restrict__ beta, __half* __restrict__ out)
{
    int row = blockIdx.x, tid = threadIdx.x;
    float4 t = ((const float4*)(x + (size_t)row * DIM))[tid];
    float s = t.x + t.y + t.z + t.w;
    float q = t.x * t.x + t.y * t.y + t.z * t.z + t.w * t.w;
    #pragma unroll
    for (int o = 16; o; o >>= 1) {
        s += __shfl_xor_sync(0xffffffffu, s, o);
        q += __shfl_xor_sync(0xffffffffu, q, o);
    }
    __shared__ float ssum[8], ssq[8], smean, srstd;
    int wid = tid >> 5, lane = tid & 31;
    if (lane == 0) { ssum[wid] = s; ssq[wid] = q; }
    __syncthreads();
    if (tid == 0) {
        float S = 0.f, Q = 0.f;
        #pragma unroll
        for (int i = 0; i < 8; i++) { S += ssum[i]; Q += ssq[i]; }
        float mean = S * (1.f / DIM);
        smean = mean;
        srstd = rsqrtf(Q * (1.f / DIM) - mean * mean + 1e-5f);
    }
    __syncthreads();
    float mean = smean, rstd = srstd;
    float4 gg = ((const float4*)gamma)[tid];
    float4 bb = ((const float4*)beta)[tid];
    __half2* orow = (__half2*)(out + (size_t)row * DIM);
    orow[tid * 2 + 0] = __floats2half2_rn((t.x - mean) * rstd * gg.x + bb.x,
                                          (t.y - mean) * rstd * gg.y + bb.y);
    orow[tid * 2 + 1] = __floats2half2_rn((t.z - mean) * rstd * gg.z + bb.z,
                                          (t.w - mean) * rstd * gg.w + bb.w);
}

// ---- fp16 GEMM v2: 128x128 tile, K-stage 64, 3-stage cp.async, 1 sync/stage ----
#define HG_STAGE 32768              // 16KB A + 16KB B
#define HG_SMEM  (3 * HG_STAGE)     // 96KB

template<bool OUTH>
__global__ __launch_bounds__(256, 2) void hgemm(
    const __half* __restrict__ A, const __half* __restrict__ Bt,
    const float* __restrict__ bias, const float* __restrict__ Res,
    void* __restrict__ Cv, int M, int N, int K)
{
    extern __shared__ uint8_t sm[];
    const uint32_t sbase = smem_u32(sm);
    const int t = threadIdx.x, warp = t >> 5, lane = t & 31;
    const int g = lane >> 2, tg = lane & 3;
    const int sub = lane >> 3, lr = lane & 7;
    const int m0 = blockIdx.y * 128, n0 = blockIdx.x * 128;
    const int wm = (warp & 1) * 64, wn = (warp >> 1) * 32;

    // copy slots: rows of 128B (64 halves), 8 quads/row; A 4/thread, B 4/thread
    uint32_t qoff[4], a_sz[4];
    const __half* a_src[4];
    const __half* b_src[4];
    #pragma unroll
    for (int i = 0; i < 4; i++) {
        int idx = t + i * 256;
        int row = idx >> 3, kq = idx & 7;
        qoff[i] = SWZ((uint32_t)(row * 128 + kq * 16));
        int ar = (m0 + row < M) ? (m0 + row) : 0;
        a_sz[i]  = (m0 + row < M) ? 16u : 0u;
        a_src[i] = A  + (size_t)ar * K + kq * 8;
        b_src[i] = Bt + (size_t)(n0 + row) * K + kq * 8;
    }

    float c[4][4][4];
    #pragma unroll
    for (int i = 0; i < 4; i++)
        #pragma unroll
        for (int j = 0; j < 4; j++)
            #pragma unroll
            for (int r = 0; r < 4; r++) c[i][j][r] = 0.f;

    const int S = K / 64;
    #pragma unroll
    for (int st = 0; st < 2; st++) {
        uint32_t sb = sbase + st * HG_STAGE;
        #pragma unroll
        for (int i = 0; i < 4; i++) {
            cpa16(sb + qoff[i],         a_src[i] + st * 64, a_sz[i]);
            cpa16(sb + 16384 + qoff[i], b_src[i] + st * 64, 16u);
        }
        CP_COMMIT();
    }

    int buf = 0;
    for (int s = 0; s < S; s++) {
        if (s == S - 1) { CP_WAIT(0); } else { CP_WAIT(1); }
        __syncthreads();
        if (s + 2 < S) {
            int nb = buf + 2; if (nb >= 3) nb -= 3;
            uint32_t sb = sbase + nb * HG_STAGE;
            #pragma unroll
            for (int i = 0; i < 4; i++) {
                cpa16(sb + qoff[i],         a_src[i] + (s + 2) * 64, a_sz[i]);
                cpa16(sb + 16384 + qoff[i], b_src[i] + (s + 2) * 64, 16u);
            }
            CP_COMMIT();
        }

        const uint32_t ab = sbase + buf * HG_STAGE, bb = ab + 16384;
        #pragma unroll
        for (int kk = 0; kk < 4; kk++) {
            unsigned af[4][4], bf[4][2];
            #pragma unroll
            for (int i = 0; i < 4; i++) {
                uint32_t o = (uint32_t)((wm + i * 16 + (sub & 1) * 8 + lr) * 128
                                        + kk * 32 + (sub >> 1) * 16);
                ldsm4(af[i][0], af[i][1], af[i][2], af[i][3], ab + SWZ(o));
            }
            #pragma unroll
            for (int j2 = 0; j2 < 2; j2++) {
                uint32_t o = (uint32_t)((wn + j2 * 16 + (sub >> 1) * 8 + lr) * 128
                                        + kk * 32 + (sub & 1) * 16);
                unsigned r0, r1, r2, r3;
                ldsm4(r0, r1, r2, r3, bb + SWZ(o));
                bf[j2 * 2][0] = r0;     bf[j2 * 2][1] = r1;
                bf[j2 * 2 + 1][0] = r2; bf[j2 * 2 + 1][1] = r3;
            }
            #pragma unroll
            for (int i = 0; i < 4; i++)
                #pragma unroll
                for (int j = 0; j < 4; j++)
                    MMA_F16(c[i][j][0], c[i][j][1], c[i][j][2], c[i][j][3],
                            af[i][0], af[i][1], af[i][2], af[i][3],
                            bf[j][0], bf[j][1]);
        }
        if (++buf >= 3) buf = 0;
    }

    #pragma unroll
    for (int i = 0; i < 4; i++) {
        #pragma unroll
        for (int j = 0; j < 4; j++) {
            int col = n0 + wn + j * 8 + 2 * tg;
            int r0m = m0 + wm + i * 16 + g, r1m = r0m + 8;
            float bx = 0.f, by = 0.f;
            if (bias) { bx = bias[col]; by = bias[col + 1]; }
            if (OUTH) {
                __half* C = (__half*)Cv;
                if (r0m < M)
                    *(__half2*)&C[(size_t)r0m * N + col] =
                        __floats2half2_rn(c[i][j][0] + bx, c[i][j][1] + by);
                if (r1m < M)
                    *(__half2*)&C[(size_t)r1m * N + col] =
                        __floats2half2_rn(c[i][j][2] + bx, c[i][j][3] + by);
            } else {
                float* C = (float*)Cv;
                if (r0m < M) {
                    size_t o0 = (size_t)r0m * N + col;
                    float2 v; v.x = c[i][j][0] + bx; v.y = c[i][j][1] + by;
                    if (Res) { float2 rr = *(const float2*)&Res[o0]; v.x += rr.x; v.y += rr.y; }
                    *(float2*)&C[o0] = v;
                }
                if (r1m < M) {
                    size_t o1 = (size_t)r1m * N + col;
                    float2 v; v.x = c[i][j][2] + bx; v.y = c[i][j][3] + by;
                    if (Res) { float2 rr = *(const float2*)&Res[o1]; v.x += rr.x; v.y += rr.y; }
                    *(float2*)&C[o1] = v;
                }
            }
        }
    }
}

// ---- fp16 flash attention v2: cp.async double-buffered K/V, 1 sync/chunk ----
__global__ __launch_bounds__(256) void attn_h(
    const __half* __restrict__ Q, const __half* __restrict__ K,
    const __half* __restrict__ V, __half* __restrict__ O, int N, int S)
{
    __shared__ uint8_t Qs[128 * 128];       // also P after prologue
    __shared__ uint8_t Ks[2][64 * 128];
    __shared__ uint8_t Vs[2][64 * 128];
    const int t = threadIdx.x, warp = t >> 5, lane = t & 31;
    const int g = lane >> 2, tg = lane & 3;
    const int sub = lane >> 3, lr = lane & 7;
    const int b = blockIdx.z, h = blockIdx.y;
    const int q0 = blockIdx.x * 128, mb = warp * 16;
    const float scale = 0.125f;
    const uint32_t qb = smem_u32(Qs), kb = smem_u32(Ks), vb = smem_u32(Vs);

    // copy slots (shared by Q prologue and K/V chunks)
    int crow[2], ckq[2];
    uint32_t koff[2];
    #pragma unroll
    for (int i = 0; i < 2; i++) {
        int lin = t + i * 256;
        crow[i] = lin >> 3; ckq[i] = lin & 7;
        koff[i] = SWZ((uint32_t)(crow[i] * 128 + ckq[i] * 16));
    }

    // Q tile via cp.async (4 quads/thread)
    #pragma unroll
    for (int it = 0; it < 4; it++) {
        int lin = t + it * 256;
        int r = lin >> 3, cq = lin & 7;
        cpa16(qb + SWZ((uint32_t)(r * 128 + cq * 16)),
              &Q[((size_t)(b * N + q0 + r)) * DIM + h * DHEAD + cq * 8], 16u);
    }
    // K/V chunk 0
    #pragma unroll
    for (int i = 0; i < 2; i++) {
        int sg = crow[i];
        uint32_t sz = (sg < S) ? 16u : 0u;
        size_t off = ((size_t)(b * S + (sg < S ? sg : 0))) * DIM + h * DHEAD + ckq[i] * 8;
        cpa16(kb + koff[i], &K[off], sz);
        cpa16(vb + koff[i], &V[off], sz);
    }
    CP_COMMIT();
    CP_WAIT(0);
    __syncthreads();

    unsigned aq[4][4];
    #pragma unroll
    for (int kk = 0; kk < 4; kk++) {
        uint32_t o = (uint32_t)((mb + (sub & 1) * 8 + lr) * 128 + kk * 32 + (sub >> 1) * 16);
        ldsm4(aq[kk][0], aq[kk][1], aq[kk][2], aq[kk][3], qb + SWZ(o));
    }
    __syncthreads();

    float ov[8][4];
    #pragma unroll
    for (int j = 0; j < 8; j++) { ov[j][0] = ov[j][1] = ov[j][2] = ov[j][3] = 0.f; }
    float m0_ = -1e30f, m1_ = -1e30f, l0_ = 0.f, l1_ = 0.f;

    const int nch = (S + 63) / 64;
    for (int ci = 0; ci < nch; ci++) {
        int bufc = ci & 1;
        if (ci + 1 < nch) {          // prefetch next chunk into other buffer
            int nb = bufc ^ 1;
            #pragma unroll
            for (int i = 0; i < 2; i++) {
                int sg = (ci + 1) * 64 + crow[i];
                uint32_t sz = (sg < S) ? 16u : 0u;
                size_t off = ((size_t)(b * S + (sg < S ? sg : 0))) * DIM + h * DHEAD + ckq[i] * 8;
                cpa16(kb + nb * 8192 + koff[i], &K[off], sz);
                cpa16(vb + nb * 8192 + koff[i], &V[off], sz);
            }
            CP_COMMIT();
        }
        const uint32_t kcb = kb + bufc * 8192, vcb = vb + bufc * 8192;
        const int s0 = ci * 64;

        float sc[8][4];
        #pragma unroll
        for (int j = 0; j < 8; j++) { sc[j][0] = sc[j][1] = sc[j][2] = sc[j][3] = 0.f; }
        #pragma unroll
        for (int kk = 0; kk < 4; kk++) {
            #pragma unroll
            for (int j2 = 0; j2 < 4; j2++) {
                uint32_t o = (uint32_t)(((2 * j2 + (sub >> 1)) * 8 + lr) * 128
                                        + kk * 32 + (sub & 1) * 16);
                unsigned r0, r1, r2, r3;
                ldsm4(r0, r1, r2, r3, kcb + SWZ(o));
                MMA_F16(sc[2 * j2][0], sc[2 * j2][1], sc[2 * j2][2], sc[2 * j2][3],
                        aq[kk][0], aq[kk][1], aq[kk][2], aq[kk][3], r0, r1);
                MMA_F16(sc[2 * j2 + 1][0], sc[2 * j2 + 1][1], sc[2 * j2 + 1][2], sc[2 * j2 + 1][3],
                        aq[kk][0], aq[kk][1], aq[kk][2], aq[kk][3], r2, r3);
            }
        }

        bool tail = (s0 + 64 > S);
        #pragma unroll
        for (int j = 0; j < 8; j++) {
            sc[j][0] *= scale; sc[j][1] *= scale; sc[j][2] *= scale; sc[j][3] *= scale;
            if (tail) {
                int col = s0 + j * 8 + 2 * tg;
                if (col     >= S) { sc[j][0] = -1e30f; sc[j][2] = -1e30f; }
                if (col + 1 >= S) { sc[j][1] = -1e30f; sc[j][3] = -1e30f; }
            }
        }
        float rm0 = -1e30f, rm1 = -1e30f;
        #pragma unroll
        for (int j = 0; j < 8; j++) {
            rm0 = fmaxf(rm0, fmaxf(sc[j][0], sc[j][1]));
            rm1 = fmaxf(rm1, fmaxf(sc[j][2], sc[j][3]));
        }
        rm0 = fmaxf(rm0, __shfl_xor_sync(0xffffffffu, rm0, 1));
        rm0 = fmaxf(rm0, __shfl_xor_sync(0xffffffffu, rm0, 2));
        rm1 = fmaxf(rm1, __shfl_xor_sync(0xffffffffu, rm1, 1));
        rm1 = fmaxf(rm1, __shfl_xor_sync(0xffffffffu, rm1, 2));
        float nm0 = fmaxf(m0_, rm0), nm1 = fmaxf(m1_, rm1);
        float cc0 = __expf(m0_ - nm0), cc1 = __expf(m1_ - nm1);
        m0_ = nm0; m1_ = nm1;
        float rs0 = 0.f, rs1 = 0.f;
        #pragma unroll
        for (int j = 0; j < 8; j++) {
            float p0 = __expf(sc[j][0] - nm0), p1 = __expf(sc[j][1] - nm0);
            float p2 = __expf(sc[j][2] - nm1), p3 = __expf(sc[j][3] - nm1);
            rs0 += p0 + p1; rs1 += p2 + p3;
            uint32_t o0 = (uint32_t)((mb + g) * 128 + j * 16 + 4 * tg);
            uint32_t o1 = (uint32_t)((mb + g + 8) * 128 + j * 16 + 4 * tg);
            *(__half2*)(Qs + SWZ(o0)) = __floats2half2_rn(p0, p1);
            *(__half2*)(Qs + SWZ(o1)) = __floats2half2_rn(p2, p3);
        }
        rs0 += __shfl_xor_sync(0xffffffffu, rs0, 1);
        rs0 += __shfl_xor_sync(0xffffffffu, rs0, 2);
        rs1 += __shfl_xor_sync(0xffffffffu, rs1, 1);
        rs1 += __shfl_xor_sync(0xffffffffu, rs1, 2);
        l0_ = l0_ * cc0 + rs0;
        l1_ = l1_ * cc1 + rs1;
        #pragma unroll
        for (int j = 0; j < 8; j++) {
            ov[j][0] *= cc0; ov[j][1] *= cc0; ov[j][2] *= cc1; ov[j][3] *= cc1;
        }
        __syncwarp();

        #pragma unroll
        for (int kk = 0; kk < 4; kk++) {
            unsigned ap[4];
            uint32_t o = (uint32_t)((mb + (sub & 1) * 8 + lr) * 128 + kk * 32 + (sub >> 1) * 16);
            ldsm4(ap[0], ap[1], ap[2], ap[3], qb + SWZ(o));
            #pragma unroll
            for (int j2 = 0; j2 < 4; j2++) {
                uint32_t o2 = (uint32_t)((kk * 16 + (sub & 1) * 8 + lr) * 128
                                         + (2 * j2 + (sub >> 1)) * 16);
                unsigned r0, r1, r2, r3;
                ldsm4t(r0, r1, r2, r3, vcb + SWZ(o2));
                MMA_F16(ov[2 * j2][0], ov[2 * j2][1], ov[2 * j2][2], ov[2 * j2][3],
                        ap[0], ap[1], ap[2], ap[3], r0, r1);
                MMA_F16(ov[2 * j2 + 1][0], ov[2 * j2 + 1][1], ov[2 * j2 + 1][2], ov[2 * j2 + 1][3],
                        ap[0], ap[1], ap[2], ap[3], r2, r3);
            }
        }
        if (ci + 1 < nch) { CP_WAIT(0); }
        __syncthreads();
    }

    float inv0 = 1.f / l0_, inv1 = 1.f / l1_;
    size_t r0 = ((size_t)(b * N + q0 + mb + g)) * DIM + h * DHEAD;
    size_t r1 = ((size_t)(b * N + q0 + mb + g + 8)) * DIM + h * DHEAD;
    #pragma unroll
    for (int j = 0; j < 8; j++) {
        *(__half2*)&O[r0 + j * 8 + 2 * tg] = __floats2half2_rn(ov[j][0] * inv0, ov[j][1] * inv0);
        *(__half2*)&O[r1 + j * 8 + 2 * tg] = __floats2half2_rn(ov[j][2] * inv1, ov[j][3] * inv1);
    }
}

// ---- GEGLU: half in/out ----
__global__ __launch_bounds__(256) void geglu_kernel(
    const __half* __restrict__ h, __half* __restrict__ out)
{
    int idx = blockIdx.x * 256 + threadIdx.x;
    if (idx >= BTOK * (FFIN / 2)) return;
    int m = idx >> 11, j2 = idx & 2047;
    const __half2* hr = (const __half2*)(h + (size_t)m * 2 * FFIN);
    float2 a = __half22float2(hr[j2]);
    float2 gt = __half22float2(hr[2048 + j2]);
    float g0 = 0.5f * gt.x * (1.f + erff(gt.x * 0.70710678118654752f));
    float g1 = 0.5f * gt.y * (1.f + erff(gt.y * 0.70710678118654752f));
    ((__half2*)(out + (size_t)m * FFIN))[j2] = __floats2half2_rn(a.x * g0, a.y * g1);
}

extern "C" void kernel_launch(void* const* d_in, const int* in_sizes, int n_in,
                              void* d_out, int out_size)
{
    (void)in_sizes; (void)n_in; (void)out_size;
    const float* x   = (const float*)d_in[0];
    const float* ctx = (const float*)d_in[1];
    const float* Wq1 = (const float*)d_in[2];
    const float* Wk1 = (const float*)d_in[3];
    const float* Wv1 = (const float*)d_in[4];
    const float* Wo1 = (const float*)d_in[5];
    const float* bo1 = (const float*)d_in[6];
    const float* Wq2 = (const float*)d_in[7];
    const float* Wk2 = (const float*)d_in[8];
    const float* Wv2 = (const float*)d_in[9];
    const float* Wo2 = (const float*)d_in[10];
    const float* bo2 = (const float*)d_in[11];
    const float* Wp  = (const float*)d_in[12];
    const float* bp  = (const float*)d_in[13];
    const float* Wf  = (const float*)d_in[14];
    const float* bf  = (const float*)d_in[15];
    const float* g1 = (const float*)d_in[16]; const float* b1 = (const float*)d_in[17];
    const float* g2 = (const float*)d_in[18]; const float* b2 = (const float*)d_in[19];
    const float* g3 = (const float*)d_in[20]; const float* b3 = (const float*)d_in[21];
    float* out = (float*)d_out;

    __half *ln, *q, *k, *v, *att, *hb, *gl, *cc;
    __half *w1, *w2, *w3, *w4, *w5, *w6, *w7, *wp, *wf;
    float* xb;
    cudaGetSymbolAddress((void**)&ln,  g_ln);
    cudaGetSymbolAddress((void**)&q,   g_q);
    cudaGetSymbolAddress((void**)&k,   g_k);
    cudaGetSymbolAddress((void**)&v,   g_v);
    cudaGetSymbolAddress((void**)&att, g_att);
    cudaGetSymbolAddress((void**)&xb,  g_x);
    cudaGetSymbolAddress((void**)&hb,  g_h);
    cudaGetSymbolAddress((void**)&gl,  g_gl);
    cudaGetSymbolAddress((void**)&cc,  g_cc);
    cudaGetSymbolAddress((void**)&w1,  g_w1t);
    cudaGetSymbolAddress((void**)&w2,  g_w2t);
    cudaGetSymbolAddress((void**)&w3,  g_w3t);
    cudaGetSymbolAddress((void**)&w4,  g_w4t);
    cudaGetSymbolAddress((void**)&w5,  g_w5t);
    cudaGetSymbolAddress((void**)&w6,  g_w6t);
    cudaGetSymbolAddress((void**)&w7,  g_w7t);
    cudaGetSymbolAddress((void**)&wp,  g_wpt);
    cudaGetSymbolAddress((void**)&wf,  g_wft);

    cudaFuncSetAttribute(hgemm<true>,  cudaFuncAttributeMaxDynamicSharedMemorySize, HG_SMEM);
    cudaFuncSetAttribute(hgemm<false>, cudaFuncAttributeMaxDynamicSharedMemorySize, HG_SMEM);

    const int B = 4, N = 2048, S = 77;
    const int M = B * N, Mc = B * S;
    dim3 tb(32, 8);
    dim3 gemm1024(1024 / 128, M / 128);
    dim3 gemmCtx(1024 / 128, (Mc + 127) / 128);
    dim3 gemmWp(2 * FFIN / 128, M / 128);
    dim3 aGrid(N / 128, HEADS, B);

    // weight prep (Wo2 reuses w1 after the Wq1 GEMM consumed it)
    transpose_cvt<<<dim3(32, 32), tb>>>(Wq1, w1, 1024, 1024);
    transpose_cvt<<<dim3(32, 32), tb>>>(Wk1, w2, 1024, 1024);
    transpose_cvt<<<dim3(32, 32), tb>>>(Wv1, w3, 1024, 1024);
    transpose_cvt<<<dim3(32, 32), tb>>>(Wo1, w4, 1024, 1024);
    transpose_cvt<<<dim3(32, 32), tb>>>(Wq2, w7, 1024, 1024);
    transpose_cvt<<<dim3(32, 24), tb>>>(Wk2, w5, 768, 1024);
    transpose_cvt<<<dim3(32, 24), tb>>>(Wv2, w6, 768, 1024);
    transpose_cvt<<<dim3(256, 32), tb>>>(Wp, wp, 1024, 2 * FFIN);
    transpose_cvt<<<dim3(32, 128), tb>>>(Wf, wf, 4096, 1024);
    cvt_kernel<<<(Mc * 768 + 255) / 256, 256>>>(ctx, cc, Mc * 768);

    // stage 1: self-attention
    ln_kernel<<<M, 256>>>(x, g1, b1, ln);
    hgemm<true><<<gemm1024, 256, HG_SMEM>>>(ln, w1, nullptr, nullptr, q, M, 1024, 1024);
    hgemm<true><<<gemm1024, 256, HG_SMEM>>>(ln, w2, nullptr, nullptr, k, M, 1024, 1024);
    hgemm<true><<<gemm1024, 256, HG_SMEM>>>(ln, w3, nullptr, nullptr, v, M, 1024, 1024);
    transpose_cvt<<<dim3(32, 32), tb>>>(Wo2, w1, 1024, 1024);
    attn_h<<<aGrid, 256>>>(q, k, v, att, N, N);
    hgemm<false><<<gemm1024, 256, HG_SMEM>>>(att, w4, bo1, x, xb, M, 1024, 1024);

    // stage 2: cross-attention
    ln_kernel<<<M, 256>>>(xb, g2, b2, ln);
    hgemm<true><<<gemm1024, 256, HG_SMEM>>>(ln, w7, nullptr, nullptr, q, M, 1024, 1024);
    hgemm<true><<<gemmCtx, 256, HG_SMEM>>>(cc, w5, nullptr, nullptr, k, Mc, 1024, 768);
    hgemm<true><<<gemmCtx, 256, HG_SMEM>>>(cc, w6, nullptr, nullptr, v, Mc, 1024, 768);
    attn_h<<<aGrid, 256>>>(q, k, v, att, N, S);
    hgemm<false><<<gemm1024, 256, HG_SMEM>>>(att, w1, bo2, xb, xb, M, 1024, 1024);

    // stage 3: GEGLU FF
    ln_kernel<<<M, 256>>>(xb, g3, b3, ln);
    hgemm<true><<<gemmWp, 256, HG_SMEM>>>(ln, wp, bp, nullptr, hb, M, 2 * FFIN, 1024);
    geglu_kernel<<<BTOK * (FFIN / 2) / 256, 256>>>(hb, gl);
    hgemm<false><<<gemm1024, 256, HG_SMEM>>>(gl, wf, bf, xb, out, M, 1024, FFIN);
}

// round 12
// speedup vs baseline: 8.5849x; 1.0177x over previous
#include <cuda_runtime.h>
#include <cuda_fp16.h>
#include <math.h>
#include <stdint.h>

#define DIM   1024
#define HEADS 16
#define DHEAD 64
#define BTOK  8192
#define FFIN  4096

// ---------------- scratch ----------------
__device__ __half g_ln  [BTOK * DIM];
__device__ __half g_q   [BTOK * DIM];
__device__ __half g_kv  [BTOK * DIM];
__device__ __half g_att [BTOK * DIM];
__device__ float  g_x   [BTOK * DIM];
__device__ __half g_qkv [(size_t)BTOK * 3 * DIM];
__device__ __half g_gl  [(size_t)BTOK * FFIN];
__device__ __half g_wqkv[3 * 1024 * 1024];
__device__ __half g_wo1 [1024 * 1024];
__device__ __half g_wq2 [1024 * 1024];
__device__ __half g_wkv [2048 * 768];
__device__ __half g_wo2 [1024 * 1024];
__device__ __half g_wpt [(size_t)(2 * FFIN) * 1024];
__device__ __half g_wft [1024 * FFIN];
__device__ __half g_cc  [308 * 768];

__device__ __forceinline__ uint32_t smem_u32(const void* p) {
    uint32_t a;
    asm("{ .reg .u64 t; cvta.to.shared.u64 t, %1; cvt.u32.u64 %0, t; }" : "=r"(a) : "l"(p));
    return a;
}
#define SWZ(o) ((o) ^ (((o) >> 3) & 0x70))
__device__ __forceinline__ void ldsm4(unsigned &r0, unsigned &r1, unsigned &r2,
                                      unsigned &r3, uint32_t a) {
    asm volatile("ldmatrix.sync.aligned.m8n8.x4.shared.b16 {%0,%1,%2,%3}, [%4];"
                 : "=r"(r0), "=r"(r1), "=r"(r2), "=r"(r3) : "r"(a));
}
__device__ __forceinline__ void ldsm4t(unsigned &r0, unsigned &r1, unsigned &r2,
                                       unsigned &r3, uint32_t a) {
    asm volatile("ldmatrix.sync.aligned.m8n8.x4.trans.shared.b16 {%0,%1,%2,%3}, [%4];"
                 : "=r"(r0), "=r"(r1), "=r"(r2), "=r"(r3) : "r"(a));
}
#define MMA_F16(c0,c1,c2,c3,a0,a1,a2,a3,b0,b1)                               \
    asm volatile(                                                            \
        "mma.sync.aligned.m16n8k16.row.col.f32.f16.f16.f32 "                 \
        "{%0,%1,%2,%3}, {%4,%5,%6,%7}, {%8,%9}, {%0,%1,%2,%3};"              \
        : "+f"(c0), "+f"(c1), "+f"(c2), "+f"(c3)                             \
        : "r"(a0), "r"(a1), "r"(a2), "r"(a3), "r"(b0), "r"(b1))
__device__ __forceinline__ void cpa16(uint32_t dst, const void* src, uint32_t sz) {
    asm volatile("cp.async.cg.shared.global [%0], [%1], 16, %2;"
                 :: "r"(dst), "l"(src), "r"(sz) : "memory");
}
#define CP_COMMIT() asm volatile("cp.async.commit_group;" ::: "memory")
#define CP_WAIT(n)  asm volatile("cp.async.wait_group %0;" :: "n"(n) : "memory")

__global__ __launch_bounds__(256) void transpose_cvt(
    const float* __restrict__ W, __half* __restrict__ Wt, int K, int N, int pack)
{
    __shared__ float tile[32][33];
    int tx = threadIdx.x, ty = threadIdx.y;
    int n = blockIdx.x * 32 + tx, k0 = blockIdx.y * 32;
    #pragma unroll
    for (int j = 0; j < 32; j += 8)
        tile[ty + j][tx] = W[(size_t)(k0 + ty + j) * N + n];
    __syncthreads();
    int k = k0 + tx, n0 = blockIdx.x * 32;
    #pragma unroll
    for (int j = 0; j < 32; j += 8) {
        int nr = n0 + ty + j;
        int nn = pack ? (2 * (nr & 4095) + (nr >> 12)) : nr;
        Wt[(size_t)nn * K + k] = __float2half(tile[tx][ty + j]);
    }
}

__global__ __launch_bounds__(256) void cvt_kernel(
    const float* __restrict__ in, __half* __restrict__ out, int n)
{
    int i = blockIdx.x * 256 + threadIdx.x;
    if (i < n) out[i] = __float2half(in[i]);
}

__global__ __launch_bounds__(256) void ln_kernel(
    const float* __restrict__ x, const float* __restrict__ gamma,
    const float* __restrict__ beta, __half* __restrict__ out)
{
    int row = blockIdx.x, tid = threadIdx.x;
    float4 t = ((const float4*)(x + (size_t)row * DIM))[tid];
    float s = t.x + t.y + t.z + t.w;
    float q = t.x * t.x + t.y * t.y + t.z * t.z + t.w * t.w;
    #pragma unroll
    for (int o = 16; o; o >>= 1) {
        s += __shfl_xor_sync(0xffffffffu, s, o);
        q += __shfl_xor_sync(0xffffffffu, q, o);
    }
    __shared__ float ssum[8], ssq[8], smean, srstd;
    int wid = tid >> 5, lane = tid & 31;
    if (lane == 0) { ssum[wid] = s; ssq[wid] = q; }
    __syncthreads();
    if (tid == 0) {
        float S = 0.f, Q = 0.f;
        #pragma unroll
        for (int i = 0; i < 8; i++) { S += ssum[i]; Q += ssq[i]; }
        float mean = S * (1.f / DIM);
        smean = mean;
        srstd = rsqrtf(Q * (1.f / DIM) - mean * mean + 1e-5f);
    }
    __syncthreads();
    float mean = smean, rstd = srstd;
    float4 gg = ((const float4*)gamma)[tid];
    float4 bb = ((const float4*)beta)[tid];
    __half2* orow = (__half2*)(out + (size_t)row * DIM);
    orow[tid * 2 + 0] = __floats2half2_rn((t.x - mean) * rstd * gg.x + bb.x,
                                          (t.y - mean) * rstd * gg.y + bb.y);
    orow[tid * 2 + 1] = __floats2half2_rn((t.z - mean) * rstd * gg.z + bb.z,
                                          (t.w - mean) * rstd * gg.w + bb.w);
}

#define HG_STAGE 32768
#define HG_SMEM  (3 * HG_STAGE)

template<int MODE>
__global__ __launch_bounds__(256, 2) void hgemm(
    const __half* __restrict__ A, const __half* __restrict__ Bt,
    const float* __restrict__ bias, const float* __restrict__ Res,
    void* __restrict__ Cv, int M, int N, int K)
{
    extern __shared__ uint8_t sm[];
    const uint32_t sbase = smem_u32(sm);
    const int t = threadIdx.x, warp = t >> 5, lane = t & 31;
    const int g = lane >> 2, tg = lane & 3;
    const int sub = lane >> 3, lr = lane & 7;
    const int m0 = blockIdx.y * 128, n0 = blockIdx.x * 128;
    const int wm = (warp & 1) * 64, wn = (warp >> 1) * 32;

    uint32_t qoff[4], a_sz[4];
    const __half* a_src[4];
    const __half* b_src[4];
    #pragma unroll
    for (int i = 0; i < 4; i++) {
        int idx = t + i * 256;
        int row = idx >> 3, kq = idx & 7;
        qoff[i] = SWZ((uint32_t)(row * 128 + kq * 16));
        int ar = (m0 + row < M) ? (m0 + row) : 0;
        a_sz[i]  = (m0 + row < M) ? 16u : 0u;
        a_src[i] = A  + (size_t)ar * K + kq * 8;
        b_src[i] = Bt + (size_t)(n0 + row) * K + kq * 8;
    }

    float c[4][4][4];
    #pragma unroll
    for (int i = 0; i < 4; i++)
        #pragma unroll
        for (int j = 0; j < 4; j++)
            #pragma unroll
            for (int r = 0; r < 4; r++) c[i][j][r] = 0.f;

    const int S = K / 64;
    #pragma unroll
    for (int st = 0; st < 2; st++) {
        uint32_t sb = sbase + st * HG_STAGE;
        #pragma unroll
        for (int i = 0; i < 4; i++) {
            cpa16(sb + qoff[i],         a_src[i] + st * 64, a_sz[i]);
            cpa16(sb + 16384 + qoff[i], b_src[i] + st * 64, 16u);
        }
        CP_COMMIT();
    }

    int buf = 0;
    for (int s = 0; s < S; s++) {
        if (s == S - 1) { CP_WAIT(0); } else { CP_WAIT(1); }
        __syncthreads();
        if (s + 2 < S) {
            int nb = buf + 2; if (nb >= 3) nb -= 3;
            uint32_t sb = sbase + nb * HG_STAGE;
            #pragma unroll
            for (int i = 0; i < 4; i++) {
                cpa16(sb + qoff[i],         a_src[i] + (s + 2) * 64, a_sz[i]);
                cpa16(sb + 16384 + qoff[i], b_src[i] + (s + 2) * 64, 16u);
            }
            CP_COMMIT();
        }

        const uint32_t ab = sbase + buf * HG_STAGE, bb = ab + 16384;
        #pragma unroll
        for (int kk = 0; kk < 4; kk++) {
            unsigned af[4][4], bf[4][2];
            #pragma unroll
            for (int i = 0; i < 4; i++) {
                uint32_t o = (uint32_t)((wm + i * 16 + (sub & 1) * 8 + lr) * 128
                                        + kk * 32 + (sub >> 1) * 16);
                ldsm4(af[i][0], af[i][1], af[i][2], af[i][3], ab + SWZ(o));
            }
            #pragma unroll
            for (int j2 = 0; j2 < 2; j2++) {
                uint32_t o = (uint32_t)((wn + j2 * 16 + (sub >> 1) * 8 + lr) * 128
                                        + kk * 32 + (sub & 1) * 16);
                unsigned r0, r1, r2, r3;
                ldsm4(r0, r1, r2, r3, bb + SWZ(o));
                bf[j2 * 2][0] = r0;     bf[j2 * 2][1] = r1;
                bf[j2 * 2 + 1][0] = r2; bf[j2 * 2 + 1][1] = r3;
            }
            #pragma unroll
            for (int i = 0; i < 4; i++)
                #pragma unroll
                for (int j = 0; j < 4; j++)
                    MMA_F16(c[i][j][0], c[i][j][1], c[i][j][2], c[i][j][3],
                            af[i][0], af[i][1], af[i][2], af[i][3],
                            bf[j][0], bf[j][1]);
        }
        if (++buf >= 3) buf = 0;
    }

    #pragma unroll
    for (int i = 0; i < 4; i++) {
        #pragma unroll
        for (int j = 0; j < 4; j++) {
            int col = n0 + wn + j * 8 + 2 * tg;
            int r0m = m0 + wm + i * 16 + g, r1m = r0m + 8;
            if (MODE == 2) {
                __half* C = (__half*)Cv;
                int jj = col >> 1;
                float ba = bias[jj], bg = bias[jj + FFIN];
                if (r0m < M) {
                    float a = c[i][j][0] + ba, gt = c[i][j][1] + bg;
                    C[(size_t)r0m * (N >> 1) + jj] =
                        __float2half(a * 0.5f * gt * (1.f + erff(gt * 0.70710678118654752f)));
                }
                if (r1m < M) {
                    float a = c[i][j][2] + ba, gt = c[i][j][3] + bg;
                    C[(size_t)r1m * (N >> 1) + jj] =
                        __float2half(a * 0.5f * gt * (1.f + erff(gt * 0.70710678118654752f)));
                }
            } else {
                float bx = 0.f, by = 0.f;
                if (bias) { bx = bias[col]; by = bias[col + 1]; }
                if (MODE == 1) {
                    __half* C = (__half*)Cv;
                    if (r0m < M)
                        *(__half2*)&C[(size_t)r0m * N + col] =
                            __floats2half2_rn(c[i][j][0] + bx, c[i][j][1] + by);
                    if (r1m < M)
                        *(__half2*)&C[(size_t)r1m * N + col] =
                            __floats2half2_rn(c[i][j][2] + bx, c[i][j][3] + by);
                } else {
                    float* C = (float*)Cv;
                    if (r0m < M) {
                        size_t o0 = (size_t)r0m * N + col;
                        float2 v; v.x = c[i][j][0] + bx; v.y = c[i][j][1] + by;
                        if (Res) { float2 rr = *(const float2*)&Res[o0]; v.x += rr.x; v.y += rr.y; }
                        *(float2*)&C[o0] = v;
                    }
                    if (r1m < M) {
                        size_t o1 = (size_t)r1m * N + col;
                        float2 v; v.x = c[i][j][2] + bx; v.y = c[i][j][3] + by;
                        if (Res) { float2 rr = *(const float2*)&Res[o1]; v.x += rr.x; v.y += rr.y; }
                        *(float2*)&C[o1] = v;
                    }
                }
            }
        }
    }
}

__global__ __launch_bounds__(256) void attn_h(
    const __half* __restrict__ Q, const __half* __restrict__ K,
    const __half* __restrict__ V, __half* __restrict__ O,
    int N, int S, int sQ, int sKV)
{
    __shared__ uint8_t Qs[128 * 128];
    __shared__ uint8_t Ks[2][64 * 128];
    __shared__ uint8_t Vs[2][64 * 128];
    const int t = threadIdx.x, warp = t >> 5, lane = t & 31;
    const int g = lane >> 2, tg = lane & 3;
    const int sub = lane >> 3, lr = lane & 7;
    const int b = blockIdx.z, h = blockIdx.y;
    const int q0 = blockIdx.x * 128, mb = warp * 16;
    const float scale = 0.125f;
    const uint32_t qb = smem_u32(Qs), kb = smem_u32(Ks), vb = smem_u32(Vs);

    int crow[2], ckq[2];
    uint32_t koff[2];
    #pragma unroll
    for (int i = 0; i < 2; i++) {
        int lin = t + i * 256;
        crow[i] = lin >> 3; ckq[i] = lin & 7;
        koff[i] = SWZ((uint32_t)(crow[i] * 128 + ckq[i] * 16));
    }

    #pragma unroll
    for (int it = 0; it < 4; it++) {
        int lin = t + it * 256;
        int r = lin >> 3, cq = lin & 7;
        cpa16(qb + SWZ((uint32_t)(r * 128 + cq * 16)),
              &Q[((size_t)(b * N + q0 + r)) * sQ + h * DHEAD + cq * 8], 16u);
    }
    #pragma unroll
    for (int i = 0; i < 2; i++) {
        int sg = crow[i];
        uint32_t sz = (sg < S) ? 16u : 0u;
        size_t off = ((size_t)(b * S + (sg < S ? sg : 0))) * sKV + h * DHEAD + ckq[i] * 8;
        cpa16(kb + koff[i], &K[off], sz);
        cpa16(vb + koff[i], &V[off], sz);
    }
    CP_COMMIT();
    CP_WAIT(0);
    __syncthreads();

    unsigned aq[4][4];
    #pragma unroll
    for (int kk = 0; kk < 4; kk++) {
        uint32_t o = (uint32_t)((mb + (sub & 1) * 8 + lr) * 128 + kk * 32 + (sub >> 1) * 16);
        ldsm4(aq[kk][0], aq[kk][1], aq[kk][2], aq[kk][3], qb + SWZ(o));
    }
    __syncthreads();

    float ov[8][4];
    #pragma unroll
    for (int j = 0; j < 8; j++) { ov[j][0] = ov[j][1] = ov[j][2] = ov[j][3] = 0.f; }
    float m0_ = -1e30f, m1_ = -1e30f, l0_ = 0.f, l1_ = 0.f;

    const int nch = (S + 63) / 64;
    for (int ci = 0; ci < nch; ci++) {
        int bufc = ci & 1;
        if (ci + 1 < nch) {
            int nb = bufc ^ 1;
            #pragma unroll
            for (int i = 0; i < 2; i++) {
                int sg = (ci + 1) * 64 + crow[i];
                uint32_t sz = (sg < S) ? 16u : 0u;
                size_t off = ((size_t)(b * S + (sg < S ? sg : 0))) * sKV + h * DHEAD + ckq[i] * 8;
                cpa16(kb + nb * 8192 + koff[i], &K[off], sz);
                cpa16(vb + nb * 8192 + koff[i], &V[off], sz);
            }
            CP_COMMIT();
        }
        const uint32_t kcb = kb + bufc * 8192, vcb = vb + bufc * 8192;
        const int s0 = ci * 64;

        float sc[8][4];
        #pragma unroll
        for (int j = 0; j < 8; j++) { sc[j][0] = sc[j][1] = sc[j][2] = sc[j][3] = 0.f; }
        #pragma unroll
        for (int kk = 0; kk < 4; kk++) {
            #pragma unroll
            for (int j2 = 0; j2 < 4; j2++) {
                uint32_t o = (uint32_t)(((2 * j2 + (sub >> 1)) * 8 + lr) * 128
                                        + kk * 32 + (sub & 1) * 16);
                unsigned r0, r1, r2, r3;
                ldsm4(r0, r1, r2, r3, kcb + SWZ(o));
                MMA_F16(sc[2 * j2][0], sc[2 * j2][1], sc[2 * j2][2], sc[2 * j2][3],
                        aq[kk][0], aq[kk][1], aq[kk][2], aq[kk][3], r0, r1);
                MMA_F16(sc[2 * j2 + 1][0], sc[2 * j2 + 1][1], sc[2 * j2 + 1][2], sc[2 * j2 + 1][3],
                        aq[kk][0], aq[kk][1], aq[kk][2], aq[kk][3], r2, r3);
            }
        }

        bool tail = (s0 + 64 > S);
        #pragma unroll
        for (int j = 0; j < 8; j++) {
            sc[j][0] *= scale; sc[j][1] *= scale; sc[j][2] *= scale; sc[j][3] *= scale;
            if (tail) {
                int col = s0 + j * 8 + 2 * tg;
                if (col     >= S) { sc[j][0] = -1e30f; sc[j][2] = -1e30f; }
                if (col + 1 >= S) { sc[j][1] = -1e30f; sc[j][3] = -1e30f; }
            }
        }
        float rm0 = -1e30f, rm1 = -1e30f;
        #pragma unroll
        for (int j = 0; j < 8; j++) {
            rm0 = fmaxf(rm0, fmaxf(sc[j][0], sc[j][1]));
            rm1 = fmaxf(rm1, fmaxf(sc[j][2], sc[j][3]));
        }
        rm0 = fmaxf(rm0, __shfl_xor_sync(0xffffffffu, rm0, 1));
        rm0 = fmaxf(rm0, __shfl_xor_sync(0xffffffffu, rm0, 2));
        rm1 = fmaxf(rm1, __shfl_xor_sync(0xffffffffu, rm1, 1));
        rm1 = fmaxf(rm1, __shfl_xor_sync(0xffffffffu, rm1, 2));
        float nm0 = fmaxf(m0_, rm0), nm1 = fmaxf(m1_, rm1);
        float cc0 = __expf(m0_ - nm0), cc1 = __expf(m1_ - nm1);
        m0_ = nm0; m1_ = nm1;
        float rs0 = 0.f, rs1 = 0.f;
        #pragma unroll
        for (int j = 0; j < 8; j++) {
            float p0 = __expf(sc[j][0] - nm0), p1 = __expf(sc[j][1] - nm0);
            float p2 = __expf(sc[j][2] - nm1), p3 = __expf(sc[j][3] - nm1);
            rs0 += p0 + p1; rs1 += p2 + p3;
            uint32_t o0 = (uint32_t)((mb + g) * 128 + j * 16 + 4 * tg);
            uint32_t o1 = (uint32_t)((mb + g + 8) * 128 + j * 16 + 4 * tg);
            *(__half2*)(Qs + SWZ(o0)) = __floats2half2_rn(p0, p1);
            *(__half2*)(Qs + SWZ(o1)) = __floats2half2_rn(p2, p3);
        }
        rs0 += __shfl_xor_sync(0xffffffffu, rs0, 1);
        rs0 += __shfl_xor_sync(0xffffffffu, rs0, 2);
        rs1 += __shfl_xor_sync(0xffffffffu, rs1, 1);
        rs1 += __shfl_xor_sync(0xffffffffu, rs1, 2);
        l0_ = l0_ * cc0 + rs0;
        l1_ = l1_ * cc1 + rs1;
        #pragma unroll
        for (int j = 0; j < 8; j++) {
            ov[j][0] *= cc0; ov[j][1] *= cc0; ov[j][2] *= cc1; ov[j][3] *= cc1;
        }
        __syncwarp();

        #pragma unroll
        for (int kk = 0; kk < 4; kk++) {
            unsigned ap[4];
            uint32_t o = (uint32_t)((mb + (sub & 1) * 8 + lr) * 128 + kk * 32 + (sub >> 1) * 16);
            ldsm4(ap[0], ap[1], ap[2], ap[3], qb + SWZ(o));
            #pragma unroll
            for (int j2 = 0; j2 < 4; j2++) {
                uint32_t o2 = (uint32_t)((kk * 16 + (sub & 1) * 8 + lr) * 128
                                         + (2 * j2 + (sub >> 1)) * 16);
                unsigned r0, r1, r2, r3;
                ldsm4t(r0, r1, r2, r3, vcb + SWZ(o2));
                MMA_F16(ov[2 * j2][0], ov[2 * j2][1], ov[2 * j2][2], ov[2 * j2][3],
                        ap[0], ap[1], ap[2], ap[3], r0, r1);
                MMA_F16(ov[2 * j2 + 1][0], ov[2 * j2 + 1][1], ov[2 * j2 + 1][2], ov[2 * j2 + 1][3],
                        ap[0], ap[1], ap[2], ap[3], r2, r3);
            }
        }
        if (ci + 1 < nch) { CP_WAIT(0); }
        __syncthreads();
    }

    float inv0 = 1.f / l0_, inv1 = 1.f / l1_;
    size_t r0 = ((size_t)(b * N + q0 + mb + g)) * DIM + h * DHEAD;
    size_t r1 = ((size_t)(b * N + q0 + mb + g + 8)) * DIM + h * DHEAD;
    #pragma unroll
    for (int j = 0; j < 8; j++) {
        *(__half2*)&O[r0 + j * 8 + 2 * tg] = __floats2half2_rn(ov[j][0] * inv0, ov[j][1] * inv0);
        *(__half2*)&O[r1 + j * 8 + 2 * tg] = __floats2half2_rn(ov[j][2] * inv1, ov[j][3] * inv1);
    }
}

extern "C" void kernel_launch(void* const* d_in, const int* in_sizes, int n_in,
                              void* d_out, int out_size)
{
    (void)in_sizes; (void)n_in; (void)out_size;
    const float* x   = (const float*)d_in[0];
    const float* ctx = (const float*)d_in[1];
    const float* Wq1 = (const float*)d_in[2];
    const float* Wk1 = (const float*)d_in[3];
    const float* Wv1 = (const float*)d_in[4];
    const float* Wo1 = (const float*)d_in[5];
    const float* bo1 = (const float*)d_in[6];
    const float* Wq2 = (const float*)d_in[7];
    const float* Wk2 = (const float*)d_in[8];
    const float* Wv2 = (const float*)d_in[9];
    const float* Wo2 = (const float*)d_in[10];
    const float* bo2 = (const float*)d_in[11];
    const float* Wp  = (const float*)d_in[12];
    const float* bp  = (const float*)d_in[13];
    const float* Wf  = (const float*)d_in[14];
    const float* bf  = (const float*)d_in[15];
    const float* g1 = (const float*)d_in[16]; const float* b1 = (const float*)d_in[17];
    const float* g2 = (const float*)d_in[18]; const float* b2 = (const float*)d_in[19];
    const float* g3 = (const float*)d_in[20]; const float* b3 = (const float*)d_in[21];
    float* out = (float*)d_out;

    __half *ln, *q, *kv, *att, *qkv, *gl, *cc;
    __half *wqkv, *wo1, *wq2, *wkv, *wo2, *wp, *wf;
    float* xb;
    cudaGetSymbolAddress((void**)&ln,   g_ln);
    cudaGetSymbolAddress((void**)&q,    g_q);
    cudaGetSymbolAddress((void**)&kv,   g_kv);
    cudaGetSymbolAddress((void**)&att,  g_att);
    cudaGetSymbolAddress((void**)&xb,   g_x);
    cudaGetSymbolAddress((void**)&qkv,  g_qkv);
    cudaGetSymbolAddress((void**)&gl,   g_gl);
    cudaGetSymbolAddress((void**)&cc,   g_cc);
    cudaGetSymbolAddress((void**)&wqkv, g_wqkv);
    cudaGetSymbolAddress((void**)&wo1,  g_wo1);
    cudaGetSymbolAddress((void**)&wq2,  g_wq2);
    cudaGetSymbolAddress((void**)&wkv,  g_wkv);
    cudaGetSymbolAddress((void**)&wo2,  g_wo2);
    cudaGetSymbolAddress((void**)&wp,   g_wpt);
    cudaGetSymbolAddress((void**)&wf,   g_wft);

    cudaFuncSetAttribute(hgemm<0>, cudaFuncAttributeMaxDynamicSharedMemorySize, HG_SMEM);
    cudaFuncSetAttribute(hgemm<1>, cudaFuncAttributeMaxDynamicSharedMemorySize, HG_SMEM);
    cudaFuncSetAttribute(hgemm<2>, cudaFuncAttributeMaxDynamicSharedMemorySize, HG_SMEM);

    const int B = 4, N = 2048, S = 77;
    const int M = B * N, Mc = B * S;
    dim3 tb(32, 8);
    dim3 gQKV(3072 / 128, M / 128);
    dim3 g1024(1024 / 128, M / 128);
    dim3 gKV(2048 / 128, (Mc + 127) / 128);
    dim3 gWp(2 * FFIN / 128, M / 128);
    dim3 aGrid(N / 128, HEADS, B);

    transpose_cvt<<<dim3(32, 32), tb>>>(Wq1, wqkv, 1024, 1024, 0);
    transpose_cvt<<<dim3(32, 32), tb>>>(Wk1, wqkv + 1024 * 1024, 1024, 1024, 0);
    transpose_cvt<<<dim3(32, 32), tb>>>(Wv1, wqkv + 2 * 1024 * 1024, 1024, 1024, 0);
    transpose_cvt<<<dim3(32, 32), tb>>>(Wo1, wo1, 1024, 1024, 0);
    transpose_cvt<<<dim3(32, 32), tb>>>(Wq2, wq2, 1024, 1024, 0);
    transpose_cvt<<<dim3(32, 24), tb>>>(Wk2, wkv, 768, 1024, 0);
    transpose_cvt<<<dim3(32, 24), tb>>>(Wv2, wkv + 1024 * 768, 768, 1024, 0);
    transpose_cvt<<<dim3(32, 32), tb>>>(Wo2, wo2, 1024, 1024, 0);
    transpose_cvt<<<dim3(256, 32), tb>>>(Wp, wp, 1024, 2 * FFIN, 1);
    transpose_cvt<<<dim3(32, 128), tb>>>(Wf, wf, 4096, 1024, 0);
    cvt_kernel<<<(Mc * 768 + 255) / 256, 256>>>(ctx, cc, Mc * 768);

    ln_kernel<<<M, 256>>>(x, g1, b1, ln);
    hgemm<1><<<gQKV, 256, HG_SMEM>>>(ln, wqkv, nullptr, nullptr, qkv, M, 3072, 1024);
    attn_h<<<aGrid, 256>>>(qkv, qkv + 1024, qkv + 2048, att, N, N, 3072, 3072);
    hgemm<0><<<g1024, 256, HG_SMEM>>>(att, wo1, bo1, x, xb, M, 1024, 1024);

    ln_kernel<<<M, 256>>>(xb, g2, b2, ln);
    hgemm<1><<<g1024, 256, HG_SMEM>>>(ln, wq2, nullptr, nullptr, q, M, 1024, 1024);
    hgemm<1><<<gKV, 256, HG_SMEM>>>(cc, wkv, nullptr, nullptr, kv, Mc, 2048, 768);
    attn_h<<<aGrid, 256>>>(q, kv, kv + 1024, att, N, S, 1024, 2048);
    hgemm<0><<<g1024, 256, HG_SMEM>>>(att, wo2, bo2, xb, xb, M, 1024, 1024);

    ln_kernel<<<M, 256>>>(xb, g3, b3, ln);
    hgemm<2><<<gWp, 256, HG_SMEM>>>(ln, wp, bp, nullptr, gl, M, 2 * FFIN, 1024);
    hgemm<0><<<g1024, 256, HG_SMEM>>>(gl, wf, bf, xb, out, M, 1024, FFIN);
}

// round 15
// speedup vs baseline: 9.2504x; 1.0775x over previous
#include <cuda_runtime.h>
#include <cuda_fp16.h>
#include <math.h>
#include <stdint.h>

#define DIM   1024
#define HEADS 16
#define DHEAD 64
#define BTOK  8192
#define FFIN  4096

// ---------------- scratch ----------------
__device__ __half g_ln  [BTOK * DIM];
__device__ __half g_q   [BTOK * DIM];
__device__ __half g_kv  [BTOK * DIM];
__device__ __half g_att [BTOK * DIM];
__device__ float  g_x   [BTOK * DIM];
__device__ __half g_qkv [(size_t)BTOK * 3 * DIM];
__device__ __half g_gl  [(size_t)BTOK * FFIN];
__device__ __half g_wqkv[3 * 1024 * 1024];
__device__ __half g_wo1 [1024 * 1024];
__device__ __half g_wq2 [1024 * 1024];
__device__ __half g_wkv [2048 * 768];
__device__ __half g_wo2 [1024 * 1024];
__device__ __half g_wpt [(size_t)(2 * FFIN) * 1024];
__device__ __half g_wft [1024 * FFIN];
__device__ __half g_cc  [308 * 768];

__device__ __forceinline__ uint32_t smem_u32(const void* p) {
    uint32_t a;
    asm("{ .reg .u64 t; cvta.to.shared.u64 t, %1; cvt.u32.u64 %0, t; }" : "=r"(a) : "l"(p));
    return a;
}
__device__ __forceinline__ float ex2f(float x) {
    float y; asm("ex2.approx.ftz.f32 %0, %1;" : "=f"(y) : "f"(x)); return y;
}
__device__ __forceinline__ unsigned packh2(float a, float b) {
    __half2 hv = __floats2half2_rn(a, b);
    unsigned u;
    asm("mov.b32 %0, %1;" : "=r"(u) : "r"(*(unsigned*)&hv));
    return u;
}
#define SWZ(o) ((o) ^ (((o) >> 3) & 0x70))
__device__ __forceinline__ void ldsm4(unsigned &r0, unsigned &r1, unsigned &r2,
                                      unsigned &r3, uint32_t a) {
    asm volatile("ldmatrix.sync.aligned.m8n8.x4.shared.b16 {%0,%1,%2,%3}, [%4];"
                 : "=r"(r0), "=r"(r1), "=r"(r2), "=r"(r3) : "r"(a));
}
__device__ __forceinline__ void ldsm4t(unsigned &r0, unsigned &r1, unsigned &r2,
                                       unsigned &r3, uint32_t a) {
    asm volatile("ldmatrix.sync.aligned.m8n8.x4.trans.shared.b16 {%0,%1,%2,%3}, [%4];"
                 : "=r"(r0), "=r"(r1), "=r"(r2), "=r"(r3) : "r"(a));
}
#define MMA_F16(c0,c1,c2,c3,a0,a1,a2,a3,b0,b1)                               \
    asm volatile(                                                            \
        "mma.sync.aligned.m16n8k16.row.col.f32.f16.f16.f32 "                 \
        "{%0,%1,%2,%3}, {%4,%5,%6,%7}, {%8,%9}, {%0,%1,%2,%3};"              \
        : "+f"(c0), "+f"(c1), "+f"(c2), "+f"(c3)                             \
        : "r"(a0), "r"(a1), "r"(a2), "r"(a3), "r"(b0), "r"(b1))
__device__ __forceinline__ void cpa16(uint32_t dst, const void* src, uint32_t sz) {
    asm volatile("cp.async.cg.shared.global [%0], [%1], 16, %2;"
                 :: "r"(dst), "l"(src), "r"(sz) : "memory");
}
#define CP_COMMIT() asm volatile("cp.async.commit_group;" ::: "memory")
#define CP_WAIT(n)  asm volatile("cp.async.wait_group %0;" :: "n"(n) : "memory")

// ---- batched weight transpose: Wt[N][K] = W[K][N], z selects pair ----
struct TBatch { const float* src[6]; __half* dst[6]; };

__global__ __launch_bounds__(256) void transpose_multi(TBatch tb, int K, int N)
{
    __shared__ float tile[32][33];
    const float* W = tb.src[blockIdx.z];
    __half* Wt = tb.dst[blockIdx.z];
    int tx = threadIdx.x, ty = threadIdx.y;
    int n = blockIdx.x * 32 + tx, k0 = blockIdx.y * 32;
    #pragma unroll
    for (int j = 0; j < 32; j += 8)
        tile[ty + j][tx] = W[(size_t)(k0 + ty + j) * N + n];
    __syncthreads();
    int k = k0 + tx, n0 = blockIdx.x * 32;
    #pragma unroll
    for (int j = 0; j < 32; j += 8)
        Wt[(size_t)(n0 + ty + j) * K + k] = __float2half(tile[tx][ty + j]);
}

__global__ __launch_bounds__(256) void transpose_cvt(
    const float* __restrict__ W, __half* __restrict__ Wt, int K, int N, int pack)
{
    __shared__ float tile[32][33];
    int tx = threadIdx.x, ty = threadIdx.y;
    int n = blockIdx.x * 32 + tx, k0 = blockIdx.y * 32;
    #pragma unroll
    for (int j = 0; j < 32; j += 8)
        tile[ty + j][tx] = W[(size_t)(k0 + ty + j) * N + n];
    __syncthreads();
    int k = k0 + tx, n0 = blockIdx.x * 32;
    #pragma unroll
    for (int j = 0; j < 32; j += 8) {
        int nr = n0 + ty + j;
        int nn = pack ? (2 * (nr & 4095) + (nr >> 12)) : nr;
        Wt[(size_t)nn * K + k] = __float2half(tile[tx][ty + j]);
    }
}

__global__ __launch_bounds__(256) void cvt_kernel(
    const float* __restrict__ in, __half* __restrict__ out, int n)
{
    int i = blockIdx.x * 256 + threadIdx.x;
    if (i < n) out[i] = __float2half(in[i]);
}

__global__ __launch_bounds__(256) void ln_kernel(
    const float* __restrict__ x, const float* __restrict__ gamma,
    const float* __restrict__ beta, __half* __restrict__ out)
{
    int row = blockIdx.x, tid = threadIdx.x;
    float4 t = ((const float4*)(x + (size_t)row * DIM))[tid];
    float s = t.x + t.y + t.z + t.w;
    float q = t.x * t.x + t.y * t.y + t.z * t.z + t.w * t.w;
    #pragma unroll
    for (int o = 16; o; o >>= 1) {
        s += __shfl_xor_sync(0xffffffffu, s, o);
        q += __shfl_xor_sync(0xffffffffu, q, o);
    }
    __shared__ float ssum[8], ssq[8], smean, srstd;
    int wid = tid >> 5, lane = tid & 31;
    if (lane == 0) { ssum[wid] = s; ssq[wid] = q; }
    __syncthreads();
    if (tid == 0) {
        float S = 0.f, Q = 0.f;
        #pragma unroll
        for (int i = 0; i < 8; i++) { S += ssum[i]; Q += ssq[i]; }
        float mean = S * (1.f / DIM);
        smean = mean;
        srstd = rsqrtf(Q * (1.f / DIM) - mean * mean + 1e-5f);
    }
    __syncthreads();
    float mean = smean, rstd = srstd;
    float4 gg = ((const float4*)gamma)[tid];
    float4 bb = ((const float4*)beta)[tid];
    __half2* orow = (__half2*)(out + (size_t)row * DIM);
    orow[tid * 2 + 0] = __floats2half2_rn((t.x - mean) * rstd * gg.x + bb.x,
                                          (t.y - mean) * rstd * gg.y + bb.y);
    orow[tid * 2 + 1] = __floats2half2_rn((t.z - mean) * rstd * gg.z + bb.z,
                                          (t.w - mean) * rstd * gg.w + bb.w);
}

#define HG_STAGE 32768
#define HG_SMEM  (3 * HG_STAGE)

template<int MODE>
__global__ __launch_bounds__(256, 2) void hgemm(
    const __half* __restrict__ A, const __half* __restrict__ Bt,
    const float* __restrict__ bias, const float* __restrict__ Res,
    void* __restrict__ Cv, int M, int N, int K)
{
    extern __shared__ uint8_t sm[];
    const uint32_t sbase = smem_u32(sm);
    const int t = threadIdx.x, warp = t >> 5, lane = t & 31;
    const int g = lane >> 2, tg = lane & 3;
    const int sub = lane >> 3, lr = lane & 7;
    const int m0 = blockIdx.y * 128, n0 = blockIdx.x * 128;
    const int wm = (warp & 1) * 64, wn = (warp >> 1) * 32;

    uint32_t qoff[4], a_sz[4];
    const __half* a_src[4];
    const __half* b_src[4];
    #pragma unroll
    for (int i = 0; i < 4; i++) {
        int idx = t + i * 256;
        int row = idx >> 3, kq = idx & 7;
        qoff[i] = SWZ((uint32_t)(row * 128 + kq * 16));
        int ar = (m0 + row < M) ? (m0 + row) : 0;
        a_sz[i]  = (m0 + row < M) ? 16u : 0u;
        a_src[i] = A  + (size_t)ar * K + kq * 8;
        b_src[i] = Bt + (size_t)(n0 + row) * K + kq * 8;
    }

    float c[4][4][4];
    #pragma unroll
    for (int i = 0; i < 4; i++)
        #pragma unroll
        for (int j = 0; j < 4; j++)
            #pragma unroll
            for (int r = 0; r < 4; r++) c[i][j][r] = 0.f;

    const int S = K / 64;
    #pragma unroll
    for (int st = 0; st < 2; st++) {
        uint32_t sb = sbase + st * HG_STAGE;
        #pragma unroll
        for (int i = 0; i < 4; i++) {
            cpa16(sb + qoff[i],         a_src[i] + st * 64, a_sz[i]);
            cpa16(sb + 16384 + qoff[i], b_src[i] + st * 64, 16u);
        }
        CP_COMMIT();
    }

    int buf = 0;
    for (int s = 0; s < S; s++) {
        if (s == S - 1) { CP_WAIT(0); } else { CP_WAIT(1); }
        __syncthreads();
        if (s + 2 < S) {
            int nb = buf + 2; if (nb >= 3) nb -= 3;
            uint32_t sb = sbase + nb * HG_STAGE;
            #pragma unroll
            for (int i = 0; i < 4; i++) {
                cpa16(sb + qoff[i],         a_src[i] + (s + 2) * 64, a_sz[i]);
                cpa16(sb + 16384 + qoff[i], b_src[i] + (s + 2) * 64, 16u);
            }
            CP_COMMIT();
        }

        const uint32_t ab = sbase + buf * HG_STAGE, bb = ab + 16384;
        #pragma unroll
        for (int kk = 0; kk < 4; kk++) {
            unsigned af[4][4], bf[4][2];
            #pragma unroll
            for (int i = 0; i < 4; i++) {
                uint32_t o = (uint32_t)((wm + i * 16 + (sub & 1) * 8 + lr) * 128
                                        + kk * 32 + (sub >> 1) * 16);
                ldsm4(af[i][0], af[i][1], af[i][2], af[i][3], ab + SWZ(o));
            }
            #pragma unroll
            for (int j2 = 0; j2 < 2; j2++) {
                uint32_t o = (uint32_t)((wn + j2 * 16 + (sub >> 1) * 8 + lr) * 128
                                        + kk * 32 + (sub & 1) * 16);
                unsigned r0, r1, r2, r3;
                ldsm4(r0, r1, r2, r3, bb + SWZ(o));
                bf[j2 * 2][0] = r0;     bf[j2 * 2][1] = r1;
                bf[j2 * 2 + 1][0] = r2; bf[j2 * 2 + 1][1] = r3;
            }
            #pragma unroll
            for (int i = 0; i < 4; i++)
                #pragma unroll
                for (int j = 0; j < 4; j++)
                    MMA_F16(c[i][j][0], c[i][j][1], c[i][j][2], c[i][j][3],
                            af[i][0], af[i][1], af[i][2], af[i][3],
                            bf[j][0], bf[j][1]);
        }
        if (++buf >= 3) buf = 0;
    }

    #pragma unroll
    for (int i = 0; i < 4; i++) {
        #pragma unroll
        for (int j = 0; j < 4; j++) {
            int col = n0 + wn + j * 8 + 2 * tg;
            int r0m = m0 + wm + i * 16 + g, r1m = r0m + 8;
            if (MODE == 2) {
                __half* C = (__half*)Cv;
                int jj = col >> 1;
                float ba = bias[jj], bg = bias[jj + FFIN];
                if (r0m < M) {
                    float a = c[i][j][0] + ba, gt = c[i][j][1] + bg;
                    C[(size_t)r0m * (N >> 1) + jj] =
                        __float2half(a * 0.5f * gt * (1.f + erff(gt * 0.70710678118654752f)));
                }
                if (r1m < M) {
                    float a = c[i][j][2] + ba, gt = c[i][j][3] + bg;
                    C[(size_t)r1m * (N >> 1) + jj] =
                        __float2half(a * 0.5f * gt * (1.f + erff(gt * 0.70710678118654752f)));
                }
            } else {
                float bx = 0.f, by = 0.f;
                if (bias) { bx = bias[col]; by = bias[col + 1]; }
                if (MODE == 1) {
                    __half* C = (__half*)Cv;
                    if (r0m < M)
                        *(__half2*)&C[(size_t)r0m * N + col] =
                            __floats2half2_rn(c[i][j][0] + bx, c[i][j][1] + by);
                    if (r1m < M)
                        *(__half2*)&C[(size_t)r1m * N + col] =
                            __floats2half2_rn(c[i][j][2] + bx, c[i][j][3] + by);
                } else {
                    float* C = (float*)Cv;
                    if (r0m < M) {
                        size_t o0 = (size_t)r0m * N + col;
                        float2 v; v.x = c[i][j][0] + bx; v.y = c[i][j][1] + by;
                        if (Res) { float2 rr = *(const float2*)&Res[o0]; v.x += rr.x; v.y += rr.y; }
                        *(float2*)&C[o0] = v;
                    }
                    if (r1m < M) {
                        size_t o1 = (size_t)r1m * N + col;
                        float2 v; v.x = c[i][j][2] + bx; v.y = c[i][j][3] + by;
                        if (Res) { float2 rr = *(const float2*)&Res[o1]; v.x += rr.x; v.y += rr.y; }
                        *(float2*)&C[o1] = v;
                    }
                }
            }
        }
    }
}

// ---- fp16 flash attention v3: P kept in registers, base-2 softmax ----
__global__ __launch_bounds__(256) void attn_h(
    const __half* __restrict__ Q, const __half* __restrict__ K,
    const __half* __restrict__ V, __half* __restrict__ O,
    int N, int S, int sQ, int sKV)
{
    __shared__ uint8_t Qs[128 * 128];
    __shared__ uint8_t Ks[2][64 * 128];
    __shared__ uint8_t Vs[2][64 * 128];
    const int t = threadIdx.x, warp = t >> 5, lane = t & 31;
    const int g = lane >> 2, tg = lane & 3;
    const int sub = lane >> 3, lr = lane & 7;
    const int b = blockIdx.z, h = blockIdx.y;
    const int q0 = blockIdx.x * 128, mb = warp * 16;
    const float scale2 = 0.125f * 1.4426950408889634f;   // scale * log2(e)
    const uint32_t qb = smem_u32(Qs), kb = smem_u32(Ks), vb = smem_u32(Vs);

    int crow[2], ckq[2];
    uint32_t koff[2];
    #pragma unroll
    for (int i = 0; i < 2; i++) {
        int lin = t + i * 256;
        crow[i] = lin >> 3; ckq[i] = lin & 7;
        koff[i] = SWZ((uint32_t)(crow[i] * 128 + ckq[i] * 16));
    }

    #pragma unroll
    for (int it = 0; it < 4; it++) {
        int lin = t + it * 256;
        int r = lin >> 3, cq = lin & 7;
        cpa16(qb + SWZ((uint32_t)(r * 128 + cq * 16)),
              &Q[((size_t)(b * N + q0 + r)) * sQ + h * DHEAD + cq * 8], 16u);
    }
    #pragma unroll
    for (int i = 0; i < 2; i++) {
        int sg = crow[i];
        uint32_t sz = (sg < S) ? 16u : 0u;
        size_t off = ((size_t)(b * S + (sg < S ? sg : 0))) * sKV + h * DHEAD + ckq[i] * 8;
        cpa16(kb + koff[i], &K[off], sz);
        cpa16(vb + koff[i], &V[off], sz);
    }
    CP_COMMIT();
    CP_WAIT(0);
    __syncthreads();

    unsigned aq[4][4];
    #pragma unroll
    for (int kk = 0; kk < 4; kk++) {
        uint32_t o = (uint32_t)((mb + (sub & 1) * 8 + lr) * 128 + kk * 32 + (sub >> 1) * 16);
        ldsm4(aq[kk][0], aq[kk][1], aq[kk][2], aq[kk][3], qb + SWZ(o));
    }

    float ov[8][4];
    #pragma unroll
    for (int j = 0; j < 8; j++) { ov[j][0] = ov[j][1] = ov[j][2] = ov[j][3] = 0.f; }
    float m0_ = -1e30f, m1_ = -1e30f, l0_ = 0.f, l1_ = 0.f;

    const int nch = (S + 63) / 64;
    for (int ci = 0; ci < nch; ci++) {
        int bufc = ci & 1;
        if (ci + 1 < nch) {
            int nb = bufc ^ 1;
            #pragma unroll
            for (int i = 0; i < 2; i++) {
                int sg = (ci + 1) * 64 + crow[i];
                uint32_t sz = (sg < S) ? 16u : 0u;
                size_t off = ((size_t)(b * S + (sg < S ? sg : 0))) * sKV + h * DHEAD + ckq[i] * 8;
                cpa16(kb + nb * 8192 + koff[i], &K[off], sz);
                cpa16(vb + nb * 8192 + koff[i], &V[off], sz);
            }
            CP_COMMIT();
        }
        const uint32_t kcb = kb + bufc * 8192, vcb = vb + bufc * 8192;
        const int s0 = ci * 64;

        float sc[8][4];
        #pragma unroll
        for (int j = 0; j < 8; j++) { sc[j][0] = sc[j][1] = sc[j][2] = sc[j][3] = 0.f; }
        #pragma unroll
        for (int kk = 0; kk < 4; kk++) {
            #pragma unroll
            for (int j2 = 0; j2 < 4; j2++) {
                uint32_t o = (uint32_t)(((2 * j2 + (sub >> 1)) * 8 + lr) * 128
                                        + kk * 32 + (sub & 1) * 16);
                unsigned r0, r1, r2, r3;
                ldsm4(r0, r1, r2, r3, kcb + SWZ(o));
                MMA_F16(sc[2 * j2][0], sc[2 * j2][1], sc[2 * j2][2], sc[2 * j2][3],
                        aq[kk][0], aq[kk][1], aq[kk][2], aq[kk][3], r0, r1);
                MMA_F16(sc[2 * j2 + 1][0], sc[2 * j2 + 1][1], sc[2 * j2 + 1][2], sc[2 * j2 + 1][3],
                        aq[kk][0], aq[kk][1], aq[kk][2], aq[kk][3], r2, r3);
            }
        }

        bool tail = (s0 + 64 > S);
        #pragma unroll
        for (int j = 0; j < 8; j++) {
            sc[j][0] *= scale2; sc[j][1] *= scale2; sc[j][2] *= scale2; sc[j][3] *= scale2;
            if (tail) {
                int col = s0 + j * 8 + 2 * tg;
                if (col     >= S) { sc[j][0] = -1e30f; sc[j][2] = -1e30f; }
                if (col + 1 >= S) { sc[j][1] = -1e30f; sc[j][3] = -1e30f; }
            }
        }
        float rm0 = -1e30f, rm1 = -1e30f;
        #pragma unroll
        for (int j = 0; j < 8; j++) {
            rm0 = fmaxf(rm0, fmaxf(sc[j][0], sc[j][1]));
            rm1 = fmaxf(rm1, fmaxf(sc[j][2], sc[j][3]));
        }
        rm0 = fmaxf(rm0, __shfl_xor_sync(0xffffffffu, rm0, 1));
        rm0 = fmaxf(rm0, __shfl_xor_sync(0xffffffffu, rm0, 2));
        rm1 = fmaxf(rm1, __shfl_xor_sync(0xffffffffu, rm1, 1));
        rm1 = fmaxf(rm1, __shfl_xor_sync(0xffffffffu, rm1, 2));
        float nm0 = fmaxf(m0_, rm0), nm1 = fmaxf(m1_, rm1);
        float cc0 = ex2f(m0_ - nm0), cc1 = ex2f(m1_ - nm1);
        m0_ = nm0; m1_ = nm1;

        // P stays in registers: score frag (rows g/g+8, cols j*8+2tg) for
        // j=2kk,2kk+1 is exactly the m16n8k16 A-fragment of k-tile kk.
        unsigned pf[4][4];
        float rs0 = 0.f, rs1 = 0.f;
        #pragma unroll
        for (int j = 0; j < 8; j++) {
            float p0 = ex2f(sc[j][0] - nm0), p1 = ex2f(sc[j][1] - nm0);
            float p2 = ex2f(sc[j][2] - nm1), p3 = ex2f(sc[j][3] - nm1);
            rs0 += p0 + p1; rs1 += p2 + p3;
            int kk = j >> 1, hi = (j & 1) * 2;
            pf[kk][hi]     = packh2(p0, p1);
            pf[kk][hi + 1] = packh2(p2, p3);
        }
        rs0 += __shfl_xor_sync(0xffffffffu, rs0, 1);
        rs0 += __shfl_xor_sync(0xffffffffu, rs0, 2);
        rs1 += __shfl_xor_sync(0xffffffffu, rs1, 1);
        rs1 += __shfl_xor_sync(0xffffffffu, rs1, 2);
        l0_ = l0_ * cc0 + rs0;
        l1_ = l1_ * cc1 + rs1;
        #pragma unroll
        for (int j = 0; j < 8; j++) {
            ov[j][0] *= cc0; ov[j][1] *= cc0; ov[j][2] *= cc1; ov[j][3] *= cc1;
        }

        #pragma unroll
        for (int kk = 0; kk < 4; kk++) {
            #pragma unroll
            for (int j2 = 0; j2 < 4; j2++) {
                uint32_t o2 = (uint32_t)((kk * 16 + (sub & 1) * 8 + lr) * 128
                                         + (2 * j2 + (sub >> 1)) * 16);
                unsigned r0, r1, r2, r3;
                ldsm4t(r0, r1, r2, r3, vcb + SWZ(o2));
                MMA_F16(ov[2 * j2][0], ov[2 * j2][1], ov[2 * j2][2], ov[2 * j2][3],
                        pf[kk][0], pf[kk][1], pf[kk][2], pf[kk][3], r0, r1);
                MMA_F16(ov[2 * j2 + 1][0], ov[2 * j2 + 1][1], ov[2 * j2 + 1][2], ov[2 * j2 + 1][3],
                        pf[kk][0], pf[kk][1], pf[kk][2], pf[kk][3], r2, r3);
            }
        }
        if (ci + 1 < nch) { CP_WAIT(0); }
        __syncthreads();
    }

    float inv0 = 1.f / l0_, inv1 = 1.f / l1_;
    size_t r0 = ((size_t)(b * N + q0 + mb + g)) * DIM + h * DHEAD;
    size_t r1 = ((size_t)(b * N + q0 + mb + g + 8)) * DIM + h * DHEAD;
    #pragma unroll
    for (int j = 0; j < 8; j++) {
        *(__half2*)&O[r0 + j * 8 + 2 * tg] = __floats2half2_rn(ov[j][0] * inv0, ov[j][1] * inv0);
        *(__half2*)&O[r1 + j * 8 + 2 * tg] = __floats2half2_rn(ov[j][2] * inv1, ov[j][3] * inv1);
    }
}

extern "C" void kernel_launch(void* const* d_in, const int* in_sizes, int n_in,
                              void* d_out, int out_size)
{
    (void)in_sizes; (void)n_in; (void)out_size;
    const float* x   = (const float*)d_in[0];
    const float* ctx = (const float*)d_in[1];
    const float* Wq1 = (const float*)d_in[2];
    const float* Wk1 = (const float*)d_in[3];
    const float* Wv1 = (const float*)d_in[4];
    const float* Wo1 = (const float*)d_in[5];
    const float* bo1 = (const float*)d_in[6];
    const float* Wq2 = (const float*)d_in[7];
    const float* Wk2 = (const float*)d_in[8];
    const float* Wv2 = (const float*)d_in[9];
    const float* Wo2 = (const float*)d_in[10];
    const float* bo2 = (const float*)d_in[11];
    const float* Wp  = (const float*)d_in[12];
    const float* bp  = (const float*)d_in[13];
    const float* Wf  = (const float*)d_in[14];
    const float* bf  = (const float*)d_in[15];
    const float* g1 = (const float*)d_in[16]; const float* b1 = (const float*)d_in[17];
    const float* g2 = (const float*)d_in[18]; const float* b2 = (const float*)d_in[19];
    const float* g3 = (const float*)d_in[20]; const float* b3 = (const float*)d_in[21];
    float* out = (float*)d_out;

    __half *ln, *q, *kv, *att, *qkv, *gl, *cc;
    __half *wqkv, *wo1, *wq2, *wkv, *wo2, *wp, *wf;
    float* xb;
    cudaGetSymbolAddress((void**)&ln,   g_ln);
    cudaGetSymbolAddress((void**)&q,    g_q);
    cudaGetSymbolAddress((void**)&kv,   g_kv);
    cudaGetSymbolAddress((void**)&att,  g_att);
    cudaGetSymbolAddress((void**)&xb,   g_x);
    cudaGetSymbolAddress((void**)&qkv,  g_qkv);
    cudaGetSymbolAddress((void**)&gl,   g_gl);
    cudaGetSymbolAddress((void**)&cc,   g_cc);
    cudaGetSymbolAddress((void**)&wqkv, g_wqkv);
    cudaGetSymbolAddress((void**)&wo1,  g_wo1);
    cudaGetSymbolAddress((void**)&wq2,  g_wq2);
    cudaGetSymbolAddress((void**)&wkv,  g_wkv);
    cudaGetSymbolAddress((void**)&wo2,  g_wo2);
    cudaGetSymbolAddress((void**)&wp,   g_wpt);
    cudaGetSymbolAddress((void**)&wf,   g_wft);

    cudaFuncSetAttribute(hgemm<0>, cudaFuncAttributeMaxDynamicSharedMemorySize, HG_SMEM);
    cudaFuncSetAttribute(hgemm<1>, cudaFuncAttributeMaxDynamicSharedMemorySize, HG_SMEM);
    cudaFuncSetAttribute(hgemm<2>, cudaFuncAttributeMaxDynamicSharedMemorySize, HG_SMEM);

    const int B = 4, N = 2048, S = 77;
    const int M = B * N, Mc = B * S;
    dim3 tb(32, 8);
    dim3 gQKV(3072 / 128, M / 128);
    dim3 g1024(1024 / 128, M / 128);
    dim3 gKV(2048 / 128, (Mc + 127) / 128);
    dim3 gWp(2 * FFIN / 128, M / 128);
    dim3 aGrid(N / 128, HEADS, B);

    TBatch tb6;
    tb6.src[0] = Wq1; tb6.dst[0] = wqkv;
    tb6.src[1] = Wk1; tb6.dst[1] = wqkv + 1024 * 1024;
    tb6.src[2] = Wv1; tb6.dst[2] = wqkv + 2 * 1024 * 1024;
    tb6.src[3] = Wo1; tb6.dst[3] = wo1;
    tb6.src[4] = Wq2; tb6.dst[4] = wq2;
    tb6.src[5] = Wo2; tb6.dst[5] = wo2;
    transpose_multi<<<dim3(32, 32, 6), tb>>>(tb6, 1024, 1024);
    TBatch tb2;
    tb2.src[0] = Wk2; tb2.dst[0] = wkv;
    tb2.src[1] = Wv2; tb2.dst[1] = wkv + 1024 * 768;
    tb2.src[2] = tb2.src[1]; tb2.dst[2] = tb2.dst[1];
    tb2.src[3] = tb2.src[1]; tb2.dst[3] = tb2.dst[1];
    tb2.src[4] = tb2.src[1]; tb2.dst[4] = tb2.dst[1];
    tb2.src[5] = tb2.src[1]; tb2.dst[5] = tb2.dst[1];
    transpose_multi<<<dim3(32, 24, 2), tb>>>(tb2, 768, 1024);
    transpose_cvt<<<dim3(256, 32), tb>>>(Wp, wp, 1024, 2 * FFIN, 1);
    transpose_cvt<<<dim3(32, 128), tb>>>(Wf, wf, 4096, 1024, 0);
    cvt_kernel<<<(Mc * 768 + 255) / 256, 256>>>(ctx, cc, Mc * 768);

    ln_kernel<<<M, 256>>>(x, g1, b1, ln);
    hgemm<1><<<gQKV, 256, HG_SMEM>>>(ln, wqkv, nullptr, nullptr, qkv, M, 3072, 1024);
    attn_h<<<aGrid, 256>>>(qkv, qkv + 1024, qkv + 2048, att, N, N, 3072, 3072);
    hgemm<0><<<g1024, 256, HG_SMEM>>>(att, wo1, bo1, x, xb, M, 1024, 1024);

    ln_kernel<<<M, 256>>>(xb, g2, b2, ln);
    hgemm<1><<<g1024, 256, HG_SMEM>>>(ln, wq2, nullptr, nullptr, q, M, 1024, 1024);
    hgemm<1><<<gKV, 256, HG_SMEM>>>(cc, wkv, nullptr, nullptr, kv, Mc, 2048, 768);
    attn_h<<<aGrid, 256>>>(q, kv, kv + 1024, att, N, S, 1024, 2048);
    hgemm<0><<<g1024, 256, HG_SMEM>>>(att, wo2, bo2, xb, xb, M, 1024, 1024);

    ln_kernel<<<M, 256>>>(xb, g3, b3, ln);
    hgemm<2><<<gWp, 256, HG_SMEM>>>(ln, wp, bp, nullptr, gl, M, 2 * FFIN, 1024);
    hgemm<0><<<g1024, 256, HG_SMEM>>>(gl, wf, bf, xb, out, M, 1024, FFIN);
}

// round 17
// speedup vs baseline: 9.5793x; 1.0356x over previous
#include <cuda_runtime.h>
#include <cuda_fp16.h>
#include <math.h>
#include <stdint.h>

#define DIM   1024
#define HEADS 16
#define DHEAD 64
#define BTOK  8192
#define FFIN  4096

// ---------------- scratch ----------------
__device__ __half g_ln  [BTOK * DIM];
__device__ __half g_q   [BTOK * DIM];
__device__ __half g_kv  [BTOK * DIM];
__device__ __half g_att [BTOK * DIM];
__device__ float  g_x   [BTOK * DIM];
__device__ __half g_qkv [(size_t)BTOK * 3 * DIM];
__device__ __half g_gl  [(size_t)BTOK * FFIN];
__device__ __half g_wqkv[3 * 1024 * 1024];
__device__ __half g_wo1 [1024 * 1024];
__device__ __half g_wq2 [1024 * 1024];
__device__ __half g_wkv [2048 * 768];
__device__ __half g_wo2 [1024 * 1024];
__device__ __half g_wpt [(size_t)(2 * FFIN) * 1024];
__device__ __half g_wft [1024 * FFIN];
__device__ __half g_cc  [308 * 768];

__device__ __forceinline__ uint32_t smem_u32(const void* p) {
    uint32_t a;
    asm("{ .reg .u64 t; cvta.to.shared.u64 t, %1; cvt.u32.u64 %0, t; }" : "=r"(a) : "l"(p));
    return a;
}
__device__ __forceinline__ float ex2f(float x) {
    float y; asm("ex2.approx.ftz.f32 %0, %1;" : "=f"(y) : "f"(x)); return y;
}
__device__ __forceinline__ unsigned packh2(float a, float b) {
    __half2 hv = __floats2half2_rn(a, b);
    unsigned u;
    asm("mov.b32 %0, %1;" : "=r"(u) : "r"(*(unsigned*)&hv));
    return u;
}
#define SWZ(o) ((o) ^ (((o) >> 3) & 0x70))
__device__ __forceinline__ void ldsm4(unsigned &r0, unsigned &r1, unsigned &r2,
                                      unsigned &r3, uint32_t a) {
    asm volatile("ldmatrix.sync.aligned.m8n8.x4.shared.b16 {%0,%1,%2,%3}, [%4];"
                 : "=r"(r0), "=r"(r1), "=r"(r2), "=r"(r3) : "r"(a));
}
__device__ __forceinline__ void ldsm4t(unsigned &r0, unsigned &r1, unsigned &r2,
                                       unsigned &r3, uint32_t a) {
    asm volatile("ldmatrix.sync.aligned.m8n8.x4.trans.shared.b16 {%0,%1,%2,%3}, [%4];"
                 : "=r"(r0), "=r"(r1), "=r"(r2), "=r"(r3) : "r"(a));
}
#define MMA_F16(c0,c1,c2,c3,a0,a1,a2,a3,b0,b1)                               \
    asm volatile(                                                            \
        "mma.sync.aligned.m16n8k16.row.col.f32.f16.f16.f32 "                 \
        "{%0,%1,%2,%3}, {%4,%5,%6,%7}, {%8,%9}, {%0,%1,%2,%3};"              \
        : "+f"(c0), "+f"(c1), "+f"(c2), "+f"(c3)                             \
        : "r"(a0), "r"(a1), "r"(a2), "r"(a3), "r"(b0), "r"(b1))
__device__ __forceinline__ void cpa16(uint32_t dst, const void* src, uint32_t sz) {
    asm volatile("cp.async.cg.shared.global [%0], [%1], 16, %2;"
                 :: "r"(dst), "l"(src), "r"(sz) : "memory");
}
#define CP_COMMIT() asm volatile("cp.async.commit_group;" ::: "memory")
#define CP_WAIT(n)  asm volatile("cp.async.wait_group %0;" :: "n"(n) : "memory")

// ---- unified weight prep: one launch, 10 transpose slices ----
struct PrepSlice { const float* src; __half* dst; int K, N, bx, pack, start; };
struct PrepAll { PrepSlice s[10]; };

__global__ __launch_bounds__(256) void prep_kernel(PrepAll pa)
{
    __shared__ float tile[32][33];
    int bid = blockIdx.x;
    int si = 0;
    #pragma unroll
    for (int i = 1; i < 10; i++)
        if (bid >= pa.s[i].start) si = i;
    PrepSlice sl = pa.s[si];
    int lb = bid - sl.start;
    int bx = lb % sl.bx, by = lb / sl.bx;
    int tx = threadIdx.x, ty = threadIdx.y;
    int n = bx * 32 + tx, k0 = by * 32;
    #pragma unroll
    for (int j = 0; j < 32; j += 8)
        tile[ty + j][tx] = sl.src[(size_t)(k0 + ty + j) * sl.N + n];
    __syncthreads();
    int k = k0 + tx, n0 = bx * 32;
    #pragma unroll
    for (int j = 0; j < 32; j += 8) {
        int nr = n0 + ty + j;
        int nn = sl.pack ? (2 * (nr & 4095) + (nr >> 12)) : nr;
        sl.dst[(size_t)nn * sl.K + k] = __float2half(tile[tx][ty + j]);
    }
}

__global__ __launch_bounds__(256) void cvt_kernel(
    const float* __restrict__ in, __half* __restrict__ out, int n)
{
    int i = blockIdx.x * 256 + threadIdx.x;
    if (i < n) out[i] = __float2half(in[i]);
}

__global__ __launch_bounds__(256) void ln_kernel(
    const float* __restrict__ x, const float* __restrict__ gamma,
    const float* __restrict__ beta, __half* __restrict__ out)
{
    int row = blockIdx.x, tid = threadIdx.x;
    float4 t = ((const float4*)(x + (size_t)row * DIM))[tid];
    float s = t.x + t.y + t.z + t.w;
    float q = t.x * t.x + t.y * t.y + t.z * t.z + t.w * t.w;
    #pragma unroll
    for (int o = 16; o; o >>= 1) {
        s += __shfl_xor_sync(0xffffffffu, s, o);
        q += __shfl_xor_sync(0xffffffffu, q, o);
    }
    __shared__ float ssum[8], ssq[8], smean, srstd;
    int wid = tid >> 5, lane = tid & 31;
    if (lane == 0) { ssum[wid] = s; ssq[wid] = q; }
    __syncthreads();
    if (tid == 0) {
        float S = 0.f, Q = 0.f;
        #pragma unroll
        for (int i = 0; i < 8; i++) { S += ssum[i]; Q += ssq[i]; }
        float mean = S * (1.f / DIM);
        smean = mean;
        srstd = rsqrtf(Q * (1.f / DIM) - mean * mean + 1e-5f);
    }
    __syncthreads();
    float mean = smean, rstd = srstd;
    float4 gg = ((const float4*)gamma)[tid];
    float4 bb = ((const float4*)beta)[tid];
    __half2* orow = (__half2*)(out + (size_t)row * DIM);
    orow[tid * 2 + 0] = __floats2half2_rn((t.x - mean) * rstd * gg.x + bb.x,
                                          (t.y - mean) * rstd * gg.y + bb.y);
    orow[tid * 2 + 1] = __floats2half2_rn((t.z - mean) * rstd * gg.z + bb.z,
                                          (t.w - mean) * rstd * gg.w + bb.w);
}

#define HG_STAGE 32768
#define HG_SMEM  (3 * HG_STAGE)

// ---- fp16 GEMM core as a device function ----
template<int MODE>
__device__ __forceinline__ void hgemm_body(
    const __half* __restrict__ A, const __half* __restrict__ Bt,
    const float* __restrict__ bias, const float* __restrict__ Res,
    void* __restrict__ Cv, int M, int N, int K, int bx, int by,
    uint8_t* sm)
{
    const uint32_t sbase = smem_u32(sm);
    const int t = threadIdx.x, warp = t >> 5, lane = t & 31;
    const int g = lane >> 2, tg = lane & 3;
    const int sub = lane >> 3, lr = lane & 7;
    const int m0 = by * 128, n0 = bx * 128;
    const int wm = (warp & 1) * 64, wn = (warp >> 1) * 32;

    uint32_t qoff[4], a_sz[4];
    const __half* a_src[4];
    const __half* b_src[4];
    #pragma unroll
    for (int i = 0; i < 4; i++) {
        int idx = t + i * 256;
        int row = idx >> 3, kq = idx & 7;
        qoff[i] = SWZ((uint32_t)(row * 128 + kq * 16));
        int ar = (m0 + row < M) ? (m0 + row) : 0;
        a_sz[i]  = (m0 + row < M) ? 16u : 0u;
        a_src[i] = A  + (size_t)ar * K + kq * 8;
        b_src[i] = Bt + (size_t)(n0 + row) * K + kq * 8;
    }

    float c[4][4][4];
    #pragma unroll
    for (int i = 0; i < 4; i++)
        #pragma unroll
        for (int j = 0; j < 4; j++)
            #pragma unroll
            for (int r = 0; r < 4; r++) c[i][j][r] = 0.f;

    const int S = K / 64;
    #pragma unroll
    for (int st = 0; st < 2; st++) {
        uint32_t sb = sbase + st * HG_STAGE;
        #pragma unroll
        for (int i = 0; i < 4; i++) {
            cpa16(sb + qoff[i],         a_src[i] + st * 64, a_sz[i]);
            cpa16(sb + 16384 + qoff[i], b_src[i] + st * 64, 16u);
        }
        CP_COMMIT();
    }

    int buf = 0;
    for (int s = 0; s < S; s++) {
        if (s == S - 1) { CP_WAIT(0); } else { CP_WAIT(1); }
        __syncthreads();
        if (s + 2 < S) {
            int nb = buf + 2; if (nb >= 3) nb -= 3;
            uint32_t sb = sbase + nb * HG_STAGE;
            #pragma unroll
            for (int i = 0; i < 4; i++) {
                cpa16(sb + qoff[i],         a_src[i] + (s + 2) * 64, a_sz[i]);
                cpa16(sb + 16384 + qoff[i], b_src[i] + (s + 2) * 64, 16u);
            }
            CP_COMMIT();
        }

        const uint32_t ab = sbase + buf * HG_STAGE, bb = ab + 16384;
        #pragma unroll
        for (int kk = 0; kk < 4; kk++) {
            unsigned af[4][4], bf[4][2];
            #pragma unroll
            for (int i = 0; i < 4; i++) {
                uint32_t o = (uint32_t)((wm + i * 16 + (sub & 1) * 8 + lr) * 128
                                        + kk * 32 + (sub >> 1) * 16);
                ldsm4(af[i][0], af[i][1], af[i][2], af[i][3], ab + SWZ(o));
            }
            #pragma unroll
            for (int j2 = 0; j2 < 2; j2++) {
                uint32_t o = (uint32_t)((wn + j2 * 16 + (sub >> 1) * 8 + lr) * 128
                                        + kk * 32 + (sub & 1) * 16);
                unsigned r0, r1, r2, r3;
                ldsm4(r0, r1, r2, r3, bb + SWZ(o));
                bf[j2 * 2][0] = r0;     bf[j2 * 2][1] = r1;
                bf[j2 * 2 + 1][0] = r2; bf[j2 * 2 + 1][1] = r3;
            }
            #pragma unroll
            for (int i = 0; i < 4; i++)
                #pragma unroll
                for (int j = 0; j < 4; j++)
                    MMA_F16(c[i][j][0], c[i][j][1], c[i][j][2], c[i][j][3],
                            af[i][0], af[i][1], af[i][2], af[i][3],
                            bf[j][0], bf[j][1]);
        }
        if (++buf >= 3) buf = 0;
    }

    #pragma unroll
    for (int i = 0; i < 4; i++) {
        #pragma unroll
        for (int j = 0; j < 4; j++) {
            int col = n0 + wn + j * 8 + 2 * tg;
            int r0m = m0 + wm + i * 16 + g, r1m = r0m + 8;
            if (MODE == 2) {
                __half* C = (__half*)Cv;
                int jj = col >> 1;
                float ba = bias[jj], bg = bias[jj + FFIN];
                if (r0m < M) {
                    float a = c[i][j][0] + ba, gt = c[i][j][1] + bg;
                    C[(size_t)r0m * (N >> 1) + jj] =
                        __float2half(a * 0.5f * gt * (1.f + erff(gt * 0.70710678118654752f)));
                }
                if (r1m < M) {
                    float a = c[i][j][2] + ba, gt = c[i][j][3] + bg;
                    C[(size_t)r1m * (N >> 1) + jj] =
                        __float2half(a * 0.5f * gt * (1.f + erff(gt * 0.70710678118654752f)));
                }
            } else if (MODE == 1) {
                __half* C = (__half*)Cv;
                if (r0m < M)
                    *(__half2*)&C[(size_t)r0m * N + col] =
                        __floats2half2_rn(c[i][j][0], c[i][j][1]);
                if (r1m < M)
                    *(__half2*)&C[(size_t)r1m * N + col] =
                        __floats2half2_rn(c[i][j][2], c[i][j][3]);
            } else {
                float bx2 = 0.f, by2 = 0.f;
                if (bias) { bx2 = bias[col]; by2 = bias[col + 1]; }
                float* C = (float*)Cv;
                if (r0m < M) {
                    size_t o0 = (size_t)r0m * N + col;
                    float2 v; v.x = c[i][j][0] + bx2; v.y = c[i][j][1] + by2;
                    if (Res) { float2 rr = *(const float2*)&Res[o0]; v.x += rr.x; v.y += rr.y; }
                    *(float2*)&C[o0] = v;
                }
                if (r1m < M) {
                    size_t o1 = (size_t)r1m * N + col;
                    float2 v; v.x = c[i][j][2] + bx2; v.y = c[i][j][3] + by2;
                    if (Res) { float2 rr = *(const float2*)&Res[o1]; v.x += rr.x; v.y += rr.y; }
                    *(float2*)&C[o1] = v;
                }
            }
        }
    }
}

template<int MODE>
__global__ __launch_bounds__(256, 2) void hgemm(
    const __half* __restrict__ A, const __half* __restrict__ Bt,
    const float* __restrict__ bias, const float* __restrict__ Res,
    void* __restrict__ Cv, int M, int N, int K)
{
    extern __shared__ uint8_t sm[];
    hgemm_body<MODE>(A, Bt, bias, Res, Cv, M, N, K, blockIdx.x, blockIdx.y, sm);
}

// ---- dual GEMM: set0 (Q2) blocks [0,split), set1 (KV) blocks [split,..) ----
struct GemmP { const __half* A; const __half* Bt; __half* C; int M, N, K, nx; };

__global__ __launch_bounds__(256, 2) void hgemm_dual(GemmP p0, GemmP p1, int split)
{
    extern __shared__ uint8_t sm[];
    int bid = blockIdx.x;
    if (bid < split) {
        hgemm_body<1>(p0.A, p0.Bt, nullptr, nullptr, p0.C,
                      p0.M, p0.N, p0.K, bid % p0.nx, bid / p0.nx, sm);
    } else {
        int b2 = bid - split;
        hgemm_body<1>(p1.A, p1.Bt, nullptr, nullptr, p1.C,
                      p1.M, p1.N, p1.K, b2 % p1.nx, b2 / p1.nx, sm);
    }
}

// ---- fp16 flash attention: P in registers, base-2 softmax ----
__global__ __launch_bounds__(256) void attn_h(
    const __half* __restrict__ Q, const __half* __restrict__ K,
    const __half* __restrict__ V, __half* __restrict__ O,
    int N, int S, int sQ, int sKV)
{
    __shared__ uint8_t Qs[128 * 128];
    __shared__ uint8_t Ks[2][64 * 128];
    __shared__ uint8_t Vs[2][64 * 128];
    const int t = threadIdx.x, warp = t >> 5, lane = t & 31;
    const int g = lane >> 2, tg = lane & 3;
    const int sub = lane >> 3, lr = lane & 7;
    const int b = blockIdx.z, h = blockIdx.y;
    const int q0 = blockIdx.x * 128, mb = warp * 16;
    const float scale2 = 0.125f * 1.4426950408889634f;
    const uint32_t qb = smem_u32(Qs), kb = smem_u32(Ks), vb = smem_u32(Vs);

    int crow[2], ckq[2];
    uint32_t koff[2];
    #pragma unroll
    for (int i = 0; i < 2; i++) {
        int lin = t + i * 256;
        crow[i] = lin >> 3; ckq[i] = lin & 7;
        koff[i] = SWZ((uint32_t)(crow[i] * 128 + ckq[i] * 16));
    }

    #pragma unroll
    for (int it = 0; it < 4; it++) {
        int lin = t + it * 256;
        int r = lin >> 3, cq = lin & 7;
        cpa16(qb + SWZ((uint32_t)(r * 128 + cq * 16)),
              &Q[((size_t)(b * N + q0 + r)) * sQ + h * DHEAD + cq * 8], 16u);
    }
    #pragma unroll
    for (int i = 0; i < 2; i++) {
        int sg = crow[i];
        uint32_t sz = (sg < S) ? 16u : 0u;
        size_t off = ((size_t)(b * S + (sg < S ? sg : 0))) * sKV + h * DHEAD + ckq[i] * 8;
        cpa16(kb + koff[i], &K[off], sz);
        cpa16(vb + koff[i], &V[off], sz);
    }
    CP_COMMIT();
    CP_WAIT(0);
    __syncthreads();

    unsigned aq[4][4];
    #pragma unroll
    for (int kk = 0; kk < 4; kk++) {
        uint32_t o = (uint32_t)((mb + (sub & 1) * 8 + lr) * 128 + kk * 32 + (sub >> 1) * 16);
        ldsm4(aq[kk][0], aq[kk][1], aq[kk][2], aq[kk][3], qb + SWZ(o));
    }

    float ov[8][4];
    #pragma unroll
    for (int j = 0; j < 8; j++) { ov[j][0] = ov[j][1] = ov[j][2] = ov[j][3] = 0.f; }
    float m0_ = -1e30f, m1_ = -1e30f, l0_ = 0.f, l1_ = 0.f;

    const int nch = (S + 63) / 64;
    for (int ci = 0; ci < nch; ci++) {
        int bufc = ci & 1;
        if (ci + 1 < nch) {
            int nb = bufc ^ 1;
            #pragma unroll
            for (int i = 0; i < 2; i++) {
                int sg = (ci + 1) * 64 + crow[i];
                uint32_t sz = (sg < S) ? 16u : 0u;
                size_t off = ((size_t)(b * S + (sg < S ? sg : 0))) * sKV + h * DHEAD + ckq[i] * 8;
                cpa16(kb + nb * 8192 + koff[i], &K[off], sz);
                cpa16(vb + nb * 8192 + koff[i], &V[off], sz);
            }
            CP_COMMIT();
        }
        const uint32_t kcb = kb + bufc * 8192, vcb = vb + bufc * 8192;
        const int s0 = ci * 64;

        float sc[8][4];
        #pragma unroll
        for (int j = 0; j < 8; j++) { sc[j][0] = sc[j][1] = sc[j][2] = sc[j][3] = 0.f; }
        #pragma unroll
        for (int kk = 0; kk < 4; kk++) {
            #pragma unroll
            for (int j2 = 0; j2 < 4; j2++) {
                uint32_t o = (uint32_t)(((2 * j2 + (sub >> 1)) * 8 + lr) * 128
                                        + kk * 32 + (sub & 1) * 16);
                unsigned r0, r1, r2, r3;
                ldsm4(r0, r1, r2, r3, kcb + SWZ(o));
                MMA_F16(sc[2 * j2][0], sc[2 * j2][1], sc[2 * j2][2], sc[2 * j2][3],
                        aq[kk][0], aq[kk][1], aq[kk][2], aq[kk][3], r0, r1);
                MMA_F16(sc[2 * j2 + 1][0], sc[2 * j2 + 1][1], sc[2 * j2 + 1][2], sc[2 * j2 + 1][3],
                        aq[kk][0], aq[kk][1], aq[kk][2], aq[kk][3], r2, r3);
            }
        }

        bool tail = (s0 + 64 > S);
        #pragma unroll
        for (int j = 0; j < 8; j++) {
            sc[j][0] *= scale2; sc[j][1] *= scale2; sc[j][2] *= scale2; sc[j][3] *= scale2;
            if (tail) {
                int col = s0 + j * 8 + 2 * tg;
                if (col     >= S) { sc[j][0] = -1e30f; sc[j][2] = -1e30f; }
                if (col + 1 >= S) { sc[j][1] = -1e30f; sc[j][3] = -1e30f; }
            }
        }
        float rm0 = -1e30f, rm1 = -1e30f;
        #pragma unroll
        for (int j = 0; j < 8; j++) {
            rm0 = fmaxf(rm0, fmaxf(sc[j][0], sc[j][1]));
            rm1 = fmaxf(rm1, fmaxf(sc[j][2], sc[j][3]));
        }
        rm0 = fmaxf(rm0, __shfl_xor_sync(0xffffffffu, rm0, 1));
        rm0 = fmaxf(rm0, __shfl_xor_sync(0xffffffffu, rm0, 2));
        rm1 = fmaxf(rm1, __shfl_xor_sync(0xffffffffu, rm1, 1));
        rm1 = fmaxf(rm1, __shfl_xor_sync(0xffffffffu, rm1, 2));
        float nm0 = fmaxf(m0_, rm0), nm1 = fmaxf(m1_, rm1);
        float cc0 = ex2f(m0_ - nm0), cc1 = ex2f(m1_ - nm1);
        m0_ = nm0; m1_ = nm1;

        unsigned pf[4][4];
        float rs0 = 0.f, rs1 = 0.f;
        #pragma unroll
        for (int j = 0; j < 8; j++) {
            float p0 = ex2f(sc[j][0] - nm0), p1 = ex2f(sc[j][1] - nm0);
            float p2 = ex2f(sc[j][2] - nm1), p3 = ex2f(sc[j][3] - nm1);
            rs0 += p0 + p1; rs1 += p2 + p3;
            int kk = j >> 1, hi = (j & 1) * 2;
            pf[kk][hi]     = packh2(p0, p1);
            pf[kk][hi + 1] = packh2(p2, p3);
        }
        rs0 += __shfl_xor_sync(0xffffffffu, rs0, 1);
        rs0 += __shfl_xor_sync(0xffffffffu, rs0, 2);
        rs1 += __shfl_xor_sync(0xffffffffu, rs1, 1);
        rs1 += __shfl_xor_sync(0xffffffffu, rs1, 2);
        l0_ = l0_ * cc0 + rs0;
        l1_ = l1_ * cc1 + rs1;
        #pragma unroll
        for (int j = 0; j < 8; j++) {
            ov[j][0] *= cc0; ov[j][1] *= cc0; ov[j][2] *= cc1; ov[j][3] *= cc1;
        }

        #pragma unroll
        for (int kk = 0; kk < 4; kk++) {
            #pragma unroll
            for (int j2 = 0; j2 < 4; j2++) {
                uint32_t o2 = (uint32_t)((kk * 16 + (sub & 1) * 8 + lr) * 128
                                         + (2 * j2 + (sub >> 1)) * 16);
                unsigned r0, r1, r2, r3;
                ldsm4t(r0, r1, r2, r3, vcb + SWZ(o2));
                MMA_F16(ov[2 * j2][0], ov[2 * j2][1], ov[2 * j2][2], ov[2 * j2][3],
                        pf[kk][0], pf[kk][1], pf[kk][2], pf[kk][3], r0, r1);
                MMA_F16(ov[2 * j2 + 1][0], ov[2 * j2 + 1][1], ov[2 * j2 + 1][2], ov[2 * j2 + 1][3],
                        pf[kk][0], pf[kk][1], pf[kk][2], pf[kk][3], r2, r3);
            }
        }
        if (ci + 1 < nch) { CP_WAIT(0); }
        __syncthreads();
    }

    float inv0 = 1.f / l0_, inv1 = 1.f / l1_;
    size_t r0 = ((size_t)(b * N + q0 + mb + g)) * DIM + h * DHEAD;
    size_t r1 = ((size_t)(b * N + q0 + mb + g + 8)) * DIM + h * DHEAD;
    #pragma unroll
    for (int j = 0; j < 8; j++) {
        *(__half2*)&O[r0 + j * 8 + 2 * tg] = __floats2half2_rn(ov[j][0] * inv0, ov[j][1] * inv0);
        *(__half2*)&O[r1 + j * 8 + 2 * tg] = __floats2half2_rn(ov[j][2] * inv1, ov[j][3] * inv1);
    }
}

extern "C" void kernel_launch(void* const* d_in, const int* in_sizes, int n_in,
                              void* d_out, int out_size)
{
    (void)in_sizes; (void)n_in; (void)out_size;
    const float* x   = (const float*)d_in[0];
    const float* ctx = (const float*)d_in[1];
    const float* Wq1 = (const float*)d_in[2];
    const float* Wk1 = (const float*)d_in[3];
    const float* Wv1 = (const float*)d_in[4];
    const float* Wo1 = (const float*)d_in[5];
    const float* bo1 = (const float*)d_in[6];
    const float* Wq2 = (const float*)d_in[7];
    const float* Wk2 = (const float*)d_in[8];
    const float* Wv2 = (const float*)d_in[9];
    const float* Wo2 = (const float*)d_in[10];
    const float* bo2 = (const float*)d_in[11];
    const float* Wp  = (const float*)d_in[12];
    const float* bp  = (const float*)d_in[13];
    const float* Wf  = (const float*)d_in[14];
    const float* bf  = (const float*)d_in[15];
    const float* g1 = (const float*)d_in[16]; const float* b1 = (const float*)d_in[17];
    const float* g2 = (const float*)d_in[18]; const float* b2 = (const float*)d_in[19];
    const float* g3 = (const float*)d_in[20]; const float* b3 = (const float*)d_in[21];
    float* out = (float*)d_out;

    __half *ln, *q, *kv, *att, *qkv, *gl, *cc;
    __half *wqkv, *wo1, *wq2, *wkv, *wo2, *wp, *wf;
    float* xb;
    cudaGetSymbolAddress((void**)&ln,   g_ln);
    cudaGetSymbolAddress((void**)&q,    g_q);
    cudaGetSymbolAddress((void**)&kv,   g_kv);
    cudaGetSymbolAddress((void**)&att,  g_att);
    cudaGetSymbolAddress((void**)&xb,   g_x);
    cudaGetSymbolAddress((void**)&qkv,  g_qkv);
    cudaGetSymbolAddress((void**)&gl,   g_gl);
    cudaGetSymbolAddress((void**)&cc,   g_cc);
    cudaGetSymbolAddress((void**)&wqkv, g_wqkv);
    cudaGetSymbolAddress((void**)&wo1,  g_wo1);
    cudaGetSymbolAddress((void**)&wq2,  g_wq2);
    cudaGetSymbolAddress((void**)&wkv,  g_wkv);
    cudaGetSymbolAddress((void**)&wo2,  g_wo2);
    cudaGetSymbolAddress((void**)&wp,   g_wpt);
    cudaGetSymbolAddress((void**)&wf,   g_wft);

    cudaFuncSetAttribute(hgemm<0>, cudaFuncAttributeMaxDynamicSharedMemorySize, HG_SMEM);
    cudaFuncSetAttribute(hgemm<1>, cudaFuncAttributeMaxDynamicSharedMemorySize, HG_SMEM);
    cudaFuncSetAttribute(hgemm<2>, cudaFuncAttributeMaxDynamicSharedMemorySize, HG_SMEM);
    cudaFuncSetAttribute(hgemm_dual, cudaFuncAttributeMaxDynamicSharedMemorySize, HG_SMEM);

    const int B = 4, N = 2048, S = 77;
    const int M = B * N, Mc = B * S;
    dim3 tb(32, 8);
    dim3 gQKV(3072 / 128, M / 128);
    dim3 g1024(1024 / 128, M / 128);
    dim3 gWp(2 * FFIN / 128, M / 128);
    dim3 aGrid(N / 128, HEADS, B);

    // unified weight prep: 10 slices, one launch
    PrepAll pa;
    const float* srcs[10] = { Wq1, Wk1, Wv1, Wo1, Wq2, Wo2, Wk2, Wv2, Wp, Wf };
    __half* dsts[10] = { wqkv, wqkv + 1024 * 1024, wqkv + 2 * 1024 * 1024,
                         wo1, wq2, wo2, wkv, wkv + 1024 * 768, wp, wf };
    int Ks[10]   = { 1024, 1024, 1024, 1024, 1024, 1024, 768, 768, 1024, 4096 };
    int Ns[10]   = { 1024, 1024, 1024, 1024, 1024, 1024, 1024, 1024, 8192, 1024 };
    int bxs[10]  = { 32, 32, 32, 32, 32, 32, 32, 32, 256, 32 };
    int bys[10]  = { 32, 32, 32, 32, 32, 32, 24, 24, 32, 128 };
    int packs[10] = { 0, 0, 0, 0, 0, 0, 0, 0, 1, 0 };
    int cum = 0;
    for (int i = 0; i < 10; i++) {
        pa.s[i].src = srcs[i]; pa.s[i].dst = dsts[i];
        pa.s[i].K = Ks[i]; pa.s[i].N = Ns[i];
        pa.s[i].bx = bxs[i]; pa.s[i].pack = packs[i];
        pa.s[i].start = cum;
        cum += bxs[i] * bys[i];
    }
    prep_kernel<<<cum, tb>>>(pa);
    cvt_kernel<<<(Mc * 768 + 255) / 256, 256>>>(ctx, cc, Mc * 768);

    // stage 1
    ln_kernel<<<M, 256>>>(x, g1, b1, ln);
    hgemm<1><<<gQKV, 256, HG_SMEM>>>(ln, wqkv, nullptr, nullptr, qkv, M, 3072, 1024);
    attn_h<<<aGrid, 256>>>(qkv, qkv + 1024, qkv + 2048, att, N, N, 3072, 3072);
    hgemm<0><<<g1024, 256, HG_SMEM>>>(att, wo1, bo1, x, xb, M, 1024, 1024);

    // stage 2 (Q2 + KV fused into one launch)
    ln_kernel<<<M, 256>>>(xb, g2, b2, ln);
    GemmP p0, p1;
    p0.A = ln; p0.Bt = wq2; p0.C = q;  p0.M = M;  p0.N = 1024; p0.K = 1024; p0.nx = 8;
    p1.A = cc; p1.Bt = wkv; p1.C = kv; p1.M = Mc; p1.N = 2048; p1.K = 768;  p1.nx = 16;
    int split = p0.nx * (M / 128);                 // 512
    int total = split + p1.nx * ((Mc + 127) / 128); // +48
    hgemm_dual<<<total, 256, HG_SMEM>>>(p0, p1, split);
    attn_h<<<aGrid, 256>>>(q, kv, kv + 1024, att, N, S, 1024, 2048);
    hgemm<0><<<g1024, 256, HG_SMEM>>>(att, wo2, bo2, xb, xb, M, 1024, 1024);

    // stage 3
    ln_kernel<<<M, 256>>>(xb, g3, b3, ln);
    hgemm<2><<<gWp, 256, HG_SMEM>>>(ln, wp, bp, nullptr, gl, M, 2 * FFIN, 1024);
    hgemm<0><<<g1024, 256, HG_SMEM>>>(gl, wf, bf, xb, out, M, 1024, FFIN);
}